// round 1
// baseline (speedup 1.0000x reference)
#include <cuda_runtime.h>
#include <math.h>

#define BB   4
#define T    8192
#define DIM  512
#define H    8
#define D    64
#define C    64
#define NCH  128           // T/C
#define BH   32            // BB*H
#define EPSR 1.1920929e-07f
#define MAXLR 0.01f

// ------------------- scratch (device globals; no allocs allowed) -------------------
__device__ float g_s   [BB*T*DIM];     // rmsnorm(seq)
__device__ float g_q   [BH*T*D];       // per-head q (unshifted token index)
__device__ float g_k   [BH*T*D];
__device__ float g_v   [BH*T*D];
__device__ float g_lr  [BH*T];         // sigmoid(s@Wstep)*MAXLR*(2/D)  (prefolded)
__device__ float g_gate[BH*T];         // sigmoid(s@Wgate)
__device__ float g_mg  [BH*NCH];
__device__ float g_dec [BH*NCH];
__device__ float g_u1  [(long)BH*NCH*D*D];  // surprises -> (in-place scan) -> updates
__device__ float g_u2  [(long)BH*NCH*D*D];
__device__ float g_vals[BB*T*DIM];     // merged-head retrieve output (pre-combine)

__device__ __forceinline__ float sigm(float x){ return 1.f/(1.f+__expf(-x)); }

// ------------------- K1: rmsnorm + per-token lr & gate -------------------
__global__ void k1_rmsnorm(const float* __restrict__ seq,
                           const float* __restrict__ Wstep,
                           const float* __restrict__ Wgate)
{
    int tok = blockIdx.x;           // 0..BB*T-1
    int tid = threadIdx.x;          // 256
    __shared__ float s[DIM];
    __shared__ float red[256];
    float x0 = seq[(long)tok*DIM + tid*2];
    float x1 = seq[(long)tok*DIM + tid*2 + 1];
    red[tid] = x0*x0 + x1*x1;
    __syncthreads();
    for (int o = 128; o > 0; o >>= 1){
        if (tid < o) red[tid] += red[tid+o];
        __syncthreads();
    }
    float sc = rsqrtf(red[0]*(1.f/DIM) + EPSR);
    float s0 = x0*sc, s1 = x1*sc;
    s[tid*2] = s0; s[tid*2+1] = s1;
    g_s[(long)tok*DIM + tid*2]     = s0;
    g_s[(long)tok*DIM + tid*2 + 1] = s1;
    __syncthreads();
    int w = tid >> 5, lane = tid & 31;   // warp w -> head w
    float ds = 0.f, dg = 0.f;
    for (int i = lane; i < DIM; i += 32){
        float sv = s[i];
        ds += sv * Wstep[i*H + w];
        dg += sv * Wgate[i*H + w];
    }
    for (int o = 16; o; o >>= 1){
        ds += __shfl_down_sync(0xffffffffu, ds, o);
        dg += __shfl_down_sync(0xffffffffu, dg, o);
    }
    if (lane == 0){
        int b = tok / T, t = tok % T;
        int bh = b*H + w;
        g_lr  [(long)bh*T + t] = sigm(ds) * MAXLR * (2.0f/D);
        g_gate[(long)bh*T + t] = sigm(dg);
    }
}

// ------------------- K2: per-chunk momentum / decay gates -------------------
__global__ void k2_chunkgates(const float* __restrict__ Wmom,
                              const float* __restrict__ Wdecay)
{
    int nc = blockIdx.x, b = blockIdx.y;
    int tid = threadIdx.x;          // 256
    __shared__ float m[DIM];
    const float* base = g_s + ((long)b*T + nc*C)*DIM;
    float a0 = 0.f, a1 = 0.f;
    for (int r = 0; r < C; r++){
        a0 += base[(long)r*DIM + tid*2];
        a1 += base[(long)r*DIM + tid*2 + 1];
    }
    m[tid*2] = a0*(1.f/C); m[tid*2+1] = a1*(1.f/C);
    __syncthreads();
    int w = tid >> 5, lane = tid & 31;
    float dm = 0.f, dd = 0.f;
    for (int i = lane; i < DIM; i += 32){
        float v = m[i];
        dm += v * Wmom[i*H + w];
        dd += v * Wdecay[i*H + w];
    }
    for (int o = 16; o; o >>= 1){
        dm += __shfl_down_sync(0xffffffffu, dm, o);
        dd += __shfl_down_sync(0xffffffffu, dd, o);
    }
    if (lane == 0){
        int bh = b*H + w;
        g_mg [bh*NCH + nc] = sigm(dm);
        g_dec[bh*NCH + nc] = sigm(dd);
    }
}

// ------------------- K3: s @ [Wq | Wk | Wv]  (M=32768, K=512, N=1536) -------------------
__global__ void k3_proj(const float* __restrict__ Wq, const float* __restrict__ Wkv)
{
    __shared__ float As[8][132];
    __shared__ float Bs[8][128];
    int tid = threadIdx.x;
    int row0 = blockIdx.y * 128;
    int col0 = blockIdx.x * 128;
    const float* Bp; int ldb, bc0;
    if (col0 < 512){ Bp = Wq;  ldb = 512;  bc0 = col0; }
    else           { Bp = Wkv; ldb = 1024; bc0 = col0 - 512; }
    const float* A = g_s;
    float acc[8][8] = {};
    int a_row = tid >> 1, a_k = (tid & 1)*4;
    int b_k = tid >> 5, b_c = (tid & 31)*4;
    int tx = tid & 15, ty = tid >> 4;
    for (int k0 = 0; k0 < 512; k0 += 8){
        float4 av = *(const float4*)(A + (long)(row0 + a_row)*512 + k0 + a_k);
        As[a_k+0][a_row] = av.x; As[a_k+1][a_row] = av.y;
        As[a_k+2][a_row] = av.z; As[a_k+3][a_row] = av.w;
        *(float4*)&Bs[b_k][b_c] = *(const float4*)(Bp + (long)(k0 + b_k)*ldb + bc0 + b_c);
        __syncthreads();
        #pragma unroll
        for (int kk = 0; kk < 8; kk++){
            float a[8], bb[8];
            *(float4*)(a)    = *(float4*)&As[kk][ty*8];
            *(float4*)(a+4)  = *(float4*)&As[kk][ty*8+4];
            *(float4*)(bb)   = *(float4*)&Bs[kk][tx*8];
            *(float4*)(bb+4) = *(float4*)&Bs[kk][tx*8+4];
            #pragma unroll
            for (int u = 0; u < 8; u++)
                #pragma unroll
                for (int v = 0; v < 8; v++) acc[u][v] += a[u]*bb[v];
        }
        __syncthreads();
    }
    int cbase = col0 + tx*8;
    int mtx = cbase / 512;
    int hh  = (cbase % 512) / 64;
    int j0  = cbase % 64;
    float* dbase = (mtx == 0) ? g_q : (mtx == 1 ? g_k : g_v);
    #pragma unroll
    for (int u = 0; u < 8; u++){
        int r = row0 + ty*8 + u;
        int b = r >> 13, tok = r & 8191;
        float* dst = dbase + ((long)(b*H + hh)*T + tok)*D + j0;
        *(float4*)dst     = make_float4(acc[u][0],acc[u][1],acc[u][2],acc[u][3]);
        *(float4*)(dst+4) = make_float4(acc[u][4],acc[u][5],acc[u][6],acc[u][7]);
    }
}

// ------------------- tiny 64x64x64 GEMM helper (256 thr, 4x4 micro-tile) -------------------
template<class LA, class LB, class ST>
__device__ __forceinline__ void mm64(int tid, LA la, LB lb, ST st)
{
    int tx = tid & 15, ty = tid >> 4;
    int r0 = ty*4, c0 = tx*4;
    float acc[4][4] = {};
    #pragma unroll 4
    for (int k = 0; k < 64; k++){
        float a[4], bb[4];
        #pragma unroll
        for (int u = 0; u < 4; u++) a[u] = la(r0+u, k);
        #pragma unroll
        for (int v = 0; v < 4; v++) bb[v] = lb(k, c0+v);
        #pragma unroll
        for (int u = 0; u < 4; u++)
            #pragma unroll
            for (int v = 0; v < 4; v++) acc[u][v] += a[u]*bb[v];
    }
    #pragma unroll
    for (int u = 0; u < 4; u++)
        #pragma unroll
        for (int v = 0; v < 4; v++) st(r0+u, c0+v, acc[u][v]);
}

// ------------------- K4: per-chunk MLP grads (surprises) -------------------
__global__ void k4_grads(const float* __restrict__ w1, const float* __restrict__ w2)
{
    extern __shared__ float sm[];
    float* sK  = sm;            // 64*65 each
    float* sV  = sK  + 4160;
    float* sW  = sV  + 4160;
    float* sX  = sW  + 4160;
    float* sH  = sX  + 4160;
    float* sDY = sH  + 4160;
    float* slr = sDY + 4160;    // 64
    int nc = blockIdx.x, bh = blockIdx.y;
    int tid = threadIdx.x;
    long base = ((long)bh*T + nc*C)*D;
    for (int idx = tid; idx < 4096; idx += 256){
        int r = idx >> 6, c = idx & 63;
        sK[r*65+c] = g_k[base + idx];
        sV[r*65+c] = g_v[base + idx];
        sW[r*65+c] = w1[idx];
    }
    if (tid < 64) slr[tid] = g_lr[(long)bh*T + nc*C + tid];
    __syncthreads();
    // x = k @ w1
    mm64(tid, [&](int i,int k){ return sK[i*65+k]; },
              [&](int k,int j){ return sW[k*65+j]; },
              [&](int i,int j,float v){ sX[i*65+j] = v; });
    __syncthreads();
    // h = silu(x); reload w2
    for (int idx = tid; idx < 4096; idx += 256){
        int r = idx >> 6, c = idx & 63;
        float x = sX[r*65+c];
        sH[r*65+c] = x * sigm(x);
        sW[r*65+c] = w2[idx];
    }
    __syncthreads();
    // y = h @ w2;  dY = lr*(2/d)*(y - v)   (2/d prefolded into lr)
    mm64(tid, [&](int i,int k){ return sH[i*65+k]; },
              [&](int k,int j){ return sW[k*65+j]; },
              [&](int i,int j,float y){ sDY[i*65+j] = slr[i]*(y - sV[i*65+j]); });
    __syncthreads();
    long gbase = ((long)bh*NCH + nc)*4096;
    // g2 = h^T @ dY  -> store -g2
    mm64(tid, [&](int p,int i){ return sH[i*65+p]; },
              [&](int i,int j){ return sDY[i*65+j]; },
              [&](int p,int j,float v){ g_u2[gbase + p*64 + j] = -v; });
    // dH = dY @ w2^T -> sV (v consumed)
    mm64(tid, [&](int i,int j){ return sDY[i*65+j]; },
              [&](int j,int p){ return sW[p*65+j]; },
              [&](int i,int p,float v){ sV[i*65+p] = v; });
    __syncthreads();
    // dX = dH * silu'(x)   in-place into sX
    for (int idx = tid; idx < 4096; idx += 256){
        int r = idx >> 6, c = idx & 63;
        float x = sX[r*65+c];
        float sg = sigm(x);
        sX[r*65+c] = sV[r*65+c] * sg * (1.f + x*(1.f - sg));
    }
    __syncthreads();
    // g1 = k^T @ dX -> store -g1
    mm64(tid, [&](int p,int i){ return sK[i*65+p]; },
              [&](int i,int j){ return sX[i*65+j]; },
              [&](int p,int j,float v){ g_u1[gbase + p*64 + j] = -v; });
}

// ------------------- K5: momentum + decay scans (in-place -> updates) -------------------
__global__ void k5_scan()
{
    int e  = blockIdx.x*blockDim.x + threadIdx.x;   // 0..4095
    int bh = blockIdx.y;
    float* g = blockIdx.z ? g_u2 : g_u1;
    const float* mg = g_mg  + bh*NCH;
    const float* dc = g_dec + bh*NCH;
    float m = 0.f, u = 0.f;
    long base = (long)bh*NCH*4096 + e;
    for (int t = 0; t < NCH; t++){
        float s = g[base + (long)t*4096];
        m = mg[t]*m + s;
        u = (1.f - dc[t])*u + m;
        g[base + (long)t*4096] = u;
    }
}

// ------------------- K6: retrieve (fast-weight apply + head RMSNorm + gate) -------------------
__global__ void k6_retrieve(const float* __restrict__ w1, const float* __restrict__ w2,
                            const float* __restrict__ gamma)
{
    extern __shared__ float sm[];
    float* sQ = sm;            // 64*65
    float* sW = sQ + 4160;
    float* sX = sW + 4160;
    int nc = blockIdx.x, bh = blockIdx.y;
    int tid = threadIdx.x;
    int h = bh % H, b = bh / H;
    long ubase = ((long)bh*NCH + nc)*4096;
    for (int idx = tid; idx < 4096; idx += 256){
        int r = idx >> 6, c = idx & 63;
        int tok = nc*C + r + (C-1);                   // causal shift
        sQ[r*65+c] = (tok < T) ? g_q[((long)bh*T + tok)*D + c] : 0.f;
        sW[r*65+c] = w1[idx] + g_u1[ubase + idx];
    }
    __syncthreads();
    // x = silu(q @ (w1+u1))
    mm64(tid, [&](int i,int k){ return sQ[i*65+k]; },
              [&](int k,int j){ return sW[k*65+j]; },
              [&](int i,int j,float v){ sX[i*65+j] = v * sigm(v); });
    __syncthreads();
    for (int idx = tid; idx < 4096; idx += 256){
        int r = idx >> 6, c = idx & 63;
        sW[r*65+c] = w2[idx] + g_u2[ubase + idx];
    }
    __syncthreads();
    // out = x @ (w2+u2)  -> reuse sQ
    mm64(tid, [&](int i,int k){ return sX[i*65+k]; },
              [&](int k,int j){ return sW[k*65+j]; },
              [&](int i,int j,float v){ sQ[i*65+j] = v; });
    __syncthreads();
    // per-row RMSNorm(d=64) * (gamma+1) * gate, write merged-head layout
    int row = tid >> 2, sub = tid & 3;                // 4 lanes per row
    float ss = 0.f;
    for (int j = sub; j < 64; j += 4){ float v = sQ[row*65+j]; ss += v*v; }
    ss += __shfl_xor_sync(0xffffffffu, ss, 1);
    ss += __shfl_xor_sync(0xffffffffu, ss, 2);
    float sc = rsqrtf(ss*(1.f/64) + EPSR);
    int tokq = nc*C + row + (C-1);
    float gate = (tokq < T) ? g_gate[(long)bh*T + tokq] : 0.f;
    float* dst = g_vals + ((long)b*T + nc*C + row)*DIM + h*D;
    for (int j = sub; j < 64; j += 4)
        dst[j] = sQ[row*65+j]*sc*(gamma[h*D + j] + 1.f)*gate;
}

// ------------------- K7: vals @ Wcombine with causal output shift -------------------
__global__ void k7_combine(const float* __restrict__ Wc, float* __restrict__ out)
{
    __shared__ float As[8][132];
    __shared__ float Bs[8][128];
    int tid = threadIdx.x;
    int row0 = blockIdx.y * 128;
    int col0 = blockIdx.x * 128;
    const float* A = g_vals;
    float acc[8][8] = {};
    int a_row = tid >> 1, a_k = (tid & 1)*4;
    int b_k = tid >> 5, b_c = (tid & 31)*4;
    int tx = tid & 15, ty = tid >> 4;
    for (int k0 = 0; k0 < 512; k0 += 8){
        float4 av = *(const float4*)(A + (long)(row0 + a_row)*512 + k0 + a_k);
        As[a_k+0][a_row] = av.x; As[a_k+1][a_row] = av.y;
        As[a_k+2][a_row] = av.z; As[a_k+3][a_row] = av.w;
        *(float4*)&Bs[b_k][b_c] = *(const float4*)(Wc + (long)(k0 + b_k)*512 + col0 + b_c);
        __syncthreads();
        #pragma unroll
        for (int kk = 0; kk < 8; kk++){
            float a[8], bb[8];
            *(float4*)(a)    = *(float4*)&As[kk][ty*8];
            *(float4*)(a+4)  = *(float4*)&As[kk][ty*8+4];
            *(float4*)(bb)   = *(float4*)&Bs[kk][tx*8];
            *(float4*)(bb+4) = *(float4*)&Bs[kk][tx*8+4];
            #pragma unroll
            for (int u = 0; u < 8; u++)
                #pragma unroll
                for (int v = 0; v < 8; v++) acc[u][v] += a[u]*bb[v];
        }
        __syncthreads();
    }
    int c0 = col0 + tx*8;
    #pragma unroll
    for (int u = 0; u < 8; u++){
        int r = row0 + ty*8 + u;
        int b = r >> 13, jr = r & 8191;
        if (jr <= T - C){        // jr+63 <= 8191
            float* dst = out + ((long)b*T + jr + (C-1))*DIM + c0;
            *(float4*)dst     = make_float4(acc[u][0],acc[u][1],acc[u][2],acc[u][3]);
            *(float4*)(dst+4) = make_float4(acc[u][4],acc[u][5],acc[u][6],acc[u][7]);
        }
    }
}

// ------------------- K0: zero the first c-1 output tokens -------------------
__global__ void k0_zero(float* __restrict__ out)
{
    int i = blockIdx.x*blockDim.x + threadIdx.x;
    const int per = (C-1)*DIM;                 // 32256
    if (i < BB*per){
        int b = i / per, rem = i % per;
        out[(long)b*T*DIM + rem] = 0.f;
    }
}

// ------------------- launch -------------------
extern "C" void kernel_launch(void* const* d_in, const int* in_sizes, int n_in,
                              void* d_out, int out_size)
{
    const float* seq   = (const float*)d_in[0];
    const float* w1    = (const float*)d_in[1];
    const float* w2    = (const float*)d_in[2];
    const float* Wq    = (const float*)d_in[3];
    const float* Wkv   = (const float*)d_in[4];
    const float* Wstep = (const float*)d_in[5];
    const float* Wmom  = (const float*)d_in[6];
    const float* Wdecay= (const float*)d_in[7];
    const float* Wgate = (const float*)d_in[8];
    const float* Wcomb = (const float*)d_in[9];
    const float* gamma = (const float*)d_in[10];
    float* out = (float*)d_out;

    // dynamic smem limits (idempotent; not a stream op, capture-safe)
    cudaFuncSetAttribute(k4_grads,    cudaFuncAttributeMaxDynamicSharedMemorySize, 101376);
    cudaFuncSetAttribute(k6_retrieve, cudaFuncAttributeMaxDynamicSharedMemorySize, 50176);

    k1_rmsnorm<<<BB*T, 256>>>(seq, Wstep, Wgate);
    k2_chunkgates<<<dim3(NCH, BB), 256>>>(Wmom, Wdecay);
    k3_proj<<<dim3(12, 256), 256>>>(Wq, Wkv);
    k4_grads<<<dim3(NCH, BH), 256, (6*4160 + 64)*sizeof(float)>>>(w1, w2);
    k5_scan<<<dim3(16, BH, 2), 256>>>();
    k6_retrieve<<<dim3(NCH, BH), 256, 3*4160*sizeof(float)>>>(w1, w2, gamma);
    k7_combine<<<dim3(4, 256), 256>>>(Wcomb, out);
    k0_zero<<<504, 256>>>(out);
}

// round 3
// speedup vs baseline: 1.0327x; 1.0327x over previous
#include <cuda_runtime.h>
#include <stdint.h>
#include <math.h>

#define BB   4
#define T    8192
#define DIM  512
#define H    8
#define D    64
#define C    64
#define NCH  128           // T/C
#define BH   32            // BB*H
#define EPSR 1.1920929e-07f
#define MAXLR 0.01f

// ------------------- scratch (device globals; no allocs allowed) -------------------
__device__ float g_s   [BB*T*DIM];     // rmsnorm(seq)
__device__ float g_q   [BH*T*D];       // per-head q (unshifted token index)
__device__ float g_k   [BH*T*D];
__device__ float g_v   [BH*T*D];
__device__ float g_lr  [BH*T];         // sigmoid(s@Wstep)*MAXLR*(2/D)  (prefolded)
__device__ float g_gate[BH*T];         // sigmoid(s@Wgate)
__device__ float g_mg  [BH*NCH];
__device__ float g_dec [BH*NCH];
__device__ float g_u1  [(long)BH*NCH*D*D];  // surprises -> (in-place scan) -> updates
__device__ float g_u2  [(long)BH*NCH*D*D];
__device__ float g_vals[BB*T*DIM];     // merged-head retrieve output (pre-combine)

__device__ __forceinline__ float sigm(float x){ return 1.f/(1.f+__expf(-x)); }

// ---------------- packed f32x2 helpers (Blackwell FFMA2; non-'a' PTX) ----------------
typedef unsigned long long u64t;
__device__ __forceinline__ u64t pack2(float x, float y){
    u64t r; asm("mov.b64 %0, {%1, %2};" : "=l"(r) : "f"(x), "f"(y)); return r;
}
__device__ __forceinline__ u64t fma2(u64t a, u64t b, u64t c){
    u64t d; asm("fma.rn.f32x2 %0, %1, %2, %3;" : "=l"(d) : "l"(a), "l"(b), "l"(c)); return d;
}
__device__ __forceinline__ float2 unpack2(u64t p){
    float2 f; asm("mov.b64 {%0, %1}, %2;" : "=f"(f.x), "=f"(f.y) : "l"(p)); return f;
}

// ------------------- K1: rmsnorm + per-token lr & gate -------------------
__global__ void k1_rmsnorm(const float* __restrict__ seq,
                           const float* __restrict__ Wstep,
                           const float* __restrict__ Wgate)
{
    int tok = blockIdx.x;           // 0..BB*T-1
    int tid = threadIdx.x;          // 256
    __shared__ float s[DIM];
    __shared__ float red[256];
    float x0 = seq[(long)tok*DIM + tid*2];
    float x1 = seq[(long)tok*DIM + tid*2 + 1];
    red[tid] = x0*x0 + x1*x1;
    __syncthreads();
    for (int o = 128; o > 0; o >>= 1){
        if (tid < o) red[tid] += red[tid+o];
        __syncthreads();
    }
    float sc = rsqrtf(red[0]*(1.f/DIM) + EPSR);
    float s0 = x0*sc, s1 = x1*sc;
    s[tid*2] = s0; s[tid*2+1] = s1;
    g_s[(long)tok*DIM + tid*2]     = s0;
    g_s[(long)tok*DIM + tid*2 + 1] = s1;
    __syncthreads();
    int w = tid >> 5, lane = tid & 31;   // warp w -> head w
    float ds = 0.f, dg = 0.f;
    for (int i = lane; i < DIM; i += 32){
        float sv = s[i];
        ds += sv * Wstep[i*H + w];
        dg += sv * Wgate[i*H + w];
    }
    for (int o = 16; o; o >>= 1){
        ds += __shfl_down_sync(0xffffffffu, ds, o);
        dg += __shfl_down_sync(0xffffffffu, dg, o);
    }
    if (lane == 0){
        int b = tok / T, t = tok % T;
        int bh = b*H + w;
        g_lr  [(long)bh*T + t] = sigm(ds) * MAXLR * (2.0f/D);
        g_gate[(long)bh*T + t] = sigm(dg);
    }
}

// ------------------- K2: per-chunk momentum / decay gates -------------------
__global__ void k2_chunkgates(const float* __restrict__ Wmom,
                              const float* __restrict__ Wdecay)
{
    int nc = blockIdx.x, b = blockIdx.y;
    int tid = threadIdx.x;          // 256
    __shared__ float m[DIM];
    const float* base = g_s + ((long)b*T + nc*C)*DIM;
    float a0 = 0.f, a1 = 0.f;
    for (int r = 0; r < C; r++){
        a0 += base[(long)r*DIM + tid*2];
        a1 += base[(long)r*DIM + tid*2 + 1];
    }
    m[tid*2] = a0*(1.f/C); m[tid*2+1] = a1*(1.f/C);
    __syncthreads();
    int w = tid >> 5, lane = tid & 31;
    float dm = 0.f, dd = 0.f;
    for (int i = lane; i < DIM; i += 32){
        float v = m[i];
        dm += v * Wmom[i*H + w];
        dd += v * Wdecay[i*H + w];
    }
    for (int o = 16; o; o >>= 1){
        dm += __shfl_down_sync(0xffffffffu, dm, o);
        dd += __shfl_down_sync(0xffffffffu, dd, o);
    }
    if (lane == 0){
        int bh = b*H + w;
        g_mg [bh*NCH + nc] = sigm(dm);
        g_dec[bh*NCH + nc] = sigm(dd);
    }
}

// ------------------- K3: s @ [Wq | Wk | Wv]  (M=32768, K=512, N=1536), FFMA2 -------------------
__global__ void __launch_bounds__(256, 2)
k3_proj(const float* __restrict__ Wq, const float* __restrict__ Wkv)
{
    __shared__ float As[16][132];
    __shared__ float Bs[16][128];
    int tid = threadIdx.x;
    int row0 = blockIdx.y * 128;
    int col0 = blockIdx.x * 128;
    const float* Bp; int ldb, bc0;
    if (col0 < 512){ Bp = Wq;  ldb = 512;  bc0 = col0; }
    else           { Bp = Wkv; ldb = 1024; bc0 = col0 - 512; }
    const float* A = g_s;
    u64t acc[8][4];
    #pragma unroll
    for (int u = 0; u < 8; u++)
        #pragma unroll
        for (int v = 0; v < 4; v++) acc[u][v] = 0ull;

    int a_row = tid >> 1, a_k = (tid & 1)*8;
    int b_k = tid >> 4, b_c = (tid & 15)*8;
    int tx = tid & 15, ty = tid >> 4;
    for (int k0 = 0; k0 < 512; k0 += 16){
        #pragma unroll
        for (int h2 = 0; h2 < 2; h2++){
            float4 av = *(const float4*)(A + (long)(row0 + a_row)*512 + k0 + a_k + h2*4);
            As[a_k+h2*4+0][a_row] = av.x; As[a_k+h2*4+1][a_row] = av.y;
            As[a_k+h2*4+2][a_row] = av.z; As[a_k+h2*4+3][a_row] = av.w;
        }
        *(float4*)&Bs[b_k][b_c]   = *(const float4*)(Bp + (long)(k0 + b_k)*ldb + bc0 + b_c);
        *(float4*)&Bs[b_k][b_c+4] = *(const float4*)(Bp + (long)(k0 + b_k)*ldb + bc0 + b_c + 4);
        __syncthreads();
        #pragma unroll
        for (int kk = 0; kk < 16; kk++){
            float a[8], bb[8];
            *(float4*)(a)    = *(float4*)&As[kk][ty*8];
            *(float4*)(a+4)  = *(float4*)&As[kk][ty*8+4];
            *(float4*)(bb)   = *(float4*)&Bs[kk][tx*8];
            *(float4*)(bb+4) = *(float4*)&Bs[kk][tx*8+4];
            u64t a2[8], b2[4];
            #pragma unroll
            for (int v = 0; v < 4; v++) b2[v] = pack2(bb[2*v], bb[2*v+1]);
            #pragma unroll
            for (int u = 0; u < 8; u++) a2[u] = pack2(a[u], a[u]);
            #pragma unroll
            for (int u = 0; u < 8; u++)
                #pragma unroll
                for (int v = 0; v < 4; v++) acc[u][v] = fma2(a2[u], b2[v], acc[u][v]);
        }
        __syncthreads();
    }
    int cbase = col0 + tx*8;
    int mtx = cbase / 512;
    int hh  = (cbase % 512) / 64;
    int j0  = cbase % 64;
    float* dbase = (mtx == 0) ? g_q : (mtx == 1 ? g_k : g_v);
    #pragma unroll
    for (int u = 0; u < 8; u++){
        int r = row0 + ty*8 + u;
        int b = r >> 13, tok = r & 8191;
        float* dst = dbase + ((long)(b*H + hh)*T + tok)*D + j0;
        float2 c0_ = unpack2(acc[u][0]), c1_ = unpack2(acc[u][1]);
        float2 c2_ = unpack2(acc[u][2]), c3_ = unpack2(acc[u][3]);
        *(float4*)dst     = make_float4(c0_.x, c0_.y, c1_.x, c1_.y);
        *(float4*)(dst+4) = make_float4(c2_.x, c2_.y, c3_.x, c3_.y);
    }
}

// ------------------- tiny 64x64x64 GEMM helper (256 thr, 4x4 micro-tile) -------------------
template<class LA, class LB, class ST>
__device__ __forceinline__ void mm64(int tid, LA la, LB lb, ST st)
{
    int tx = tid & 15, ty = tid >> 4;
    int r0 = ty*4, c0 = tx*4;
    float acc[4][4] = {};
    #pragma unroll 4
    for (int k = 0; k < 64; k++){
        float a[4], bb[4];
        #pragma unroll
        for (int u = 0; u < 4; u++) a[u] = la(r0+u, k);
        #pragma unroll
        for (int v = 0; v < 4; v++) bb[v] = lb(k, c0+v);
        #pragma unroll
        for (int u = 0; u < 4; u++)
            #pragma unroll
            for (int v = 0; v < 4; v++) acc[u][v] += a[u]*bb[v];
    }
    #pragma unroll
    for (int u = 0; u < 4; u++)
        #pragma unroll
        for (int v = 0; v < 4; v++) st(r0+u, c0+v, acc[u][v]);
}

// ------------------- K4: per-chunk MLP grads (surprises) -------------------
__global__ void k4_grads(const float* __restrict__ w1, const float* __restrict__ w2)
{
    extern __shared__ float sm[];
    float* sK  = sm;            // 64*65 each
    float* sV  = sK  + 4160;
    float* sW  = sV  + 4160;
    float* sX  = sW  + 4160;
    float* sH  = sX  + 4160;
    float* sDY = sH  + 4160;
    float* slr = sDY + 4160;    // 64
    int nc = blockIdx.x, bh = blockIdx.y;
    int tid = threadIdx.x;
    long base = ((long)bh*T + nc*C)*D;
    for (int idx = tid; idx < 4096; idx += 256){
        int r = idx >> 6, c = idx & 63;
        sK[r*65+c] = g_k[base + idx];
        sV[r*65+c] = g_v[base + idx];
        sW[r*65+c] = w1[idx];
    }
    if (tid < 64) slr[tid] = g_lr[(long)bh*T + nc*C + tid];
    __syncthreads();
    // x = k @ w1
    mm64(tid, [&](int i,int k){ return sK[i*65+k]; },
              [&](int k,int j){ return sW[k*65+j]; },
              [&](int i,int j,float v){ sX[i*65+j] = v; });
    __syncthreads();
    // h = silu(x); reload w2
    for (int idx = tid; idx < 4096; idx += 256){
        int r = idx >> 6, c = idx & 63;
        float x = sX[r*65+c];
        sH[r*65+c] = x * sigm(x);
        sW[r*65+c] = w2[idx];
    }
    __syncthreads();
    // y = h @ w2;  dY = lr*(2/d)*(y - v)
    mm64(tid, [&](int i,int k){ return sH[i*65+k]; },
              [&](int k,int j){ return sW[k*65+j]; },
              [&](int i,int j,float y){ sDY[i*65+j] = slr[i]*(y - sV[i*65+j]); });
    __syncthreads();
    long gbase = ((long)bh*NCH + nc)*4096;
    // g2 = h^T @ dY  -> store -g2
    mm64(tid, [&](int p,int i){ return sH[i*65+p]; },
              [&](int i,int j){ return sDY[i*65+j]; },
              [&](int p,int j,float v){ g_u2[gbase + p*64 + j] = -v; });
    // dH = dY @ w2^T -> sV
    mm64(tid, [&](int i,int j){ return sDY[i*65+j]; },
              [&](int j,int p){ return sW[p*65+j]; },
              [&](int i,int p,float v){ sV[i*65+p] = v; });
    __syncthreads();
    // dX = dH * silu'(x)
    for (int idx = tid; idx < 4096; idx += 256){
        int r = idx >> 6, c = idx & 63;
        float x = sX[r*65+c];
        float sg = sigm(x);
        sX[r*65+c] = sV[r*65+c] * sg * (1.f + x*(1.f - sg));
    }
    __syncthreads();
    // g1 = k^T @ dX -> store -g1
    mm64(tid, [&](int p,int i){ return sK[i*65+p]; },
              [&](int i,int j){ return sX[i*65+j]; },
              [&](int p,int j,float v){ g_u1[gbase + p*64 + j] = -v; });
}

// ------------------- K5: momentum + decay scans (in-place -> updates) -------------------
__global__ void k5_scan()
{
    int e  = blockIdx.x*blockDim.x + threadIdx.x;   // 0..4095
    int bh = blockIdx.y;
    float* g = blockIdx.z ? g_u2 : g_u1;
    const float* mg = g_mg  + bh*NCH;
    const float* dc = g_dec + bh*NCH;
    float m = 0.f, u = 0.f;
    long base = (long)bh*NCH*4096 + e;
    for (int t = 0; t < NCH; t++){
        float s = g[base + (long)t*4096];
        m = mg[t]*m + s;
        u = (1.f - dc[t])*u + m;
        g[base + (long)t*4096] = u;
    }
}

// ------------------- K6: retrieve (fast-weight apply + head RMSNorm + gate) -------------------
__global__ void k6_retrieve(const float* __restrict__ w1, const float* __restrict__ w2,
                            const float* __restrict__ gamma)
{
    extern __shared__ float sm[];
    float* sQ = sm;            // 64*65
    float* sW = sQ + 4160;
    float* sX = sW + 4160;
    int nc = blockIdx.x, bh = blockIdx.y;
    int tid = threadIdx.x;
    int h = bh % H, b = bh / H;
    long ubase = ((long)bh*NCH + nc)*4096;
    for (int idx = tid; idx < 4096; idx += 256){
        int r = idx >> 6, c = idx & 63;
        int tok = nc*C + r + (C-1);                   // causal shift
        sQ[r*65+c] = (tok < T) ? g_q[((long)bh*T + tok)*D + c] : 0.f;
        sW[r*65+c] = w1[idx] + g_u1[ubase + idx];
    }
    __syncthreads();
    // x = silu(q @ (w1+u1))
    mm64(tid, [&](int i,int k){ return sQ[i*65+k]; },
              [&](int k,int j){ return sW[k*65+j]; },
              [&](int i,int j,float v){ sX[i*65+j] = v * sigm(v); });
    __syncthreads();
    for (int idx = tid; idx < 4096; idx += 256){
        int r = idx >> 6, c = idx & 63;
        sW[r*65+c] = w2[idx] + g_u2[ubase + idx];
    }
    __syncthreads();
    // out = x @ (w2+u2)  -> reuse sQ
    mm64(tid, [&](int i,int k){ return sX[i*65+k]; },
              [&](int k,int j){ return sW[k*65+j]; },
              [&](int i,int j,float v){ sQ[i*65+j] = v; });
    __syncthreads();
    // per-row RMSNorm(d=64) * (gamma+1) * gate, merged-head layout
    int row = tid >> 2, sub = tid & 3;
    float ss = 0.f;
    for (int j = sub; j < 64; j += 4){ float v = sQ[row*65+j]; ss += v*v; }
    ss += __shfl_xor_sync(0xffffffffu, ss, 1);
    ss += __shfl_xor_sync(0xffffffffu, ss, 2);
    float sc = rsqrtf(ss*(1.f/64) + EPSR);
    int tokq = nc*C + row + (C-1);
    float gate = (tokq < T) ? g_gate[(long)bh*T + tokq] : 0.f;
    float* dst = g_vals + ((long)b*T + nc*C + row)*DIM + h*D;
    for (int j = sub; j < 64; j += 4)
        dst[j] = sQ[row*65+j]*sc*(gamma[h*D + j] + 1.f)*gate;
}

// ------------------- K7: vals @ Wcombine with causal output shift, FFMA2 -------------------
__global__ void __launch_bounds__(256, 2)
k7_combine(const float* __restrict__ Wc, float* __restrict__ out)
{
    __shared__ float As[16][132];
    __shared__ float Bs[16][128];
    int tid = threadIdx.x;
    int row0 = blockIdx.y * 128;
    int col0 = blockIdx.x * 128;
    const float* A = g_vals;
    u64t acc[8][4];
    #pragma unroll
    for (int u = 0; u < 8; u++)
        #pragma unroll
        for (int v = 0; v < 4; v++) acc[u][v] = 0ull;

    int a_row = tid >> 1, a_k = (tid & 1)*8;
    int b_k = tid >> 4, b_c = (tid & 15)*8;
    int tx = tid & 15, ty = tid >> 4;
    for (int k0 = 0; k0 < 512; k0 += 16){
        #pragma unroll
        for (int h2 = 0; h2 < 2; h2++){
            float4 av = *(const float4*)(A + (long)(row0 + a_row)*512 + k0 + a_k + h2*4);
            As[a_k+h2*4+0][a_row] = av.x; As[a_k+h2*4+1][a_row] = av.y;
            As[a_k+h2*4+2][a_row] = av.z; As[a_k+h2*4+3][a_row] = av.w;
        }
        *(float4*)&Bs[b_k][b_c]   = *(const float4*)(Wc + (long)(k0 + b_k)*512 + col0 + b_c);
        *(float4*)&Bs[b_k][b_c+4] = *(const float4*)(Wc + (long)(k0 + b_k)*512 + col0 + b_c + 4);
        __syncthreads();
        #pragma unroll
        for (int kk = 0; kk < 16; kk++){
            float a[8], bb[8];
            *(float4*)(a)    = *(float4*)&As[kk][ty*8];
            *(float4*)(a+4)  = *(float4*)&As[kk][ty*8+4];
            *(float4*)(bb)   = *(float4*)&Bs[kk][tx*8];
            *(float4*)(bb+4) = *(float4*)&Bs[kk][tx*8+4];
            u64t a2[8], b2[4];
            #pragma unroll
            for (int v = 0; v < 4; v++) b2[v] = pack2(bb[2*v], bb[2*v+1]);
            #pragma unroll
            for (int u = 0; u < 8; u++) a2[u] = pack2(a[u], a[u]);
            #pragma unroll
            for (int u = 0; u < 8; u++)
                #pragma unroll
                for (int v = 0; v < 4; v++) acc[u][v] = fma2(a2[u], b2[v], acc[u][v]);
        }
        __syncthreads();
    }
    int c0 = col0 + tx*8;
    #pragma unroll
    for (int u = 0; u < 8; u++){
        int r = row0 + ty*8 + u;
        int b = r >> 13, jr = r & 8191;
        if (jr <= T - C){        // jr+63 <= 8191
            float* dst = out + ((long)b*T + jr + (C-1))*DIM + c0;
            float2 c0_ = unpack2(acc[u][0]), c1_ = unpack2(acc[u][1]);
            float2 c2_ = unpack2(acc[u][2]), c3_ = unpack2(acc[u][3]);
            *(float4*)dst     = make_float4(c0_.x, c0_.y, c1_.x, c1_.y);
            *(float4*)(dst+4) = make_float4(c2_.x, c2_.y, c3_.x, c3_.y);
        }
    }
}

// ------------------- K0: zero the first c-1 output tokens -------------------
__global__ void k0_zero(float* __restrict__ out)
{
    int i = blockIdx.x*blockDim.x + threadIdx.x;
    const int per = (C-1)*DIM;                 // 32256
    if (i < BB*per){
        int b = i / per, rem = i % per;
        out[(long)b*T*DIM + rem] = 0.f;
    }
}

// ------------------- launch -------------------
extern "C" void kernel_launch(void* const* d_in, const int* in_sizes, int n_in,
                              void* d_out, int out_size)
{
    const float* seq   = (const float*)d_in[0];
    const float* w1    = (const float*)d_in[1];
    const float* w2    = (const float*)d_in[2];
    const float* Wq    = (const float*)d_in[3];
    const float* Wkv   = (const float*)d_in[4];
    const float* Wstep = (const float*)d_in[5];
    const float* Wmom  = (const float*)d_in[6];
    const float* Wdecay= (const float*)d_in[7];
    const float* Wgate = (const float*)d_in[8];
    const float* Wcomb = (const float*)d_in[9];
    const float* gamma = (const float*)d_in[10];
    float* out = (float*)d_out;

    cudaFuncSetAttribute(k4_grads,    cudaFuncAttributeMaxDynamicSharedMemorySize, 101376);
    cudaFuncSetAttribute(k6_retrieve, cudaFuncAttributeMaxDynamicSharedMemorySize, 50176);

    k1_rmsnorm<<<BB*T, 256>>>(seq, Wstep, Wgate);
    k2_chunkgates<<<dim3(NCH, BB), 256>>>(Wmom, Wdecay);
    k3_proj<<<dim3(12, 256), 256>>>(Wq, Wkv);
    k4_grads<<<dim3(NCH, BH), 256, (6*4160 + 64)*sizeof(float)>>>(w1, w2);
    k5_scan<<<dim3(16, BH, 2), 256>>>();
    k6_retrieve<<<dim3(NCH, BH), 256, 3*4160*sizeof(float)>>>(w1, w2, gamma);
    k7_combine<<<dim3(4, 256), 256>>>(Wcomb, out);
    k0_zero<<<504, 256>>>(out);
}

// round 4
// speedup vs baseline: 1.4995x; 1.4520x over previous
#include <cuda_runtime.h>
#include <cuda_bf16.h>
#include <stdint.h>
#include <math.h>

#define BB   4
#define T    8192
#define DIM  512
#define H    8
#define D    64
#define C    64
#define NCH  128           // T/C
#define BH   32            // BB*H
#define EPSR 1.1920929e-07f
#define MAXLR 0.01f

// ------------------- scratch (device globals; no allocs allowed) -------------------
__device__ float g_s   [BB*T*DIM];     // rmsnorm(seq)
__device__ float g_q   [BH*T*D];
__device__ float g_k   [BH*T*D];
__device__ float g_v   [BH*T*D];
__device__ float g_lr  [BH*T];         // sigmoid(s@Wstep)*MAXLR*(2/D) (prefolded)
__device__ float g_gate[BH*T];
__device__ float g_mg  [BH*NCH];
__device__ float g_dec [BH*NCH];
__device__ float g_u1  [(long)BH*NCH*D*D];
__device__ float g_u2  [(long)BH*NCH*D*D];
__device__ float g_vals[BB*T*DIM];

__device__ __forceinline__ float sigm(float x){ return 1.f/(1.f+__expf(-x)); }

__device__ __forceinline__ uint32_t smem_u32(const void* p){
    uint32_t a;
    asm("{ .reg .u64 t; cvta.to.shared.u64 t, %1; cvt.u32.u64 %0, t; }" : "=r"(a) : "l"(p));
    return a;
}
__device__ __forceinline__ void ldm4(uint32_t* r, uint32_t addr){
    asm volatile("ldmatrix.sync.aligned.m8n8.x4.shared.b16 {%0,%1,%2,%3}, [%4];"
                 : "=r"(r[0]),"=r"(r[1]),"=r"(r[2]),"=r"(r[3]) : "r"(addr));
}
__device__ __forceinline__ void ldm4t(uint32_t* r, uint32_t addr){
    asm volatile("ldmatrix.sync.aligned.m8n8.x4.trans.shared.b16 {%0,%1,%2,%3}, [%4];"
                 : "=r"(r[0]),"=r"(r[1]),"=r"(r[2]),"=r"(r[3]) : "r"(addr));
}
__device__ __forceinline__ void mma16816(float* c, const uint32_t* a, uint32_t b0, uint32_t b1){
    asm volatile("mma.sync.aligned.m16n8k16.row.col.f32.bf16.bf16.f32 "
                 "{%0,%1,%2,%3}, {%4,%5,%6,%7}, {%8,%9}, {%0,%1,%2,%3};"
                 : "+f"(c[0]),"+f"(c[1]),"+f"(c[2]),"+f"(c[3])
                 : "r"(a[0]),"r"(a[1]),"r"(a[2]),"r"(a[3]), "r"(b0),"r"(b1));
}
// split a float into bf16 hi + bf16 lo, packed as two halves of consecutive pairs
__device__ __forceinline__ void bsplit(float v, uint16_t& hi, uint16_t& lo){
    __nv_bfloat16 h = __float2bfloat16(v);
    __nv_bfloat16 l = __float2bfloat16(v - __bfloat162float(h));
    hi = __bfloat16_as_ushort(h);
    lo = __bfloat16_as_ushort(l);
}

// ------------------- K1: rmsnorm + per-token lr & gate -------------------
__global__ void k1_rmsnorm(const float* __restrict__ seq,
                           const float* __restrict__ Wstep,
                           const float* __restrict__ Wgate)
{
    int tok = blockIdx.x;
    int tid = threadIdx.x;
    __shared__ float s[DIM];
    __shared__ float red[256];
    float x0 = seq[(long)tok*DIM + tid*2];
    float x1 = seq[(long)tok*DIM + tid*2 + 1];
    red[tid] = x0*x0 + x1*x1;
    __syncthreads();
    for (int o = 128; o > 0; o >>= 1){
        if (tid < o) red[tid] += red[tid+o];
        __syncthreads();
    }
    float sc = rsqrtf(red[0]*(1.f/DIM) + EPSR);
    float s0 = x0*sc, s1 = x1*sc;
    s[tid*2] = s0; s[tid*2+1] = s1;
    g_s[(long)tok*DIM + tid*2]     = s0;
    g_s[(long)tok*DIM + tid*2 + 1] = s1;
    __syncthreads();
    int w = tid >> 5, lane = tid & 31;
    float ds = 0.f, dg = 0.f;
    for (int i = lane; i < DIM; i += 32){
        float sv = s[i];
        ds += sv * Wstep[i*H + w];
        dg += sv * Wgate[i*H + w];
    }
    for (int o = 16; o; o >>= 1){
        ds += __shfl_down_sync(0xffffffffu, ds, o);
        dg += __shfl_down_sync(0xffffffffu, dg, o);
    }
    if (lane == 0){
        int b = tok / T, t = tok % T;
        int bh = b*H + w;
        g_lr  [(long)bh*T + t] = sigm(ds) * MAXLR * (2.0f/D);
        g_gate[(long)bh*T + t] = sigm(dg);
    }
}

// ------------------- K2: per-chunk momentum / decay gates -------------------
__global__ void k2_chunkgates(const float* __restrict__ Wmom,
                              const float* __restrict__ Wdecay)
{
    int nc = blockIdx.x, b = blockIdx.y;
    int tid = threadIdx.x;
    __shared__ float m[DIM];
    const float* base = g_s + ((long)b*T + nc*C)*DIM;
    float a0 = 0.f, a1 = 0.f;
    for (int r = 0; r < C; r++){
        a0 += base[(long)r*DIM + tid*2];
        a1 += base[(long)r*DIM + tid*2 + 1];
    }
    m[tid*2] = a0*(1.f/C); m[tid*2+1] = a1*(1.f/C);
    __syncthreads();
    int w = tid >> 5, lane = tid & 31;
    float dm = 0.f, dd = 0.f;
    for (int i = lane; i < DIM; i += 32){
        float v = m[i];
        dm += v * Wmom[i*H + w];
        dd += v * Wdecay[i*H + w];
    }
    for (int o = 16; o; o >>= 1){
        dm += __shfl_down_sync(0xffffffffu, dm, o);
        dd += __shfl_down_sync(0xffffffffu, dd, o);
    }
    if (lane == 0){
        int bh = b*H + w;
        g_mg [bh*NCH + nc] = sigm(dm);
        g_dec[bh*NCH + nc] = sigm(dd);
    }
}

// ===================== tensor-core bf16 2-split GEMM (mma.sync) =====================
// mode 0: [q|k|v] = g_s[32768,512] @ [Wq|Wkv] (N=1536)   grid(12,256)
// mode 1: out = g_vals[32768,512] @ Wc (N=512) with causal shift   grid(4,256)
#define PA 40     // A smem pitch in halves (128 rows)
#define PB 136    // B smem pitch in halves (32 rows, 128 cols)
__global__ void __launch_bounds__(256, 2)
kmma(const float* __restrict__ W0, const float* __restrict__ W1,
     float* __restrict__ outp, int mode)
{
    __shared__ __align__(16) uint16_t Ah[128*PA], Al[128*PA];
    __shared__ __align__(16) uint16_t Bh[32*PB],  Bl[32*PB];

    int tid = threadIdx.x, wid = tid >> 5, l = tid & 31;
    int wm = wid & 1, wn = wid >> 1;      // warp tile: rows wm*64..+63, cols wn*32..+31
    int row0 = blockIdx.y * 128;
    int col0 = blockIdx.x * 128;

    const float* A; const float* Bp; int ldb, bc0;
    if (mode == 0){
        A = g_s;
        if (col0 < 512){ Bp = W0; ldb = 512;  bc0 = col0; }
        else           { Bp = W1; ldb = 1024; bc0 = col0 - 512; }
    } else {
        A = g_vals; Bp = W0; ldb = 512; bc0 = col0;
    }

    float acc[4][4][4];
    #pragma unroll
    for (int i = 0; i < 4; i++)
        #pragma unroll
        for (int j = 0; j < 4; j++)
            #pragma unroll
            for (int e = 0; e < 4; e++) acc[i][j][e] = 0.f;

    // smem addresses for ldmatrix (per lane)
    uint32_t aAh = smem_u32(Ah), aAl = smem_u32(Al);
    uint32_t aBh = smem_u32(Bh), aBl = smem_u32(Bl);

    int a_row = tid >> 1, a_cg = (tid & 1)*16;   // A ld/st mapping
    int b_row = tid >> 3, b_cg = (tid & 7)*16;   // B ld/st mapping

    for (int kc = 0; kc < 512; kc += 32){
        // ---- global -> smem (split bf16 hi/lo) ----
        {
            const float* ap = A + (long)(row0 + a_row)*512 + kc + a_cg;
            #pragma unroll
            for (int j = 0; j < 4; j++){
                float4 x = *(const float4*)(ap + j*4);
                uint16_t h0,l0,h1,l1,h2,l2,h3,l3;
                bsplit(x.x,h0,l0); bsplit(x.y,h1,l1); bsplit(x.z,h2,l2); bsplit(x.w,h3,l3);
                int o = a_row*PA + a_cg + j*4;
                *(uint32_t*)&Ah[o]   = (uint32_t)h0 | ((uint32_t)h1<<16);
                *(uint32_t*)&Ah[o+2] = (uint32_t)h2 | ((uint32_t)h3<<16);
                *(uint32_t*)&Al[o]   = (uint32_t)l0 | ((uint32_t)l1<<16);
                *(uint32_t*)&Al[o+2] = (uint32_t)l2 | ((uint32_t)l3<<16);
            }
        }
        {
            const float* bp = Bp + (long)(kc + b_row)*ldb + bc0 + b_cg;
            #pragma unroll
            for (int j = 0; j < 4; j++){
                float4 x = *(const float4*)(bp + j*4);
                uint16_t h0,l0,h1,l1,h2,l2,h3,l3;
                bsplit(x.x,h0,l0); bsplit(x.y,h1,l1); bsplit(x.z,h2,l2); bsplit(x.w,h3,l3);
                int o = b_row*PB + b_cg + j*4;
                *(uint32_t*)&Bh[o]   = (uint32_t)h0 | ((uint32_t)h1<<16);
                *(uint32_t*)&Bh[o+2] = (uint32_t)h2 | ((uint32_t)h3<<16);
                *(uint32_t*)&Bl[o]   = (uint32_t)l0 | ((uint32_t)l1<<16);
                *(uint32_t*)&Bl[o+2] = (uint32_t)l2 | ((uint32_t)l3<<16);
            }
        }
        __syncthreads();

        // ---- 2 x k16 steps ----
        #pragma unroll
        for (int ks = 0; ks < 2; ks++){
            int k0 = ks*16;
            int arow = wm*64 + (l & 15);
            int acol = k0 + (l >> 4)*8;
            int brow = k0 + (l & 15);
            int bcol = wn*32 + (l >> 4)*8;

            uint32_t ah[4][4], bh2[2][4];
            #pragma unroll
            for (int mt = 0; mt < 4; mt++)
                ldm4(ah[mt], aAh + ((arow + mt*16)*PA + acol)*2);
            #pragma unroll
            for (int bt = 0; bt < 2; bt++)
                ldm4t(bh2[bt], aBh + (brow*PB + bcol + bt*16)*2);
            // hi*hi
            #pragma unroll
            for (int mt = 0; mt < 4; mt++)
                #pragma unroll
                for (int nt = 0; nt < 4; nt++)
                    mma16816(acc[mt][nt], ah[mt], bh2[nt>>1][(nt&1)*2? 2:0 + 0*(nt&1)] , bh2[nt>>1][(nt&1)?3:1]);
            // note: bh2[bt] = {b0(n0), b1(n0), b0(n0+8), b1(n0+8)}
            // lo(A)*hi(B)
            {
                uint32_t al4[4][4];
                #pragma unroll
                for (int mt = 0; mt < 4; mt++)
                    ldm4(al4[mt], aAl + ((arow + mt*16)*PA + acol)*2);
                #pragma unroll
                for (int mt = 0; mt < 4; mt++)
                    #pragma unroll
                    for (int nt = 0; nt < 4; nt++)
                        mma16816(acc[mt][nt], al4[mt], bh2[nt>>1][(nt&1)?2:0], bh2[nt>>1][(nt&1)?3:1]);
            }
            // hi(A)*lo(B)
            {
                uint32_t bl2[2][4];
                #pragma unroll
                for (int bt = 0; bt < 2; bt++)
                    ldm4t(bl2[bt], aBl + (brow*PB + bcol + bt*16)*2);
                #pragma unroll
                for (int mt = 0; mt < 4; mt++)
                    #pragma unroll
                    for (int nt = 0; nt < 4; nt++)
                        mma16816(acc[mt][nt], ah[mt], bl2[nt>>1][(nt&1)?2:0], bl2[nt>>1][(nt&1)?3:1]);
            }
        }
        __syncthreads();
    }

    // ---- epilogue ----
    int g = l >> 2, tq = l & 3;
    #pragma unroll
    for (int mt = 0; mt < 4; mt++){
        #pragma unroll
        for (int nt = 0; nt < 4; nt++){
            int col = col0 + wn*32 + nt*8 + 2*tq;
            #pragma unroll
            for (int half = 0; half < 2; half++){
                int r = row0 + wm*64 + mt*16 + g + half*8;
                float2 v = make_float2(acc[mt][nt][half*2], acc[mt][nt][half*2+1]);
                if (mode == 0){
                    int mtx = col >> 9, cc = col & 511;
                    int hh = cc >> 6, j0 = cc & 63;
                    float* dst = (mtx == 0) ? g_q : (mtx == 1 ? g_k : g_v);
                    int b_ = r >> 13, tok = r & 8191;
                    *(float2*)(dst + ((long)(b_*H + hh)*T + tok)*D + j0) = v;
                } else {
                    int b_ = r >> 13, jr = r & 8191;
                    if (jr <= T - C)
                        *(float2*)(outp + ((long)b_*T + jr + (C-1))*DIM + col) = v;
                }
            }
        }
    }
}

// ------------------- tiny 64x64x64 GEMM helper (256 thr, 4x4 micro-tile) -------------------
template<class LA, class LB, class ST>
__device__ __forceinline__ void mm64(int tid, LA la, LB lb, ST st)
{
    int tx = tid & 15, ty = tid >> 4;
    int r0 = ty*4, c0 = tx*4;
    float acc[4][4] = {};
    #pragma unroll 4
    for (int k = 0; k < 64; k++){
        float a[4], bb[4];
        #pragma unroll
        for (int u = 0; u < 4; u++) a[u] = la(r0+u, k);
        #pragma unroll
        for (int v = 0; v < 4; v++) bb[v] = lb(k, c0+v);
        #pragma unroll
        for (int u = 0; u < 4; u++)
            #pragma unroll
            for (int v = 0; v < 4; v++) acc[u][v] += a[u]*bb[v];
    }
    #pragma unroll
    for (int u = 0; u < 4; u++)
        #pragma unroll
        for (int v = 0; v < 4; v++) st(r0+u, c0+v, acc[u][v]);
}

// ------------------- K4: per-chunk MLP grads (surprises) -------------------
__global__ void k4_grads(const float* __restrict__ w1, const float* __restrict__ w2)
{
    extern __shared__ float sm[];
    float* sK  = sm;
    float* sV  = sK  + 4160;
    float* sW  = sV  + 4160;
    float* sX  = sW  + 4160;
    float* sH  = sX  + 4160;
    float* sDY = sH  + 4160;
    float* slr = sDY + 4160;
    int nc = blockIdx.x, bh = blockIdx.y;
    int tid = threadIdx.x;
    long base = ((long)bh*T + nc*C)*D;
    for (int idx = tid; idx < 4096; idx += 256){
        int r = idx >> 6, c = idx & 63;
        sK[r*65+c] = g_k[base + idx];
        sV[r*65+c] = g_v[base + idx];
        sW[r*65+c] = w1[idx];
    }
    if (tid < 64) slr[tid] = g_lr[(long)bh*T + nc*C + tid];
    __syncthreads();
    mm64(tid, [&](int i,int k){ return sK[i*65+k]; },
              [&](int k,int j){ return sW[k*65+j]; },
              [&](int i,int j,float v){ sX[i*65+j] = v; });
    __syncthreads();
    for (int idx = tid; idx < 4096; idx += 256){
        int r = idx >> 6, c = idx & 63;
        float x = sX[r*65+c];
        sH[r*65+c] = x * sigm(x);
        sW[r*65+c] = w2[idx];
    }
    __syncthreads();
    mm64(tid, [&](int i,int k){ return sH[i*65+k]; },
              [&](int k,int j){ return sW[k*65+j]; },
              [&](int i,int j,float y){ sDY[i*65+j] = slr[i]*(y - sV[i*65+j]); });
    __syncthreads();
    long gbase = ((long)bh*NCH + nc)*4096;
    mm64(tid, [&](int p,int i){ return sH[i*65+p]; },
              [&](int i,int j){ return sDY[i*65+j]; },
              [&](int p,int j,float v){ g_u2[gbase + p*64 + j] = -v; });
    mm64(tid, [&](int i,int j){ return sDY[i*65+j]; },
              [&](int j,int p){ return sW[p*65+j]; },
              [&](int i,int p,float v){ sV[i*65+p] = v; });
    __syncthreads();
    for (int idx = tid; idx < 4096; idx += 256){
        int r = idx >> 6, c = idx & 63;
        float x = sX[r*65+c];
        float sg = sigm(x);
        sX[r*65+c] = sV[r*65+c] * sg * (1.f + x*(1.f - sg));
    }
    __syncthreads();
    mm64(tid, [&](int p,int i){ return sK[i*65+p]; },
              [&](int i,int j){ return sX[i*65+j]; },
              [&](int p,int j,float v){ g_u1[gbase + p*64 + j] = -v; });
}

// ------------------- K5: momentum + decay scans -------------------
__global__ void k5_scan()
{
    int e  = blockIdx.x*blockDim.x + threadIdx.x;
    int bh = blockIdx.y;
    float* g = blockIdx.z ? g_u2 : g_u1;
    const float* mg = g_mg  + bh*NCH;
    const float* dc = g_dec + bh*NCH;
    float m = 0.f, u = 0.f;
    long base = (long)bh*NCH*4096 + e;
    for (int t = 0; t < NCH; t++){
        float s = g[base + (long)t*4096];
        m = mg[t]*m + s;
        u = (1.f - dc[t])*u + m;
        g[base + (long)t*4096] = u;
    }
}

// ------------------- K6: retrieve -------------------
__global__ void k6_retrieve(const float* __restrict__ w1, const float* __restrict__ w2,
                            const float* __restrict__ gamma)
{
    extern __shared__ float sm[];
    float* sQ = sm;
    float* sW = sQ + 4160;
    float* sX = sW + 4160;
    int nc = blockIdx.x, bh = blockIdx.y;
    int tid = threadIdx.x;
    int h = bh % H, b = bh / H;
    long ubase = ((long)bh*NCH + nc)*4096;
    for (int idx = tid; idx < 4096; idx += 256){
        int r = idx >> 6, c = idx & 63;
        int tok = nc*C + r + (C-1);
        sQ[r*65+c] = (tok < T) ? g_q[((long)bh*T + tok)*D + c] : 0.f;
        sW[r*65+c] = w1[idx] + g_u1[ubase + idx];
    }
    __syncthreads();
    mm64(tid, [&](int i,int k){ return sQ[i*65+k]; },
              [&](int k,int j){ return sW[k*65+j]; },
              [&](int i,int j,float v){ sX[i*65+j] = v * sigm(v); });
    __syncthreads();
    for (int idx = tid; idx < 4096; idx += 256){
        int r = idx >> 6, c = idx & 63;
        sW[r*65+c] = w2[idx] + g_u2[ubase + idx];
    }
    __syncthreads();
    mm64(tid, [&](int i,int k){ return sX[i*65+k]; },
              [&](int k,int j){ return sW[k*65+j]; },
              [&](int i,int j,float v){ sQ[i*65+j] = v; });
    __syncthreads();
    int row = tid >> 2, sub = tid & 3;
    float ss = 0.f;
    for (int j = sub; j < 64; j += 4){ float v = sQ[row*65+j]; ss += v*v; }
    ss += __shfl_xor_sync(0xffffffffu, ss, 1);
    ss += __shfl_xor_sync(0xffffffffu, ss, 2);
    float sc = rsqrtf(ss*(1.f/64) + EPSR);
    int tokq = nc*C + row + (C-1);
    float gate = (tokq < T) ? g_gate[(long)bh*T + tokq] : 0.f;
    float* dst = g_vals + ((long)b*T + nc*C + row)*DIM + h*D;
    for (int j = sub; j < 64; j += 4)
        dst[j] = sQ[row*65+j]*sc*(gamma[h*D + j] + 1.f)*gate;
}

// ------------------- K0: zero the first c-1 output tokens -------------------
__global__ void k0_zero(float* __restrict__ out)
{
    int i = blockIdx.x*blockDim.x + threadIdx.x;
    const int per = (C-1)*DIM;
    if (i < BB*per){
        int b = i / per, rem = i % per;
        out[(long)b*T*DIM + rem] = 0.f;
    }
}

// ------------------- launch -------------------
extern "C" void kernel_launch(void* const* d_in, const int* in_sizes, int n_in,
                              void* d_out, int out_size)
{
    const float* seq   = (const float*)d_in[0];
    const float* w1    = (const float*)d_in[1];
    const float* w2    = (const float*)d_in[2];
    const float* Wq    = (const float*)d_in[3];
    const float* Wkv   = (const float*)d_in[4];
    const float* Wstep = (const float*)d_in[5];
    const float* Wmom  = (const float*)d_in[6];
    const float* Wdecay= (const float*)d_in[7];
    const float* Wgate = (const float*)d_in[8];
    const float* Wcomb = (const float*)d_in[9];
    const float* gamma = (const float*)d_in[10];
    float* out = (float*)d_out;

    cudaFuncSetAttribute(k4_grads,    cudaFuncAttributeMaxDynamicSharedMemorySize, 101376);
    cudaFuncSetAttribute(k6_retrieve, cudaFuncAttributeMaxDynamicSharedMemorySize, 50176);

    k1_rmsnorm<<<BB*T, 256>>>(seq, Wstep, Wgate);
    k2_chunkgates<<<dim3(NCH, BB), 256>>>(Wmom, Wdecay);
    kmma<<<dim3(12, 256), 256>>>(Wq, Wkv, nullptr, 0);
    k4_grads<<<dim3(NCH, BH), 256, (6*4160 + 64)*sizeof(float)>>>(w1, w2);
    k5_scan<<<dim3(16, BH, 2), 256>>>();
    k6_retrieve<<<dim3(NCH, BH), 256, 3*4160*sizeof(float)>>>(w1, w2, gamma);
    kmma<<<dim3(4, 256), 256>>>(Wcomb, nullptr, out, 1);
    k0_zero<<<504, 256>>>(out);
}

// round 5
// speedup vs baseline: 1.5105x; 1.0073x over previous
#include <cuda_runtime.h>
#include <cuda_bf16.h>
#include <stdint.h>
#include <math.h>

#define BB   4
#define T    8192
#define DIM  512
#define H    8
#define D    64
#define C    64
#define NCH  128           // T/C
#define BH   32            // BB*H
#define EPSR 1.1920929e-07f
#define MAXLR 0.01f
#define PH   72            // bf16 smem pitch (halves): 144B rows, 16B aligned

// ------------------- scratch (device globals; no allocs allowed) -------------------
__device__ float g_s   [BB*T*DIM];
__device__ float g_q   [BH*T*D];
__device__ float g_k   [BH*T*D];
__device__ float g_v   [BH*T*D];
__device__ float g_lr  [BH*T];         // sigmoid(s@Wstep)*MAXLR*(2/D) (prefolded)
__device__ float g_gate[BH*T];
__device__ float g_mg  [BH*NCH];
__device__ float g_dec [BH*NCH];
__device__ float g_u1  [(long)BH*NCH*D*D];
__device__ float g_u2  [(long)BH*NCH*D*D];
__device__ float g_vals[BB*T*DIM];

__device__ __forceinline__ float sigm(float x){ return 1.f/(1.f+__expf(-x)); }

__device__ __forceinline__ uint32_t smem_u32(const void* p){
    uint32_t a;
    asm("{ .reg .u64 t; cvta.to.shared.u64 t, %1; cvt.u32.u64 %0, t; }" : "=r"(a) : "l"(p));
    return a;
}
__device__ __forceinline__ void ldm4(uint32_t* r, uint32_t addr){
    asm volatile("ldmatrix.sync.aligned.m8n8.x4.shared.b16 {%0,%1,%2,%3}, [%4];"
                 : "=r"(r[0]),"=r"(r[1]),"=r"(r[2]),"=r"(r[3]) : "r"(addr));
}
__device__ __forceinline__ void ldm4t(uint32_t* r, uint32_t addr){
    asm volatile("ldmatrix.sync.aligned.m8n8.x4.trans.shared.b16 {%0,%1,%2,%3}, [%4];"
                 : "=r"(r[0]),"=r"(r[1]),"=r"(r[2]),"=r"(r[3]) : "r"(addr));
}
__device__ __forceinline__ void mma16816(float* c, const uint32_t* a, uint32_t b0, uint32_t b1){
    asm volatile("mma.sync.aligned.m16n8k16.row.col.f32.bf16.bf16.f32 "
                 "{%0,%1,%2,%3}, {%4,%5,%6,%7}, {%8,%9}, {%0,%1,%2,%3};"
                 : "+f"(c[0]),"+f"(c[1]),"+f"(c[2]),"+f"(c[3])
                 : "r"(a[0]),"r"(a[1]),"r"(a[2]),"r"(a[3]), "r"(b0),"r"(b1));
}
__device__ __forceinline__ void bsplit(float v, uint16_t& hi, uint16_t& lo){
    __nv_bfloat16 h = __float2bfloat16(v);
    __nv_bfloat16 l = __float2bfloat16(v - __bfloat162float(h));
    hi = __bfloat16_as_ushort(h);
    lo = __bfloat16_as_ushort(l);
}

// ===== warp-tiled 64x64x64 bf16-split GEMM: 8 warps, each m16 x n32 =====
// AT: A operand is sourceT (source stored k-rows x m-cols). BT: B = sourceT (source stored n-rows x k-cols).
template<int AT, int BT, class CB>
__device__ __forceinline__ void tmm64(int wid, int l,
    const uint16_t* Ah_, const uint16_t* Al_,
    const uint16_t* Bh_, const uint16_t* Bl_, CB cb)
{
    int wm = wid & 3, wn = wid >> 2;
    float acc[4][4];
    #pragma unroll
    for (int i = 0; i < 4; i++)
        #pragma unroll
        for (int e = 0; e < 4; e++) acc[i][e] = 0.f;
    uint32_t aAh = smem_u32(Ah_), aAl = smem_u32(Al_);
    uint32_t aBh = smem_u32(Bh_), aBl = smem_u32(Bl_);
    #pragma unroll
    for (int ks = 0; ks < 4; ks++){
        int k0 = ks*16;
        uint32_t ah[4], al[4];
        if (!AT){
            uint32_t ad = (uint32_t)((wm*16 + (l&15))*PH + k0 + ((l>>4)<<3))*2u;
            ldm4(ah, aAh + ad); ldm4(al, aAl + ad);
        } else {
            uint32_t ad = (uint32_t)((k0 + (l&15))*PH + wm*16 + ((l>>4)<<3))*2u;
            uint32_t t[4];
            ldm4t(t, aAh + ad); ah[0]=t[0]; ah[1]=t[2]; ah[2]=t[1]; ah[3]=t[3];
            ldm4t(t, aAl + ad); al[0]=t[0]; al[1]=t[2]; al[2]=t[1]; al[3]=t[3];
        }
        uint32_t bh[2][4], bl[2][4];   // convention: {nlo/k0-7, nlo/k8-15, nhi/k0-7, nhi/k8-15}
        #pragma unroll
        for (int hh = 0; hh < 2; hh++){
            int n0 = wn*32 + hh*16;
            if (!BT){
                uint32_t bd = (uint32_t)((k0 + (l&15))*PH + n0 + ((l>>4)<<3))*2u;
                ldm4t(bh[hh], aBh + bd); ldm4t(bl[hh], aBl + bd);
            } else {
                uint32_t bd = (uint32_t)((n0 + (l&15))*PH + k0 + ((l>>4)<<3))*2u;
                uint32_t t[4];
                ldm4(t, aBh + bd); bh[hh][0]=t[0]; bh[hh][1]=t[2]; bh[hh][2]=t[1]; bh[hh][3]=t[3];
                ldm4(t, aBl + bd); bl[hh][0]=t[0]; bl[hh][1]=t[2]; bl[hh][2]=t[1]; bl[hh][3]=t[3];
            }
        }
        #pragma unroll
        for (int nt = 0; nt < 4; nt++){
            int hh = nt>>1, o = (nt&1)*2;
            mma16816(acc[nt], ah, bh[hh][o], bh[hh][o+1]);
            mma16816(acc[nt], al, bh[hh][o], bh[hh][o+1]);
            mma16816(acc[nt], ah, bl[hh][o], bl[hh][o+1]);
        }
    }
    #pragma unroll
    for (int nt = 0; nt < 4; nt++)
        #pragma unroll
        for (int e = 0; e < 4; e++){
            int m = wm*16 + (l>>2) + ((e>>1)<<3);
            int n = wn*32 + nt*8 + ((l&3)<<1) + (e&1);
            cb(m, n, acc[nt][e]);
        }
}

// ------------------- K1: rmsnorm + per-token lr & gate -------------------
__global__ void k1_rmsnorm(const float* __restrict__ seq,
                           const float* __restrict__ Wstep,
                           const float* __restrict__ Wgate)
{
    int tok = blockIdx.x;
    int tid = threadIdx.x;
    __shared__ float s[DIM];
    __shared__ float red[256];
    float x0 = seq[(long)tok*DIM + tid*2];
    float x1 = seq[(long)tok*DIM + tid*2 + 1];
    red[tid] = x0*x0 + x1*x1;
    __syncthreads();
    for (int o = 128; o > 0; o >>= 1){
        if (tid < o) red[tid] += red[tid+o];
        __syncthreads();
    }
    float sc = rsqrtf(red[0]*(1.f/DIM) + EPSR);
    float s0 = x0*sc, s1 = x1*sc;
    s[tid*2] = s0; s[tid*2+1] = s1;
    g_s[(long)tok*DIM + tid*2]     = s0;
    g_s[(long)tok*DIM + tid*2 + 1] = s1;
    __syncthreads();
    int w = tid >> 5, lane = tid & 31;
    float ds = 0.f, dg = 0.f;
    for (int i = lane; i < DIM; i += 32){
        float sv = s[i];
        ds += sv * Wstep[i*H + w];
        dg += sv * Wgate[i*H + w];
    }
    for (int o = 16; o; o >>= 1){
        ds += __shfl_down_sync(0xffffffffu, ds, o);
        dg += __shfl_down_sync(0xffffffffu, dg, o);
    }
    if (lane == 0){
        int b = tok / T, t = tok % T;
        int bh = b*H + w;
        g_lr  [(long)bh*T + t] = sigm(ds) * MAXLR * (2.0f/D);
        g_gate[(long)bh*T + t] = sigm(dg);
    }
}

// ------------------- K2: per-chunk momentum / decay gates -------------------
__global__ void k2_chunkgates(const float* __restrict__ Wmom,
                              const float* __restrict__ Wdecay)
{
    int nc = blockIdx.x, b = blockIdx.y;
    int tid = threadIdx.x;
    __shared__ float m[DIM];
    const float* base = g_s + ((long)b*T + nc*C)*DIM;
    float a0 = 0.f, a1 = 0.f;
    for (int r = 0; r < C; r++){
        a0 += base[(long)r*DIM + tid*2];
        a1 += base[(long)r*DIM + tid*2 + 1];
    }
    m[tid*2] = a0*(1.f/C); m[tid*2+1] = a1*(1.f/C);
    __syncthreads();
    int w = tid >> 5, lane = tid & 31;
    float dm = 0.f, dd = 0.f;
    for (int i = lane; i < DIM; i += 32){
        float v = m[i];
        dm += v * Wmom[i*H + w];
        dd += v * Wdecay[i*H + w];
    }
    for (int o = 16; o; o >>= 1){
        dm += __shfl_down_sync(0xffffffffu, dm, o);
        dd += __shfl_down_sync(0xffffffffu, dd, o);
    }
    if (lane == 0){
        int bh = b*H + w;
        g_mg [bh*NCH + nc] = sigm(dm);
        g_dec[bh*NCH + nc] = sigm(dd);
    }
}

// ===================== big GEMMs (mma.sync bf16 2-split) =====================
#define PA 40
#define PB 136
__global__ void __launch_bounds__(256, 2)
kmma(const float* __restrict__ W0, const float* __restrict__ W1,
     float* __restrict__ outp, int mode)
{
    __shared__ __align__(16) uint16_t Ah[128*PA], Al[128*PA];
    __shared__ __align__(16) uint16_t Bh[32*PB],  Bl[32*PB];

    int tid = threadIdx.x, wid = tid >> 5, l = tid & 31;
    int wm = wid & 1, wn = wid >> 1;
    int row0 = blockIdx.y * 128;
    int col0 = blockIdx.x * 128;

    const float* A; const float* Bp; int ldb, bc0;
    if (mode == 0){
        A = g_s;
        if (col0 < 512){ Bp = W0; ldb = 512;  bc0 = col0; }
        else           { Bp = W1; ldb = 1024; bc0 = col0 - 512; }
    } else {
        A = g_vals; Bp = W0; ldb = 512; bc0 = col0;
    }

    float acc[4][4][4];
    #pragma unroll
    for (int i = 0; i < 4; i++)
        #pragma unroll
        for (int j = 0; j < 4; j++)
            #pragma unroll
            for (int e = 0; e < 4; e++) acc[i][j][e] = 0.f;

    uint32_t aAh = smem_u32(Ah), aAl = smem_u32(Al);
    uint32_t aBh = smem_u32(Bh), aBl = smem_u32(Bl);

    int a_row = tid >> 1, a_cg = (tid & 1)*16;
    int b_row = tid >> 3, b_cg = (tid & 7)*16;

    for (int kc = 0; kc < 512; kc += 32){
        {
            const float* ap = A + (long)(row0 + a_row)*512 + kc + a_cg;
            #pragma unroll
            for (int j = 0; j < 4; j++){
                float4 x = *(const float4*)(ap + j*4);
                uint16_t h0,l0,h1,l1,h2,l2,h3,l3;
                bsplit(x.x,h0,l0); bsplit(x.y,h1,l1); bsplit(x.z,h2,l2); bsplit(x.w,h3,l3);
                int o = a_row*PA + a_cg + j*4;
                *(uint32_t*)&Ah[o]   = (uint32_t)h0 | ((uint32_t)h1<<16);
                *(uint32_t*)&Ah[o+2] = (uint32_t)h2 | ((uint32_t)h3<<16);
                *(uint32_t*)&Al[o]   = (uint32_t)l0 | ((uint32_t)l1<<16);
                *(uint32_t*)&Al[o+2] = (uint32_t)l2 | ((uint32_t)l3<<16);
            }
        }
        {
            const float* bp = Bp + (long)(kc + b_row)*ldb + bc0 + b_cg;
            #pragma unroll
            for (int j = 0; j < 4; j++){
                float4 x = *(const float4*)(bp + j*4);
                uint16_t h0,l0,h1,l1,h2,l2,h3,l3;
                bsplit(x.x,h0,l0); bsplit(x.y,h1,l1); bsplit(x.z,h2,l2); bsplit(x.w,h3,l3);
                int o = b_row*PB + b_cg + j*4;
                *(uint32_t*)&Bh[o]   = (uint32_t)h0 | ((uint32_t)h1<<16);
                *(uint32_t*)&Bh[o+2] = (uint32_t)h2 | ((uint32_t)h3<<16);
                *(uint32_t*)&Bl[o]   = (uint32_t)l0 | ((uint32_t)l1<<16);
                *(uint32_t*)&Bl[o+2] = (uint32_t)l2 | ((uint32_t)l3<<16);
            }
        }
        __syncthreads();

        #pragma unroll
        for (int ks = 0; ks < 2; ks++){
            int k0 = ks*16;
            int arow = wm*64 + (l & 15);
            int acol = k0 + (l >> 4)*8;
            int brow = k0 + (l & 15);
            int bcol = wn*32 + (l >> 4)*8;

            uint32_t ah[4][4], bh2[2][4];
            #pragma unroll
            for (int mt = 0; mt < 4; mt++)
                ldm4(ah[mt], aAh + ((arow + mt*16)*PA + acol)*2);
            #pragma unroll
            for (int bt = 0; bt < 2; bt++)
                ldm4t(bh2[bt], aBh + (brow*PB + bcol + bt*16)*2);
            #pragma unroll
            for (int mt = 0; mt < 4; mt++)
                #pragma unroll
                for (int nt = 0; nt < 4; nt++)
                    mma16816(acc[mt][nt], ah[mt], bh2[nt>>1][(nt&1)?2:0], bh2[nt>>1][(nt&1)?3:1]);
            {
                uint32_t al4[4][4];
                #pragma unroll
                for (int mt = 0; mt < 4; mt++)
                    ldm4(al4[mt], aAl + ((arow + mt*16)*PA + acol)*2);
                #pragma unroll
                for (int mt = 0; mt < 4; mt++)
                    #pragma unroll
                    for (int nt = 0; nt < 4; nt++)
                        mma16816(acc[mt][nt], al4[mt], bh2[nt>>1][(nt&1)?2:0], bh2[nt>>1][(nt&1)?3:1]);
            }
            {
                uint32_t bl2[2][4];
                #pragma unroll
                for (int bt = 0; bt < 2; bt++)
                    ldm4t(bl2[bt], aBl + (brow*PB + bcol + bt*16)*2);
                #pragma unroll
                for (int mt = 0; mt < 4; mt++)
                    #pragma unroll
                    for (int nt = 0; nt < 4; nt++)
                        mma16816(acc[mt][nt], ah[mt], bl2[nt>>1][(nt&1)?2:0], bl2[nt>>1][(nt&1)?3:1]);
            }
        }
        __syncthreads();
    }

    int g = l >> 2, tq = l & 3;
    #pragma unroll
    for (int mt = 0; mt < 4; mt++){
        #pragma unroll
        for (int nt = 0; nt < 4; nt++){
            int col = col0 + wn*32 + nt*8 + 2*tq;
            #pragma unroll
            for (int half = 0; half < 2; half++){
                int r = row0 + wm*64 + mt*16 + g + half*8;
                float2 v = make_float2(acc[mt][nt][half*2], acc[mt][nt][half*2+1]);
                if (mode == 0){
                    int mtx = col >> 9, cc = col & 511;
                    int hh = cc >> 6, j0 = cc & 63;
                    float* dst = (mtx == 0) ? g_q : (mtx == 1 ? g_k : g_v);
                    int b_ = r >> 13, tok = r & 8191;
                    *(float2*)(dst + ((long)(b_*H + hh)*T + tok)*D + j0) = v;
                } else {
                    int b_ = r >> 13, jr = r & 8191;
                    if (jr <= T - C)
                        *(float2*)(outp + ((long)b_*T + jr + (C-1))*DIM + col) = v;
                }
            }
        }
    }
}

// ------------------- K4: per-chunk MLP grads via tensor cores -------------------
__global__ void __launch_bounds__(256)
k4_grads(const float* __restrict__ w1, const float* __restrict__ w2)
{
    extern __shared__ __align__(16) char smraw[];
    uint16_t* Kh = (uint16_t*)smraw;
    uint16_t* Kl = Kh + 64*PH;
    uint16_t* Wh = Kl + 64*PH;
    uint16_t* Wl = Wh + 64*PH;
    uint16_t* Hh = Wl + 64*PH;
    uint16_t* Hl = Hh + 64*PH;
    uint16_t* Yh = Hl + 64*PH;   // dY
    uint16_t* Yl = Yh + 64*PH;
    uint16_t* Dh = Yl + 64*PH;   // dX
    uint16_t* Dl = Dh + 64*PH;
    float* Vf  = (float*)(Dl + 64*PH);   // 64*65
    float* Xf  = Vf + 64*65;
    float* slr = Xf + 64*65;             // 64

    int nc = blockIdx.x, bh = blockIdx.y;
    int tid = threadIdx.x, wid = tid >> 5, l = tid & 31;
    long base = ((long)bh*T + nc*C)*D;
    for (int idx = tid; idx < 4096; idx += 256){
        int r = idx >> 6, c = idx & 63;
        uint16_t h_, l_;
        bsplit(g_k[base + idx], h_, l_); Kh[r*PH+c] = h_; Kl[r*PH+c] = l_;
        bsplit(w1[idx],        h_, l_); Wh[r*PH+c] = h_; Wl[r*PH+c] = l_;
        Vf[r*65+c] = g_v[base + idx];
    }
    if (tid < 64) slr[tid] = g_lr[(long)bh*T + nc*C + tid];
    __syncthreads();

    // X = K @ W1 ; H = silu(X)
    tmm64<0,0>(wid, l, Kh, Kl, Wh, Wl, [&](int m, int n, float v){
        Xf[m*65+n] = v;
        float hv = v * sigm(v);
        uint16_t h_, l_; bsplit(hv, h_, l_);
        Hh[m*PH+n] = h_; Hl[m*PH+n] = l_;
    });
    __syncthreads();
    for (int idx = tid; idx < 4096; idx += 256){
        int r = idx >> 6, c = idx & 63;
        uint16_t h_, l_; bsplit(w2[idx], h_, l_);
        Wh[r*PH+c] = h_; Wl[r*PH+c] = l_;
    }
    __syncthreads();
    // Y = H @ W2 ; dY = lr*(Y - V)
    tmm64<0,0>(wid, l, Hh, Hl, Wh, Wl, [&](int m, int n, float y){
        float dy = slr[m]*(y - Vf[m*65+n]);
        uint16_t h_, l_; bsplit(dy, h_, l_);
        Yh[m*PH+n] = h_; Yl[m*PH+n] = l_;
    });
    __syncthreads();
    long gbase = ((long)bh*NCH + nc)*4096;
    // G2 = H^T @ dY
    tmm64<1,0>(wid, l, Hh, Hl, Yh, Yl, [&](int m, int n, float v){
        g_u2[gbase + m*64 + n] = -v;
    });
    // dH = dY @ W2^T ; dX = dH * silu'(X)
    tmm64<0,1>(wid, l, Yh, Yl, Wh, Wl, [&](int m, int n, float v){
        float x = Xf[m*65+n];
        float sg = sigm(x);
        float dx = v * sg * (1.f + x*(1.f - sg));
        uint16_t h_, l_; bsplit(dx, h_, l_);
        Dh[m*PH+n] = h_; Dl[m*PH+n] = l_;
    });
    __syncthreads();
    // G1 = K^T @ dX
    tmm64<1,0>(wid, l, Kh, Kl, Dh, Dl, [&](int m, int n, float v){
        g_u1[gbase + m*64 + n] = -v;
    });
}

// ------------------- K5: momentum + decay scans -------------------
__global__ void k5_scan()
{
    int e  = blockIdx.x*blockDim.x + threadIdx.x;
    int bh = blockIdx.y;
    float* g = blockIdx.z ? g_u2 : g_u1;
    const float* mg = g_mg  + bh*NCH;
    const float* dc = g_dec + bh*NCH;
    float m = 0.f, u = 0.f;
    long base = (long)bh*NCH*4096 + e;
    for (int t = 0; t < NCH; t++){
        float s = g[base + (long)t*4096];
        m = mg[t]*m + s;
        u = (1.f - dc[t])*u + m;
        g[base + (long)t*4096] = u;
    }
}

// ------------------- K6: retrieve via tensor cores -------------------
__global__ void __launch_bounds__(256)
k6_retrieve(const float* __restrict__ w1, const float* __restrict__ w2,
            const float* __restrict__ gamma)
{
    extern __shared__ __align__(16) char smraw[];
    uint16_t* Qh = (uint16_t*)smraw;
    uint16_t* Ql = Qh + 64*PH;
    uint16_t* Wh = Ql + 64*PH;
    uint16_t* Wl = Wh + 64*PH;
    uint16_t* Xh = Wl + 64*PH;
    uint16_t* Xl = Xh + 64*PH;
    float* Of = (float*)(Xl + 64*PH);    // 64*65

    int nc = blockIdx.x, bh = blockIdx.y;
    int tid = threadIdx.x, wid = tid >> 5, l = tid & 31;
    int h = bh % H, b = bh / H;
    long ubase = ((long)bh*NCH + nc)*4096;
    for (int idx = tid; idx < 4096; idx += 256){
        int r = idx >> 6, c = idx & 63;
        int tok = nc*C + r + (C-1);
        float qv = (tok < T) ? g_q[((long)bh*T + tok)*D + c] : 0.f;
        uint16_t h_, l_;
        bsplit(qv, h_, l_); Qh[r*PH+c] = h_; Ql[r*PH+c] = l_;
        bsplit(w1[idx] + g_u1[ubase + idx], h_, l_); Wh[r*PH+c] = h_; Wl[r*PH+c] = l_;
    }
    __syncthreads();
    // X = silu(Q @ (W1+U1))
    tmm64<0,0>(wid, l, Qh, Ql, Wh, Wl, [&](int m, int n, float v){
        float s = v * sigm(v);
        uint16_t h_, l_; bsplit(s, h_, l_);
        Xh[m*PH+n] = h_; Xl[m*PH+n] = l_;
    });
    __syncthreads();
    for (int idx = tid; idx < 4096; idx += 256){
        int r = idx >> 6, c = idx & 63;
        uint16_t h_, l_; bsplit(w2[idx] + g_u2[ubase + idx], h_, l_);
        Wh[r*PH+c] = h_; Wl[r*PH+c] = l_;
    }
    __syncthreads();
    // O = X @ (W2+U2)
    tmm64<0,0>(wid, l, Xh, Xl, Wh, Wl, [&](int m, int n, float v){
        Of[m*65+n] = v;
    });
    __syncthreads();
    // per-row RMSNorm(64) * (gamma+1) * gate, merged-head layout
    int row = tid >> 2, sub = tid & 3;
    float ss = 0.f;
    for (int j = sub; j < 64; j += 4){ float v = Of[row*65+j]; ss += v*v; }
    ss += __shfl_xor_sync(0xffffffffu, ss, 1);
    ss += __shfl_xor_sync(0xffffffffu, ss, 2);
    float sc = rsqrtf(ss*(1.f/64) + EPSR);
    int tokq = nc*C + row + (C-1);
    float gate = (tokq < T) ? g_gate[(long)bh*T + tokq] : 0.f;
    float* dst = g_vals + ((long)b*T + nc*C + row)*DIM + h*D;
    for (int j = sub; j < 64; j += 4)
        dst[j] = Of[row*65+j]*sc*(gamma[h*D + j] + 1.f)*gate;
}

// ------------------- K0: zero the first c-1 output tokens -------------------
__global__ void k0_zero(float* __restrict__ out)
{
    int i = blockIdx.x*blockDim.x + threadIdx.x;
    const int per = (C-1)*DIM;
    if (i < BB*per){
        int b = i / per, rem = i % per;
        out[(long)b*T*DIM + rem] = 0.f;
    }
}

// ------------------- launch -------------------
extern "C" void kernel_launch(void* const* d_in, const int* in_sizes, int n_in,
                              void* d_out, int out_size)
{
    const float* seq   = (const float*)d_in[0];
    const float* w1    = (const float*)d_in[1];
    const float* w2    = (const float*)d_in[2];
    const float* Wq    = (const float*)d_in[3];
    const float* Wkv   = (const float*)d_in[4];
    const float* Wstep = (const float*)d_in[5];
    const float* Wmom  = (const float*)d_in[6];
    const float* Wdecay= (const float*)d_in[7];
    const float* Wgate = (const float*)d_in[8];
    const float* Wcomb = (const float*)d_in[9];
    const float* gamma = (const float*)d_in[10];
    float* out = (float*)d_out;

    const int SM4 = 10*64*PH*2 + 2*64*65*4 + 256;   // 125,696
    const int SM6 = 6*64*PH*2 + 64*65*4;            //  71,936

    cudaFuncSetAttribute(k4_grads,    cudaFuncAttributeMaxDynamicSharedMemorySize, SM4);
    cudaFuncSetAttribute(k6_retrieve, cudaFuncAttributeMaxDynamicSharedMemorySize, SM6);

    k1_rmsnorm<<<BB*T, 256>>>(seq, Wstep, Wgate);
    k2_chunkgates<<<dim3(NCH, BB), 256>>>(Wmom, Wdecay);
    kmma<<<dim3(12, 256), 256>>>(Wq, Wkv, nullptr, 0);
    k4_grads<<<dim3(NCH, BH), 256, SM4>>>(w1, w2);
    k5_scan<<<dim3(16, BH, 2), 256>>>();
    k6_retrieve<<<dim3(NCH, BH), 256, SM6>>>(w1, w2, gamma);
    kmma<<<dim3(4, 256), 256>>>(Wcomb, nullptr, out, 1);
    k0_zero<<<504, 256>>>(out);
}

// round 6
// speedup vs baseline: 1.7576x; 1.1636x over previous
#include <cuda_runtime.h>
#include <cuda_bf16.h>
#include <stdint.h>
#include <math.h>

#define BB   4
#define T    8192
#define DIM  512
#define H    8
#define D    64
#define C    64
#define NCH  128           // T/C
#define BH   32            // BB*H
#define EPSR 1.1920929e-07f
#define MAXLR 0.01f
#define PH   72            // bf16 smem pitch (halves): 144B rows, 16B aligned

// ------------------- scratch (device globals; no allocs allowed) -------------------
__device__ float g_s   [BB*T*DIM];
__device__ float g_q   [BH*T*D];
__device__ float g_k   [BH*T*D];
__device__ float g_v   [BH*T*D];
__device__ float g_lr  [BH*T];         // sigmoid(s@Wstep)*MAXLR*(2/D) (prefolded)
__device__ float g_gate[BH*T];
__device__ float g_mg  [BH*NCH];
__device__ float g_dec [BH*NCH];
__device__ float g_u1  [(long)BH*NCH*D*D];
__device__ float g_u2  [(long)BH*NCH*D*D];
__device__ float g_vals[BB*T*DIM];

__device__ __forceinline__ float sigm(float x){ return 1.f/(1.f+__expf(-x)); }

__device__ __forceinline__ uint32_t smem_u32(const void* p){
    uint32_t a;
    asm("{ .reg .u64 t; cvta.to.shared.u64 t, %1; cvt.u32.u64 %0, t; }" : "=r"(a) : "l"(p));
    return a;
}
__device__ __forceinline__ void ldm4(uint32_t* r, uint32_t addr){
    asm volatile("ldmatrix.sync.aligned.m8n8.x4.shared.b16 {%0,%1,%2,%3}, [%4];"
                 : "=r"(r[0]),"=r"(r[1]),"=r"(r[2]),"=r"(r[3]) : "r"(addr));
}
__device__ __forceinline__ void ldm4t(uint32_t* r, uint32_t addr){
    asm volatile("ldmatrix.sync.aligned.m8n8.x4.trans.shared.b16 {%0,%1,%2,%3}, [%4];"
                 : "=r"(r[0]),"=r"(r[1]),"=r"(r[2]),"=r"(r[3]) : "r"(addr));
}
__device__ __forceinline__ void mma16816(float* c, const uint32_t* a, uint32_t b0, uint32_t b1){
    asm volatile("mma.sync.aligned.m16n8k16.row.col.f32.bf16.bf16.f32 "
                 "{%0,%1,%2,%3}, {%4,%5,%6,%7}, {%8,%9}, {%0,%1,%2,%3};"
                 : "+f"(c[0]),"+f"(c[1]),"+f"(c[2]),"+f"(c[3])
                 : "r"(a[0]),"r"(a[1]),"r"(a[2]),"r"(a[3]), "r"(b0),"r"(b1));
}
__device__ __forceinline__ void bsplit(float v, uint16_t& hi, uint16_t& lo){
    __nv_bfloat16 h = __float2bfloat16(v);
    __nv_bfloat16 l = __float2bfloat16(v - __bfloat162float(h));
    hi = __bfloat16_as_ushort(h);
    lo = __bfloat16_as_ushort(l);
}
__device__ __forceinline__ float bjoin(uint16_t hi, uint16_t lo){
    return __bfloat162float(__ushort_as_bfloat16(hi)) +
           __bfloat162float(__ushort_as_bfloat16(lo));
}

// ===== warp-tiled 64x64x64 bf16-split GEMM: 8 warps, each m16 x n32 =====
template<int AT, int BT, class CB>
__device__ __forceinline__ void tmm64(int wid, int l,
    const uint16_t* Ah_, const uint16_t* Al_,
    const uint16_t* Bh_, const uint16_t* Bl_, CB cb)
{
    int wm = wid & 3, wn = wid >> 2;
    float acc[4][4];
    #pragma unroll
    for (int i = 0; i < 4; i++)
        #pragma unroll
        for (int e = 0; e < 4; e++) acc[i][e] = 0.f;
    uint32_t aAh = smem_u32(Ah_), aAl = smem_u32(Al_);
    uint32_t aBh = smem_u32(Bh_), aBl = smem_u32(Bl_);
    #pragma unroll
    for (int ks = 0; ks < 4; ks++){
        int k0 = ks*16;
        uint32_t ah[4], al[4];
        if (!AT){
            uint32_t ad = (uint32_t)((wm*16 + (l&15))*PH + k0 + ((l>>4)<<3))*2u;
            ldm4(ah, aAh + ad); ldm4(al, aAl + ad);
        } else {
            uint32_t ad = (uint32_t)((k0 + (l&15))*PH + wm*16 + ((l>>4)<<3))*2u;
            uint32_t t[4];
            ldm4t(t, aAh + ad); ah[0]=t[0]; ah[1]=t[2]; ah[2]=t[1]; ah[3]=t[3];
            ldm4t(t, aAl + ad); al[0]=t[0]; al[1]=t[2]; al[2]=t[1]; al[3]=t[3];
        }
        uint32_t bh[2][4], bl[2][4];
        #pragma unroll
        for (int hh = 0; hh < 2; hh++){
            int n0 = wn*32 + hh*16;
            if (!BT){
                uint32_t bd = (uint32_t)((k0 + (l&15))*PH + n0 + ((l>>4)<<3))*2u;
                ldm4t(bh[hh], aBh + bd); ldm4t(bl[hh], aBl + bd);
            } else {
                uint32_t bd = (uint32_t)((n0 + (l&15))*PH + k0 + ((l>>4)<<3))*2u;
                uint32_t t[4];
                ldm4(t, aBh + bd); bh[hh][0]=t[0]; bh[hh][1]=t[2]; bh[hh][2]=t[1]; bh[hh][3]=t[3];
                ldm4(t, aBl + bd); bl[hh][0]=t[0]; bl[hh][1]=t[2]; bl[hh][2]=t[1]; bl[hh][3]=t[3];
            }
        }
        #pragma unroll
        for (int nt = 0; nt < 4; nt++){
            int hh = nt>>1, o = (nt&1)*2;
            mma16816(acc[nt], ah, bh[hh][o], bh[hh][o+1]);
            mma16816(acc[nt], al, bh[hh][o], bh[hh][o+1]);
            mma16816(acc[nt], ah, bl[hh][o], bl[hh][o+1]);
        }
    }
    #pragma unroll
    for (int nt = 0; nt < 4; nt++)
        #pragma unroll
        for (int e = 0; e < 4; e++){
            int m = wm*16 + (l>>2) + ((e>>1)<<3);
            int n = wn*32 + nt*8 + ((l&3)<<1) + (e&1);
            cb(m, n, acc[nt][e]);
        }
}

// ------------------- K1: rmsnorm + per-token lr & gate -------------------
__global__ void k1_rmsnorm(const float* __restrict__ seq,
                           const float* __restrict__ Wstep,
                           const float* __restrict__ Wgate)
{
    int tok = blockIdx.x;
    int tid = threadIdx.x;
    __shared__ float s[DIM];
    __shared__ float red[256];
    float x0 = seq[(long)tok*DIM + tid*2];
    float x1 = seq[(long)tok*DIM + tid*2 + 1];
    red[tid] = x0*x0 + x1*x1;
    __syncthreads();
    for (int o = 128; o > 0; o >>= 1){
        if (tid < o) red[tid] += red[tid+o];
        __syncthreads();
    }
    float sc = rsqrtf(red[0]*(1.f/DIM) + EPSR);
    float s0 = x0*sc, s1 = x1*sc;
    s[tid*2] = s0; s[tid*2+1] = s1;
    g_s[(long)tok*DIM + tid*2]     = s0;
    g_s[(long)tok*DIM + tid*2 + 1] = s1;
    __syncthreads();
    int w = tid >> 5, lane = tid & 31;
    float ds = 0.f, dg = 0.f;
    for (int i = lane; i < DIM; i += 32){
        float sv = s[i];
        ds += sv * Wstep[i*H + w];
        dg += sv * Wgate[i*H + w];
    }
    for (int o = 16; o; o >>= 1){
        ds += __shfl_down_sync(0xffffffffu, ds, o);
        dg += __shfl_down_sync(0xffffffffu, dg, o);
    }
    if (lane == 0){
        int b = tok / T, t = tok % T;
        int bh = b*H + w;
        g_lr  [(long)bh*T + t] = sigm(ds) * MAXLR * (2.0f/D);
        g_gate[(long)bh*T + t] = sigm(dg);
    }
}

// ------------------- K2: per-chunk momentum / decay gates -------------------
__global__ void k2_chunkgates(const float* __restrict__ Wmom,
                              const float* __restrict__ Wdecay)
{
    int nc = blockIdx.x, b = blockIdx.y;
    int tid = threadIdx.x;
    __shared__ float m[DIM];
    const float* base = g_s + ((long)b*T + nc*C)*DIM;
    float a0 = 0.f, a1 = 0.f;
    for (int r = 0; r < C; r++){
        a0 += base[(long)r*DIM + tid*2];
        a1 += base[(long)r*DIM + tid*2 + 1];
    }
    m[tid*2] = a0*(1.f/C); m[tid*2+1] = a1*(1.f/C);
    __syncthreads();
    int w = tid >> 5, lane = tid & 31;
    float dm = 0.f, dd = 0.f;
    for (int i = lane; i < DIM; i += 32){
        float v = m[i];
        dm += v * Wmom[i*H + w];
        dd += v * Wdecay[i*H + w];
    }
    for (int o = 16; o; o >>= 1){
        dm += __shfl_down_sync(0xffffffffu, dm, o);
        dd += __shfl_down_sync(0xffffffffu, dd, o);
    }
    if (lane == 0){
        int bh = b*H + w;
        g_mg [bh*NCH + nc] = sigm(dm);
        g_dec[bh*NCH + nc] = sigm(dd);
    }
}

// ===================== big GEMMs (mma.sync bf16 2-split) =====================
#define PA 40
#define PB 136
__global__ void __launch_bounds__(256, 2)
kmma(const float* __restrict__ W0, const float* __restrict__ W1,
     float* __restrict__ outp, int mode)
{
    __shared__ __align__(16) uint16_t Ah[128*PA], Al[128*PA];
    __shared__ __align__(16) uint16_t Bh[32*PB],  Bl[32*PB];

    int tid = threadIdx.x, wid = tid >> 5, l = tid & 31;
    int wm = wid & 1, wn = wid >> 1;
    int row0 = blockIdx.y * 128;
    int col0 = blockIdx.x * 128;

    const float* A; const float* Bp; int ldb, bc0;
    if (mode == 0){
        A = g_s;
        if (col0 < 512){ Bp = W0; ldb = 512;  bc0 = col0; }
        else           { Bp = W1; ldb = 1024; bc0 = col0 - 512; }
    } else {
        A = g_vals; Bp = W0; ldb = 512; bc0 = col0;
    }

    float acc[4][4][4];
    #pragma unroll
    for (int i = 0; i < 4; i++)
        #pragma unroll
        for (int j = 0; j < 4; j++)
            #pragma unroll
            for (int e = 0; e < 4; e++) acc[i][j][e] = 0.f;

    uint32_t aAh = smem_u32(Ah), aAl = smem_u32(Al);
    uint32_t aBh = smem_u32(Bh), aBl = smem_u32(Bl);

    int a_row = tid >> 1, a_cg = (tid & 1)*16;
    int b_row = tid >> 3, b_cg = (tid & 7)*16;

    for (int kc = 0; kc < 512; kc += 32){
        {
            const float* ap = A + (long)(row0 + a_row)*512 + kc + a_cg;
            #pragma unroll
            for (int j = 0; j < 4; j++){
                float4 x = *(const float4*)(ap + j*4);
                uint16_t h0,l0,h1,l1,h2,l2,h3,l3;
                bsplit(x.x,h0,l0); bsplit(x.y,h1,l1); bsplit(x.z,h2,l2); bsplit(x.w,h3,l3);
                int o = a_row*PA + a_cg + j*4;
                *(uint32_t*)&Ah[o]   = (uint32_t)h0 | ((uint32_t)h1<<16);
                *(uint32_t*)&Ah[o+2] = (uint32_t)h2 | ((uint32_t)h3<<16);
                *(uint32_t*)&Al[o]   = (uint32_t)l0 | ((uint32_t)l1<<16);
                *(uint32_t*)&Al[o+2] = (uint32_t)l2 | ((uint32_t)l3<<16);
            }
        }
        {
            const float* bp = Bp + (long)(kc + b_row)*ldb + bc0 + b_cg;
            #pragma unroll
            for (int j = 0; j < 4; j++){
                float4 x = *(const float4*)(bp + j*4);
                uint16_t h0,l0,h1,l1,h2,l2,h3,l3;
                bsplit(x.x,h0,l0); bsplit(x.y,h1,l1); bsplit(x.z,h2,l2); bsplit(x.w,h3,l3);
                int o = b_row*PB + b_cg + j*4;
                *(uint32_t*)&Bh[o]   = (uint32_t)h0 | ((uint32_t)h1<<16);
                *(uint32_t*)&Bh[o+2] = (uint32_t)h2 | ((uint32_t)h3<<16);
                *(uint32_t*)&Bl[o]   = (uint32_t)l0 | ((uint32_t)l1<<16);
                *(uint32_t*)&Bl[o+2] = (uint32_t)l2 | ((uint32_t)l3<<16);
            }
        }
        __syncthreads();

        #pragma unroll
        for (int ks = 0; ks < 2; ks++){
            int k0 = ks*16;
            int arow = wm*64 + (l & 15);
            int acol = k0 + (l >> 4)*8;
            int brow = k0 + (l & 15);
            int bcol = wn*32 + (l >> 4)*8;

            uint32_t ah[4][4], bh2[2][4];
            #pragma unroll
            for (int mt = 0; mt < 4; mt++)
                ldm4(ah[mt], aAh + ((arow + mt*16)*PA + acol)*2);
            #pragma unroll
            for (int bt = 0; bt < 2; bt++)
                ldm4t(bh2[bt], aBh + (brow*PB + bcol + bt*16)*2);
            #pragma unroll
            for (int mt = 0; mt < 4; mt++)
                #pragma unroll
                for (int nt = 0; nt < 4; nt++)
                    mma16816(acc[mt][nt], ah[mt], bh2[nt>>1][(nt&1)?2:0], bh2[nt>>1][(nt&1)?3:1]);
            {
                uint32_t al4[4][4];
                #pragma unroll
                for (int mt = 0; mt < 4; mt++)
                    ldm4(al4[mt], aAl + ((arow + mt*16)*PA + acol)*2);
                #pragma unroll
                for (int mt = 0; mt < 4; mt++)
                    #pragma unroll
                    for (int nt = 0; nt < 4; nt++)
                        mma16816(acc[mt][nt], al4[mt], bh2[nt>>1][(nt&1)?2:0], bh2[nt>>1][(nt&1)?3:1]);
            }
            {
                uint32_t bl2[2][4];
                #pragma unroll
                for (int bt = 0; bt < 2; bt++)
                    ldm4t(bl2[bt], aBl + (brow*PB + bcol + bt*16)*2);
                #pragma unroll
                for (int mt = 0; mt < 4; mt++)
                    #pragma unroll
                    for (int nt = 0; nt < 4; nt++)
                        mma16816(acc[mt][nt], ah[mt], bl2[nt>>1][(nt&1)?2:0], bl2[nt>>1][(nt&1)?3:1]);
            }
        }
        __syncthreads();
    }

    int g = l >> 2, tq = l & 3;
    #pragma unroll
    for (int mt = 0; mt < 4; mt++){
        #pragma unroll
        for (int nt = 0; nt < 4; nt++){
            int col = col0 + wn*32 + nt*8 + 2*tq;
            #pragma unroll
            for (int half = 0; half < 2; half++){
                int r = row0 + wm*64 + mt*16 + g + half*8;
                float2 v = make_float2(acc[mt][nt][half*2], acc[mt][nt][half*2+1]);
                if (mode == 0){
                    int mtx = col >> 9, cc = col & 511;
                    int hh = cc >> 6, j0 = cc & 63;
                    float* dst = (mtx == 0) ? g_q : (mtx == 1 ? g_k : g_v);
                    int b_ = r >> 13, tok = r & 8191;
                    *(float2*)(dst + ((long)(b_*H + hh)*T + tok)*D + j0) = v;
                } else {
                    int b_ = r >> 13, jr = r & 8191;
                    if (jr <= T - C)
                        *(float2*)(outp + ((long)b_*T + jr + (C-1))*DIM + col) = v;
                }
            }
        }
    }
}

// ------------------- K4: per-chunk MLP grads via tensor cores -------------------
// smem: 10 bf16 buffers (K,W,H,Y,D hi/lo) + Vf (fp32) + lr.  X stored bf16-split in D.
__global__ void __launch_bounds__(256)
k4_grads(const float* __restrict__ w1, const float* __restrict__ w2)
{
    extern __shared__ __align__(16) char smraw[];
    uint16_t* Kh = (uint16_t*)smraw;
    uint16_t* Kl = Kh + 64*PH;
    uint16_t* Wh = Kl + 64*PH;
    uint16_t* Wl = Wh + 64*PH;
    uint16_t* Hh = Wl + 64*PH;
    uint16_t* Hl = Hh + 64*PH;
    uint16_t* Yh = Hl + 64*PH;   // dY
    uint16_t* Yl = Yh + 64*PH;
    uint16_t* Dh = Yl + 64*PH;   // X, then dX
    uint16_t* Dl = Dh + 64*PH;
    float* Vf  = (float*)(Dl + 64*PH);   // 64*65
    float* slr = Vf + 64*65;             // 64

    int nc = blockIdx.x, bh = blockIdx.y;
    int tid = threadIdx.x, wid = tid >> 5, l = tid & 31;
    long base = ((long)bh*T + nc*C)*D;
    for (int idx = tid; idx < 4096; idx += 256){
        int r = idx >> 6, c = idx & 63;
        uint16_t h_, l_;
        bsplit(g_k[base + idx], h_, l_); Kh[r*PH+c] = h_; Kl[r*PH+c] = l_;
        bsplit(w1[idx],        h_, l_); Wh[r*PH+c] = h_; Wl[r*PH+c] = l_;
        Vf[r*65+c] = g_v[base + idx];
    }
    if (tid < 64) slr[tid] = g_lr[(long)bh*T + nc*C + tid];
    __syncthreads();

    // X = K @ W1 ; H = silu(X).  X saved bf16-split in D buffers.
    tmm64<0,0>(wid, l, Kh, Kl, Wh, Wl, [&](int m, int n, float v){
        uint16_t h_, l_; bsplit(v, h_, l_);
        Dh[m*PH+n] = h_; Dl[m*PH+n] = l_;
        float hv = v * sigm(v);
        bsplit(hv, h_, l_);
        Hh[m*PH+n] = h_; Hl[m*PH+n] = l_;
    });
    __syncthreads();
    for (int idx = tid; idx < 4096; idx += 256){
        int r = idx >> 6, c = idx & 63;
        uint16_t h_, l_; bsplit(w2[idx], h_, l_);
        Wh[r*PH+c] = h_; Wl[r*PH+c] = l_;
    }
    __syncthreads();
    // Y = H @ W2 ; dY = lr*(Y - V)
    tmm64<0,0>(wid, l, Hh, Hl, Wh, Wl, [&](int m, int n, float y){
        float dy = slr[m]*(y - Vf[m*65+n]);
        uint16_t h_, l_; bsplit(dy, h_, l_);
        Yh[m*PH+n] = h_; Yl[m*PH+n] = l_;
    });
    __syncthreads();
    long gbase = ((long)bh*NCH + nc)*4096;
    // G2 = H^T @ dY
    tmm64<1,0>(wid, l, Hh, Hl, Yh, Yl, [&](int m, int n, float v){
        g_u2[gbase + m*64 + n] = -v;
    });
    // dH = dY @ W2^T ; dX = dH * silu'(X)  (X read from D, dX overwrites same elem)
    tmm64<0,1>(wid, l, Yh, Yl, Wh, Wl, [&](int m, int n, float v){
        float x = bjoin(Dh[m*PH+n], Dl[m*PH+n]);
        float sg = sigm(x);
        float dx = v * sg * (1.f + x*(1.f - sg));
        uint16_t h_, l_; bsplit(dx, h_, l_);
        Dh[m*PH+n] = h_; Dl[m*PH+n] = l_;
    });
    __syncthreads();
    // G1 = K^T @ dX
    tmm64<1,0>(wid, l, Kh, Kl, Dh, Dl, [&](int m, int n, float v){
        g_u1[gbase + m*64 + n] = -v;
    });
}

// ------------------- K5: momentum + decay scans -------------------
__global__ void k5_scan()
{
    int e  = blockIdx.x*blockDim.x + threadIdx.x;
    int bh = blockIdx.y;
    float* g = blockIdx.z ? g_u2 : g_u1;
    const float* mg = g_mg  + bh*NCH;
    const float* dc = g_dec + bh*NCH;
    float m = 0.f, u = 0.f;
    long base = (long)bh*NCH*4096 + e;
    for (int t = 0; t < NCH; t++){
        float s = g[base + (long)t*4096];
        m = mg[t]*m + s;
        u = (1.f - dc[t])*u + m;
        g[base + (long)t*4096] = u;
    }
}

// ------------------- K6: retrieve via tensor cores -------------------
// smem: 6 bf16 buffers.  O written bf16-split into retired Q buffers.
__global__ void __launch_bounds__(256)
k6_retrieve(const float* __restrict__ w1, const float* __restrict__ w2,
            const float* __restrict__ gamma)
{
    extern __shared__ __align__(16) char smraw[];
    uint16_t* Qh = (uint16_t*)smraw;     // Q, then O
    uint16_t* Ql = Qh + 64*PH;
    uint16_t* Wh = Ql + 64*PH;
    uint16_t* Wl = Wh + 64*PH;
    uint16_t* Xh = Wl + 64*PH;
    uint16_t* Xl = Xh + 64*PH;

    int nc = blockIdx.x, bh = blockIdx.y;
    int tid = threadIdx.x, wid = tid >> 5, l = tid & 31;
    int h = bh % H, b = bh / H;
    long ubase = ((long)bh*NCH + nc)*4096;
    for (int idx = tid; idx < 4096; idx += 256){
        int r = idx >> 6, c = idx & 63;
        int tok = nc*C + r + (C-1);
        float qv = (tok < T) ? g_q[((long)bh*T + tok)*D + c] : 0.f;
        uint16_t h_, l_;
        bsplit(qv, h_, l_); Qh[r*PH+c] = h_; Ql[r*PH+c] = l_;
        bsplit(w1[idx] + g_u1[ubase + idx], h_, l_); Wh[r*PH+c] = h_; Wl[r*PH+c] = l_;
    }
    __syncthreads();
    // X = silu(Q @ (W1+U1))
    tmm64<0,0>(wid, l, Qh, Ql, Wh, Wl, [&](int m, int n, float v){
        float s = v * sigm(v);
        uint16_t h_, l_; bsplit(s, h_, l_);
        Xh[m*PH+n] = h_; Xl[m*PH+n] = l_;
    });
    __syncthreads();
    for (int idx = tid; idx < 4096; idx += 256){
        int r = idx >> 6, c = idx & 63;
        uint16_t h_, l_; bsplit(w2[idx] + g_u2[ubase + idx], h_, l_);
        Wh[r*PH+c] = h_; Wl[r*PH+c] = l_;
    }
    __syncthreads();
    // O = X @ (W2+U2) -> bf16-split into Q buffers (Q retired)
    tmm64<0,0>(wid, l, Xh, Xl, Wh, Wl, [&](int m, int n, float v){
        uint16_t h_, l_; bsplit(v, h_, l_);
        Qh[m*PH+n] = h_; Ql[m*PH+n] = l_;
    });
    __syncthreads();
    // per-row RMSNorm(64) * (gamma+1) * gate, merged-head layout
    int row = tid >> 2, sub = tid & 3;
    float ss = 0.f;
    float ov[16];
    #pragma unroll
    for (int jj = 0; jj < 16; jj++){
        int j = sub + jj*4;
        float v = bjoin(Qh[row*PH+j], Ql[row*PH+j]);
        ov[jj] = v;
        ss += v*v;
    }
    ss += __shfl_xor_sync(0xffffffffu, ss, 1);
    ss += __shfl_xor_sync(0xffffffffu, ss, 2);
    float sc = rsqrtf(ss*(1.f/64) + EPSR);
    int tokq = nc*C + row + (C-1);
    float gate = (tokq < T) ? g_gate[(long)bh*T + tokq] : 0.f;
    float* dst = g_vals + ((long)b*T + nc*C + row)*DIM + h*D;
    #pragma unroll
    for (int jj = 0; jj < 16; jj++){
        int j = sub + jj*4;
        dst[j] = ov[jj]*sc*(gamma[h*D + j] + 1.f)*gate;
    }
}

// ------------------- K0: zero the first c-1 output tokens -------------------
__global__ void k0_zero(float* __restrict__ out)
{
    int i = blockIdx.x*blockDim.x + threadIdx.x;
    const int per = (C-1)*DIM;
    if (i < BB*per){
        int b = i / per, rem = i % per;
        out[(long)b*T*DIM + rem] = 0.f;
    }
}

// ------------------- launch -------------------
extern "C" void kernel_launch(void* const* d_in, const int* in_sizes, int n_in,
                              void* d_out, int out_size)
{
    const float* seq   = (const float*)d_in[0];
    const float* w1    = (const float*)d_in[1];
    const float* w2    = (const float*)d_in[2];
    const float* Wq    = (const float*)d_in[3];
    const float* Wkv   = (const float*)d_in[4];
    const float* Wstep = (const float*)d_in[5];
    const float* Wmom  = (const float*)d_in[6];
    const float* Wdecay= (const float*)d_in[7];
    const float* Wgate = (const float*)d_in[8];
    const float* Wcomb = (const float*)d_in[9];
    const float* gamma = (const float*)d_in[10];
    float* out = (float*)d_out;

    const int SM4 = 10*64*PH*2 + 64*65*4 + 256;   // 109,056 -> 2 CTAs/SM
    const int SM6 = 6*64*PH*2;                    //  55,296 -> 4 CTAs/SM

    cudaFuncSetAttribute(k4_grads,    cudaFuncAttributeMaxDynamicSharedMemorySize, SM4);
    cudaFuncSetAttribute(k6_retrieve, cudaFuncAttributeMaxDynamicSharedMemorySize, SM6);

    k1_rmsnorm<<<BB*T, 256>>>(seq, Wstep, Wgate);
    k2_chunkgates<<<dim3(NCH, BB), 256>>>(Wmom, Wdecay);
    kmma<<<dim3(12, 256), 256>>>(Wq, Wkv, nullptr, 0);
    k4_grads<<<dim3(NCH, BH), 256, SM4>>>(w1, w2);
    k5_scan<<<dim3(16, BH, 2), 256>>>();
    k6_retrieve<<<dim3(NCH, BH), 256, SM6>>>(w1, w2, gamma);
    kmma<<<dim3(4, 256), 256>>>(Wcomb, nullptr, out, 1);
    k0_zero<<<504, 256>>>(out);
}

// round 7
// speedup vs baseline: 1.7679x; 1.0059x over previous
#include <cuda_runtime.h>
#include <cuda_bf16.h>
#include <stdint.h>
#include <math.h>

#define BB   4
#define T    8192
#define DIM  512
#define H    8
#define D    64
#define C    64
#define NCH  128           // T/C
#define BH   32            // BB*H
#define EPSR 1.1920929e-07f
#define MAXLR 0.01f
#define PH   72            // bf16 smem pitch (halves)

// ------------------- scratch -------------------
__device__ float g_s   [BB*T*DIM];
__device__ float g_q   [BH*T*D];
__device__ float g_k   [BH*T*D];
__device__ float g_v   [BH*T*D];
__device__ float g_lr  [BH*T];
__device__ float g_gate[BH*T];
__device__ float g_mg  [BH*NCH];
__device__ float g_dec [BH*NCH];
__device__ float g_u1  [(long)BH*NCH*D*D];
__device__ float g_u2  [(long)BH*NCH*D*D];
__device__ float g_vals[BB*T*DIM];

__device__ __forceinline__ float sigm(float x){ return 1.f/(1.f+__expf(-x)); }

__device__ __forceinline__ uint32_t smem_u32(const void* p){
    uint32_t a;
    asm("{ .reg .u64 t; cvta.to.shared.u64 t, %1; cvt.u32.u64 %0, t; }" : "=r"(a) : "l"(p));
    return a;
}
__device__ __forceinline__ void ldm4(uint32_t* r, uint32_t addr){
    asm volatile("ldmatrix.sync.aligned.m8n8.x4.shared.b16 {%0,%1,%2,%3}, [%4];"
                 : "=r"(r[0]),"=r"(r[1]),"=r"(r[2]),"=r"(r[3]) : "r"(addr));
}
__device__ __forceinline__ void ldm4t(uint32_t* r, uint32_t addr){
    asm volatile("ldmatrix.sync.aligned.m8n8.x4.trans.shared.b16 {%0,%1,%2,%3}, [%4];"
                 : "=r"(r[0]),"=r"(r[1]),"=r"(r[2]),"=r"(r[3]) : "r"(addr));
}
__device__ __forceinline__ void mma16816(float* c, const uint32_t* a, uint32_t b0, uint32_t b1){
    asm volatile("mma.sync.aligned.m16n8k16.row.col.f32.bf16.bf16.f32 "
                 "{%0,%1,%2,%3}, {%4,%5,%6,%7}, {%8,%9}, {%0,%1,%2,%3};"
                 : "+f"(c[0]),"+f"(c[1]),"+f"(c[2]),"+f"(c[3])
                 : "r"(a[0]),"r"(a[1]),"r"(a[2]),"r"(a[3]), "r"(b0),"r"(b1));
}
__device__ __forceinline__ void bsplit(float v, uint16_t& hi, uint16_t& lo){
    __nv_bfloat16 h = __float2bfloat16(v);
    __nv_bfloat16 l = __float2bfloat16(v - __bfloat162float(h));
    hi = __bfloat16_as_ushort(h);
    lo = __bfloat16_as_ushort(l);
}
__device__ __forceinline__ float bjoin(uint16_t hi, uint16_t lo){
    return __bfloat162float(__ushort_as_bfloat16(hi)) +
           __bfloat162float(__ushort_as_bfloat16(lo));
}
// pack two fp32 into two (hi,lo) 32-bit words
__device__ __forceinline__ void bsplit2(float v0, float v1, uint32_t& hw, uint32_t& lw){
    uint16_t h0,l0,h1,l1;
    bsplit(v0,h0,l0); bsplit(v1,h1,l1);
    hw = (uint32_t)h0 | ((uint32_t)h1<<16);
    lw = (uint32_t)l0 | ((uint32_t)l1<<16);
}

// ===== 8-warp 64x64x64 bf16-split GEMM, pair-callback cb(m, n_even, v0, v1) =====
template<int AT, int BT, class CB>
__device__ __forceinline__ void tmm64(int wid, int l,
    const uint16_t* Ah_, const uint16_t* Al_,
    const uint16_t* Bh_, const uint16_t* Bl_, CB cb)
{
    int wm = wid & 3, wn = wid >> 2;
    float acc[4][4];
    #pragma unroll
    for (int i = 0; i < 4; i++)
        #pragma unroll
        for (int e = 0; e < 4; e++) acc[i][e] = 0.f;
    uint32_t aAh = smem_u32(Ah_), aAl = smem_u32(Al_);
    uint32_t aBh = smem_u32(Bh_), aBl = smem_u32(Bl_);
    #pragma unroll
    for (int ks = 0; ks < 4; ks++){
        int k0 = ks*16;
        uint32_t ah[4], al[4];
        if (!AT){
            uint32_t ad = (uint32_t)((wm*16 + (l&15))*PH + k0 + ((l>>4)<<3))*2u;
            ldm4(ah, aAh + ad); ldm4(al, aAl + ad);
        } else {
            uint32_t ad = (uint32_t)((k0 + (l&15))*PH + wm*16 + ((l>>4)<<3))*2u;
            uint32_t t[4];
            ldm4t(t, aAh + ad); ah[0]=t[0]; ah[1]=t[2]; ah[2]=t[1]; ah[3]=t[3];
            ldm4t(t, aAl + ad); al[0]=t[0]; al[1]=t[2]; al[2]=t[1]; al[3]=t[3];
        }
        uint32_t bh[2][4], bl[2][4];
        #pragma unroll
        for (int hh = 0; hh < 2; hh++){
            int n0 = wn*32 + hh*16;
            if (!BT){
                uint32_t bd = (uint32_t)((k0 + (l&15))*PH + n0 + ((l>>4)<<3))*2u;
                ldm4t(bh[hh], aBh + bd); ldm4t(bl[hh], aBl + bd);
            } else {
                uint32_t bd = (uint32_t)((n0 + (l&15))*PH + k0 + ((l>>4)<<3))*2u;
                uint32_t t[4];
                ldm4(t, aBh + bd); bh[hh][0]=t[0]; bh[hh][1]=t[2]; bh[hh][2]=t[1]; bh[hh][3]=t[3];
                ldm4(t, aBl + bd); bl[hh][0]=t[0]; bl[hh][1]=t[2]; bl[hh][2]=t[1]; bl[hh][3]=t[3];
            }
        }
        #pragma unroll
        for (int nt = 0; nt < 4; nt++){
            int hh = nt>>1, o = (nt&1)*2;
            mma16816(acc[nt], ah, bh[hh][o], bh[hh][o+1]);
            mma16816(acc[nt], al, bh[hh][o], bh[hh][o+1]);
            mma16816(acc[nt], ah, bl[hh][o], bl[hh][o+1]);
        }
    }
    int m0 = wm*16 + (l>>2);
    #pragma unroll
    for (int nt = 0; nt < 4; nt++){
        int n = wn*32 + nt*8 + ((l&3)<<1);
        cb(m0,   n, acc[nt][0], acc[nt][1]);
        cb(m0+8, n, acc[nt][2], acc[nt][3]);
    }
}

// ===== 4-warp variant: warp sub in 0..3 does m16 x n64 =====
template<int AT, int BT, class CB>
__device__ __forceinline__ void tmm64h(int sub, int l,
    const uint16_t* Ah_, const uint16_t* Al_,
    const uint16_t* Bh_, const uint16_t* Bl_, CB cb)
{
    float acc[8][4];
    #pragma unroll
    for (int i = 0; i < 8; i++)
        #pragma unroll
        for (int e = 0; e < 4; e++) acc[i][e] = 0.f;
    uint32_t aAh = smem_u32(Ah_), aAl = smem_u32(Al_);
    uint32_t aBh = smem_u32(Bh_), aBl = smem_u32(Bl_);
    #pragma unroll
    for (int ks = 0; ks < 4; ks++){
        int k0 = ks*16;
        uint32_t ah[4], al[4];
        if (!AT){
            uint32_t ad = (uint32_t)((sub*16 + (l&15))*PH + k0 + ((l>>4)<<3))*2u;
            ldm4(ah, aAh + ad); ldm4(al, aAl + ad);
        } else {
            uint32_t ad = (uint32_t)((k0 + (l&15))*PH + sub*16 + ((l>>4)<<3))*2u;
            uint32_t t[4];
            ldm4t(t, aAh + ad); ah[0]=t[0]; ah[1]=t[2]; ah[2]=t[1]; ah[3]=t[3];
            ldm4t(t, aAl + ad); al[0]=t[0]; al[1]=t[2]; al[2]=t[1]; al[3]=t[3];
        }
        #pragma unroll
        for (int hh = 0; hh < 4; hh++){
            int n0 = hh*16;
            uint32_t bh[4], bl[4];
            if (!BT){
                uint32_t bd = (uint32_t)((k0 + (l&15))*PH + n0 + ((l>>4)<<3))*2u;
                ldm4t(bh, aBh + bd); ldm4t(bl, aBl + bd);
            } else {
                uint32_t bd = (uint32_t)((n0 + (l&15))*PH + k0 + ((l>>4)<<3))*2u;
                uint32_t t[4];
                ldm4(t, aBh + bd); bh[0]=t[0]; bh[1]=t[2]; bh[2]=t[1]; bh[3]=t[3];
                ldm4(t, aBl + bd); bl[0]=t[0]; bl[1]=t[2]; bl[2]=t[1]; bl[3]=t[3];
            }
            #pragma unroll
            for (int q = 0; q < 2; q++){
                int nt = hh*2 + q, o = q*2;
                mma16816(acc[nt], ah, bh[o], bh[o+1]);
                mma16816(acc[nt], al, bh[o], bh[o+1]);
                mma16816(acc[nt], ah, bl[o], bl[o+1]);
            }
        }
    }
    int m0 = sub*16 + (l>>2);
    #pragma unroll
    for (int nt = 0; nt < 8; nt++){
        int n = nt*8 + ((l&3)<<1);
        cb(m0,   n, acc[nt][0], acc[nt][1]);
        cb(m0+8, n, acc[nt][2], acc[nt][3]);
    }
}

// ------------------- K1 -------------------
__global__ void k1_rmsnorm(const float* __restrict__ seq,
                           const float* __restrict__ Wstep,
                           const float* __restrict__ Wgate)
{
    int tok = blockIdx.x;
    int tid = threadIdx.x;
    __shared__ float s[DIM];
    __shared__ float red[256];
    float x0 = seq[(long)tok*DIM + tid*2];
    float x1 = seq[(long)tok*DIM + tid*2 + 1];
    red[tid] = x0*x0 + x1*x1;
    __syncthreads();
    for (int o = 128; o > 0; o >>= 1){
        if (tid < o) red[tid] += red[tid+o];
        __syncthreads();
    }
    float sc = rsqrtf(red[0]*(1.f/DIM) + EPSR);
    float s0 = x0*sc, s1 = x1*sc;
    s[tid*2] = s0; s[tid*2+1] = s1;
    g_s[(long)tok*DIM + tid*2]     = s0;
    g_s[(long)tok*DIM + tid*2 + 1] = s1;
    __syncthreads();
    int w = tid >> 5, lane = tid & 31;
    float ds = 0.f, dg = 0.f;
    for (int i = lane; i < DIM; i += 32){
        float sv = s[i];
        ds += sv * Wstep[i*H + w];
        dg += sv * Wgate[i*H + w];
    }
    for (int o = 16; o; o >>= 1){
        ds += __shfl_down_sync(0xffffffffu, ds, o);
        dg += __shfl_down_sync(0xffffffffu, dg, o);
    }
    if (lane == 0){
        int b = tok / T, t = tok % T;
        int bh = b*H + w;
        g_lr  [(long)bh*T + t] = sigm(ds) * MAXLR * (2.0f/D);
        g_gate[(long)bh*T + t] = sigm(dg);
    }
}

// ------------------- K2 -------------------
__global__ void k2_chunkgates(const float* __restrict__ Wmom,
                              const float* __restrict__ Wdecay)
{
    int nc = blockIdx.x, b = blockIdx.y;
    int tid = threadIdx.x;
    __shared__ float m[DIM];
    const float* base = g_s + ((long)b*T + nc*C)*DIM;
    float a0 = 0.f, a1 = 0.f;
    for (int r = 0; r < C; r++){
        a0 += base[(long)r*DIM + tid*2];
        a1 += base[(long)r*DIM + tid*2 + 1];
    }
    m[tid*2] = a0*(1.f/C); m[tid*2+1] = a1*(1.f/C);
    __syncthreads();
    int w = tid >> 5, lane = tid & 31;
    float dm = 0.f, dd = 0.f;
    for (int i = lane; i < DIM; i += 32){
        float v = m[i];
        dm += v * Wmom[i*H + w];
        dd += v * Wdecay[i*H + w];
    }
    for (int o = 16; o; o >>= 1){
        dm += __shfl_down_sync(0xffffffffu, dm, o);
        dd += __shfl_down_sync(0xffffffffu, dd, o);
    }
    if (lane == 0){
        int bh = b*H + w;
        g_mg [bh*NCH + nc] = sigm(dm);
        g_dec[bh*NCH + nc] = sigm(dd);
    }
}

// ===================== big GEMMs (mma.sync bf16 2-split, A reg-prefetch) =====================
#define PA 40
#define PB 136
__global__ void __launch_bounds__(256, 2)
kmma(const float* __restrict__ W0, const float* __restrict__ W1,
     float* __restrict__ outp, int mode)
{
    __shared__ __align__(16) uint16_t Ah[128*PA], Al[128*PA];
    __shared__ __align__(16) uint16_t Bh[32*PB],  Bl[32*PB];

    int tid = threadIdx.x, wid = tid >> 5, l = tid & 31;
    int wm = wid & 1, wn = wid >> 1;
    int row0 = blockIdx.y * 128;
    int col0 = blockIdx.x * 128;

    const float* A; const float* Bp; int ldb, bc0;
    if (mode == 0){
        A = g_s;
        if (col0 < 512){ Bp = W0; ldb = 512;  bc0 = col0; }
        else           { Bp = W1; ldb = 1024; bc0 = col0 - 512; }
    } else {
        A = g_vals; Bp = W0; ldb = 512; bc0 = col0;
    }

    float acc[4][4][4];
    #pragma unroll
    for (int i = 0; i < 4; i++)
        #pragma unroll
        for (int j = 0; j < 4; j++)
            #pragma unroll
            for (int e = 0; e < 4; e++) acc[i][j][e] = 0.f;

    uint32_t aAh = smem_u32(Ah), aAl = smem_u32(Al);
    uint32_t aBh = smem_u32(Bh), aBl = smem_u32(Bl);

    int a_row = tid >> 1, a_cg = (tid & 1)*16;
    int b_row = tid >> 3, b_cg = (tid & 7)*16;

    // prefetch A chunk 0
    float aR[16];
    {
        const float* ap = A + (long)(row0 + a_row)*512 + a_cg;
        #pragma unroll
        for (int j = 0; j < 4; j++)
            *(float4*)(aR + j*4) = *(const float4*)(ap + j*4);
    }

    for (int i = 0; i < 16; i++){
        int kc = i*32;
        // store prefetched A (split)
        #pragma unroll
        for (int j = 0; j < 4; j++){
            uint32_t hw0, lw0, hw1, lw1;
            bsplit2(aR[j*4+0], aR[j*4+1], hw0, lw0);
            bsplit2(aR[j*4+2], aR[j*4+3], hw1, lw1);
            int o = a_row*PA + a_cg + j*4;
            *(uint32_t*)&Ah[o]   = hw0; *(uint32_t*)&Ah[o+2] = hw1;
            *(uint32_t*)&Al[o]   = lw0; *(uint32_t*)&Al[o+2] = lw1;
        }
        // B (L2-hot weights) inline
        {
            const float* bp = Bp + (long)(kc + b_row)*ldb + bc0 + b_cg;
            #pragma unroll
            for (int j = 0; j < 4; j++){
                float4 x = *(const float4*)(bp + j*4);
                uint32_t hw0, lw0, hw1, lw1;
                bsplit2(x.x, x.y, hw0, lw0);
                bsplit2(x.z, x.w, hw1, lw1);
                int o = b_row*PB + b_cg + j*4;
                *(uint32_t*)&Bh[o]   = hw0; *(uint32_t*)&Bh[o+2] = hw1;
                *(uint32_t*)&Bl[o]   = lw0; *(uint32_t*)&Bl[o+2] = lw1;
            }
        }
        __syncthreads();

        // issue next-A loads (latency hides under MMA work)
        if (i < 15){
            const float* ap = A + (long)(row0 + a_row)*512 + kc + 32 + a_cg;
            #pragma unroll
            for (int j = 0; j < 4; j++)
                *(float4*)(aR + j*4) = *(const float4*)(ap + j*4);
        }

        #pragma unroll
        for (int ks = 0; ks < 2; ks++){
            int k0 = ks*16;
            int arow = wm*64 + (l & 15);
            int acol = k0 + (l >> 4)*8;
            int brow = k0 + (l & 15);
            int bcol = wn*32 + (l >> 4)*8;

            uint32_t ah[4][4], bh2[2][4];
            #pragma unroll
            for (int mt = 0; mt < 4; mt++)
                ldm4(ah[mt], aAh + ((arow + mt*16)*PA + acol)*2);
            #pragma unroll
            for (int bt = 0; bt < 2; bt++)
                ldm4t(bh2[bt], aBh + (brow*PB + bcol + bt*16)*2);
            #pragma unroll
            for (int mt = 0; mt < 4; mt++)
                #pragma unroll
                for (int nt = 0; nt < 4; nt++)
                    mma16816(acc[mt][nt], ah[mt], bh2[nt>>1][(nt&1)?2:0], bh2[nt>>1][(nt&1)?3:1]);
            {
                uint32_t al4[4][4];
                #pragma unroll
                for (int mt = 0; mt < 4; mt++)
                    ldm4(al4[mt], aAl + ((arow + mt*16)*PA + acol)*2);
                #pragma unroll
                for (int mt = 0; mt < 4; mt++)
                    #pragma unroll
                    for (int nt = 0; nt < 4; nt++)
                        mma16816(acc[mt][nt], al4[mt], bh2[nt>>1][(nt&1)?2:0], bh2[nt>>1][(nt&1)?3:1]);
            }
            {
                uint32_t bl2[2][4];
                #pragma unroll
                for (int bt = 0; bt < 2; bt++)
                    ldm4t(bl2[bt], aBl + (brow*PB + bcol + bt*16)*2);
                #pragma unroll
                for (int mt = 0; mt < 4; mt++)
                    #pragma unroll
                    for (int nt = 0; nt < 4; nt++)
                        mma16816(acc[mt][nt], ah[mt], bl2[nt>>1][(nt&1)?2:0], bl2[nt>>1][(nt&1)?3:1]);
            }
        }
        __syncthreads();
    }

    int g = l >> 2, tq = l & 3;
    #pragma unroll
    for (int mt = 0; mt < 4; mt++){
        #pragma unroll
        for (int nt = 0; nt < 4; nt++){
            int col = col0 + wn*32 + nt*8 + 2*tq;
            #pragma unroll
            for (int half = 0; half < 2; half++){
                int r = row0 + wm*64 + mt*16 + g + half*8;
                float2 v = make_float2(acc[mt][nt][half*2], acc[mt][nt][half*2+1]);
                if (mode == 0){
                    int mtx = col >> 9, cc = col & 511;
                    int hh = cc >> 6, j0 = cc & 63;
                    float* dst = (mtx == 0) ? g_q : (mtx == 1 ? g_k : g_v);
                    int b_ = r >> 13, tok = r & 8191;
                    *(float2*)(dst + ((long)(b_*H + hh)*T + tok)*D + j0) = v;
                } else {
                    int b_ = r >> 13, jr = r & 8191;
                    if (jr <= T - C)
                        *(float2*)(outp + ((long)b_*T + jr + (C-1))*DIM + col) = v;
                }
            }
        }
    }
}

// ------------------- K4: per-chunk MLP grads -------------------
__global__ void __launch_bounds__(256)
k4_grads(const float* __restrict__ w1, const float* __restrict__ w2)
{
    extern __shared__ __align__(16) char smraw[];
    uint16_t* Kh = (uint16_t*)smraw;
    uint16_t* Kl = Kh + 64*PH;
    uint16_t* Wh = Kl + 64*PH;
    uint16_t* Wl = Wh + 64*PH;
    uint16_t* Hh = Wl + 64*PH;
    uint16_t* Hl = Hh + 64*PH;
    uint16_t* Yh = Hl + 64*PH;   // dY
    uint16_t* Yl = Yh + 64*PH;
    uint16_t* Dh = Yl + 64*PH;   // X, then dX
    uint16_t* Dl = Dh + 64*PH;
    float* Vf  = (float*)(Dl + 64*PH);   // 64*65
    float* slr = Vf + 64*65;

    int nc = blockIdx.x, bh = blockIdx.y;
    int tid = threadIdx.x, wid = tid >> 5, l = tid & 31;
    long base = ((long)bh*T + nc*C)*D;
    for (int idx = tid; idx < 4096; idx += 256){
        int r = idx >> 6, c = idx & 63;
        uint16_t h_, l_;
        bsplit(g_k[base + idx], h_, l_); Kh[r*PH+c] = h_; Kl[r*PH+c] = l_;
        bsplit(w1[idx],        h_, l_); Wh[r*PH+c] = h_; Wl[r*PH+c] = l_;
        Vf[r*65+c] = g_v[base + idx];
    }
    if (tid < 64) slr[tid] = g_lr[(long)bh*T + nc*C + tid];
    __syncthreads();

    // X = K @ W1 ; H = silu(X). X saved split in D.
    tmm64<0,0>(wid, l, Kh, Kl, Wh, Wl, [&](int m, int n, float v0, float v1){
        uint32_t hw, lw;
        bsplit2(v0, v1, hw, lw);
        *(uint32_t*)&Dh[m*PH+n] = hw; *(uint32_t*)&Dl[m*PH+n] = lw;
        bsplit2(v0*sigm(v0), v1*sigm(v1), hw, lw);
        *(uint32_t*)&Hh[m*PH+n] = hw; *(uint32_t*)&Hl[m*PH+n] = lw;
    });
    __syncthreads();
    for (int idx = tid; idx < 4096; idx += 256){
        int r = idx >> 6, c = idx & 63;
        uint16_t h_, l_; bsplit(w2[idx], h_, l_);
        Wh[r*PH+c] = h_; Wl[r*PH+c] = l_;
    }
    __syncthreads();
    // Y = H @ W2 ; dY = lr*(Y - V)
    tmm64<0,0>(wid, l, Hh, Hl, Wh, Wl, [&](int m, int n, float y0, float y1){
        float lr = slr[m];
        uint32_t hw, lw;
        bsplit2(lr*(y0 - Vf[m*65+n]), lr*(y1 - Vf[m*65+n+1]), hw, lw);
        *(uint32_t*)&Yh[m*PH+n] = hw; *(uint32_t*)&Yl[m*PH+n] = lw;
    });
    __syncthreads();
    long gbase = ((long)bh*NCH + nc)*4096;
    // CONCURRENT: warps 0-3 G2 = H^T@dY ; warps 4-7 dH=dY@W2^T -> dX
    if (wid < 4){
        tmm64h<1,0>(wid, l, Hh, Hl, Yh, Yl, [&](int m, int n, float v0, float v1){
            *(float2*)&g_u2[gbase + m*64 + n] = make_float2(-v0, -v1);
        });
    } else {
        tmm64h<0,1>(wid-4, l, Yh, Yl, Wh, Wl, [&](int m, int n, float v0, float v1){
            float x0 = bjoin(Dh[m*PH+n],   Dl[m*PH+n]);
            float x1 = bjoin(Dh[m*PH+n+1], Dl[m*PH+n+1]);
            float sg0 = sigm(x0), sg1 = sigm(x1);
            float dx0 = v0 * sg0 * (1.f + x0*(1.f - sg0));
            float dx1 = v1 * sg1 * (1.f + x1*(1.f - sg1));
            uint32_t hw, lw;
            bsplit2(dx0, dx1, hw, lw);
            *(uint32_t*)&Dh[m*PH+n] = hw; *(uint32_t*)&Dl[m*PH+n] = lw;
        });
    }
    __syncthreads();
    // G1 = K^T @ dX
    tmm64<1,0>(wid, l, Kh, Kl, Dh, Dl, [&](int m, int n, float v0, float v1){
        *(float2*)&g_u1[gbase + m*64 + n] = make_float2(-v0, -v1);
    });
}

// ------------------- K5: scans -------------------
__global__ void k5_scan()
{
    int e  = blockIdx.x*blockDim.x + threadIdx.x;
    int bh = blockIdx.y;
    float* g = blockIdx.z ? g_u2 : g_u1;
    const float* mg = g_mg  + bh*NCH;
    const float* dc = g_dec + bh*NCH;
    float m = 0.f, u = 0.f;
    long base = (long)bh*NCH*4096 + e;
    for (int t = 0; t < NCH; t++){
        float s = g[base + (long)t*4096];
        m = mg[t]*m + s;
        u = (1.f - dc[t])*u + m;
        g[base + (long)t*4096] = u;
    }
}

// ------------------- K6: retrieve -------------------
__global__ void __launch_bounds__(256)
k6_retrieve(const float* __restrict__ w1, const float* __restrict__ w2,
            const float* __restrict__ gamma)
{
    extern __shared__ __align__(16) char smraw[];
    uint16_t* Qh = (uint16_t*)smraw;     // Q, then O
    uint16_t* Ql = Qh + 64*PH;
    uint16_t* Wh = Ql + 64*PH;
    uint16_t* Wl = Wh + 64*PH;
    uint16_t* Xh = Wl + 64*PH;
    uint16_t* Xl = Xh + 64*PH;

    int nc = blockIdx.x, bh = blockIdx.y;
    int tid = threadIdx.x, wid = tid >> 5, l = tid & 31;
    int h = bh % H, b = bh / H;
    long ubase = ((long)bh*NCH + nc)*4096;
    for (int idx = tid; idx < 4096; idx += 256){
        int r = idx >> 6, c = idx & 63;
        int tok = nc*C + r + (C-1);
        float qv = (tok < T) ? g_q[((long)bh*T + tok)*D + c] : 0.f;
        uint16_t h_, l_;
        bsplit(qv, h_, l_); Qh[r*PH+c] = h_; Ql[r*PH+c] = l_;
        bsplit(w1[idx] + g_u1[ubase + idx], h_, l_); Wh[r*PH+c] = h_; Wl[r*PH+c] = l_;
    }
    __syncthreads();
    tmm64<0,0>(wid, l, Qh, Ql, Wh, Wl, [&](int m, int n, float v0, float v1){
        uint32_t hw, lw;
        bsplit2(v0*sigm(v0), v1*sigm(v1), hw, lw);
        *(uint32_t*)&Xh[m*PH+n] = hw; *(uint32_t*)&Xl[m*PH+n] = lw;
    });
    __syncthreads();
    for (int idx = tid; idx < 4096; idx += 256){
        int r = idx >> 6, c = idx & 63;
        uint16_t h_, l_; bsplit(w2[idx] + g_u2[ubase + idx], h_, l_);
        Wh[r*PH+c] = h_; Wl[r*PH+c] = l_;
    }
    __syncthreads();
    tmm64<0,0>(wid, l, Xh, Xl, Wh, Wl, [&](int m, int n, float v0, float v1){
        uint32_t hw, lw;
        bsplit2(v0, v1, hw, lw);
        *(uint32_t*)&Qh[m*PH+n] = hw; *(uint32_t*)&Ql[m*PH+n] = lw;
    });
    __syncthreads();
    int row = tid >> 2, sub = tid & 3;
    float ss = 0.f;
    float ov[16];
    #pragma unroll
    for (int jj = 0; jj < 16; jj++){
        int j = sub + jj*4;
        float v = bjoin(Qh[row*PH+j], Ql[row*PH+j]);
        ov[jj] = v;
        ss += v*v;
    }
    ss += __shfl_xor_sync(0xffffffffu, ss, 1);
    ss += __shfl_xor_sync(0xffffffffu, ss, 2);
    float sc = rsqrtf(ss*(1.f/64) + EPSR);
    int tokq = nc*C + row + (C-1);
    float gate = (tokq < T) ? g_gate[(long)bh*T + tokq] : 0.f;
    float* dst = g_vals + ((long)b*T + nc*C + row)*DIM + h*D;
    #pragma unroll
    for (int jj = 0; jj < 16; jj++){
        int j = sub + jj*4;
        dst[j] = ov[jj]*sc*(gamma[h*D + j] + 1.f)*gate;
    }
}

// ------------------- K0 -------------------
__global__ void k0_zero(float* __restrict__ out)
{
    int i = blockIdx.x*blockDim.x + threadIdx.x;
    const int per = (C-1)*DIM;
    if (i < BB*per){
        int b = i / per, rem = i % per;
        out[(long)b*T*DIM + rem] = 0.f;
    }
}

// ------------------- launch -------------------
extern "C" void kernel_launch(void* const* d_in, const int* in_sizes, int n_in,
                              void* d_out, int out_size)
{
    const float* seq   = (const float*)d_in[0];
    const float* w1    = (const float*)d_in[1];
    const float* w2    = (const float*)d_in[2];
    const float* Wq    = (const float*)d_in[3];
    const float* Wkv   = (const float*)d_in[4];
    const float* Wstep = (const float*)d_in[5];
    const float* Wmom  = (const float*)d_in[6];
    const float* Wdecay= (const float*)d_in[7];
    const float* Wgate = (const float*)d_in[8];
    const float* Wcomb = (const float*)d_in[9];
    const float* gamma = (const float*)d_in[10];
    float* out = (float*)d_out;

    const int SM4 = 10*64*PH*2 + 64*65*4 + 256;   // 109,056 -> 2 CTAs/SM
    const int SM6 = 6*64*PH*2;                    //  55,296 -> 4 CTAs/SM

    cudaFuncSetAttribute(k4_grads,    cudaFuncAttributeMaxDynamicSharedMemorySize, SM4);
    cudaFuncSetAttribute(k6_retrieve, cudaFuncAttributeMaxDynamicSharedMemorySize, SM6);

    k1_rmsnorm<<<BB*T, 256>>>(seq, Wstep, Wgate);
    k2_chunkgates<<<dim3(NCH, BB), 256>>>(Wmom, Wdecay);
    kmma<<<dim3(12, 256), 256>>>(Wq, Wkv, nullptr, 0);
    k4_grads<<<dim3(NCH, BH), 256, SM4>>>(w1, w2);
    k5_scan<<<dim3(16, BH, 2), 256>>>();
    k6_retrieve<<<dim3(NCH, BH), 256, SM6>>>(w1, w2, gamma);
    kmma<<<dim3(4, 256), 256>>>(Wcomb, nullptr, out, 1);
    k0_zero<<<504, 256>>>(out);
}

// round 8
// speedup vs baseline: 2.0359x; 1.1516x over previous
#include <cuda_runtime.h>
#include <cuda_bf16.h>
#include <stdint.h>
#include <math.h>

#define BB   4
#define T    8192
#define DIM  512
#define H    8
#define D    64
#define C    64
#define NCH  128
#define BH   32
#define EPSR 1.1920929e-07f
#define MAXLR 0.01f
#define PH   72

// ------------------- scratch -------------------
__device__ float g_s   [BB*T*DIM];
__device__ float g_q   [BH*T*D];
__device__ float g_k   [BH*T*D];
__device__ float g_v   [BH*T*D];
__device__ float g_lr  [BH*T];
__device__ float g_gate[BH*T];
__device__ float g_mg  [BH*NCH];
__device__ float g_dec [BH*NCH];
__device__ float g_u1  [(long)BH*NCH*D*D];
__device__ float g_u2  [(long)BH*NCH*D*D];
__device__ float g_vals[BB*T*DIM];

__device__ __forceinline__ float sigm(float x){ return 1.f/(1.f+__expf(-x)); }

__device__ __forceinline__ uint32_t smem_u32(const void* p){
    uint32_t a;
    asm("{ .reg .u64 t; cvta.to.shared.u64 t, %1; cvt.u32.u64 %0, t; }" : "=r"(a) : "l"(p));
    return a;
}
__device__ __forceinline__ void ldm4(uint32_t* r, uint32_t addr){
    asm volatile("ldmatrix.sync.aligned.m8n8.x4.shared.b16 {%0,%1,%2,%3}, [%4];"
                 : "=r"(r[0]),"=r"(r[1]),"=r"(r[2]),"=r"(r[3]) : "r"(addr));
}
__device__ __forceinline__ void ldm4t(uint32_t* r, uint32_t addr){
    asm volatile("ldmatrix.sync.aligned.m8n8.x4.trans.shared.b16 {%0,%1,%2,%3}, [%4];"
                 : "=r"(r[0]),"=r"(r[1]),"=r"(r[2]),"=r"(r[3]) : "r"(addr));
}
__device__ __forceinline__ void mma16816(float* c, const uint32_t* a, uint32_t b0, uint32_t b1){
    asm volatile("mma.sync.aligned.m16n8k16.row.col.f32.bf16.bf16.f32 "
                 "{%0,%1,%2,%3}, {%4,%5,%6,%7}, {%8,%9}, {%0,%1,%2,%3};"
                 : "+f"(c[0]),"+f"(c[1]),"+f"(c[2]),"+f"(c[3])
                 : "r"(a[0]),"r"(a[1]),"r"(a[2]),"r"(a[3]), "r"(b0),"r"(b1));
}
__device__ __forceinline__ void bsplit(float v, uint16_t& hi, uint16_t& lo){
    __nv_bfloat16 h = __float2bfloat16(v);
    __nv_bfloat16 l = __float2bfloat16(v - __bfloat162float(h));
    hi = __bfloat16_as_ushort(h);
    lo = __bfloat16_as_ushort(l);
}
__device__ __forceinline__ float bjoin(uint16_t hi, uint16_t lo){
    return __bfloat162float(__ushort_as_bfloat16(hi)) +
           __bfloat162float(__ushort_as_bfloat16(lo));
}
__device__ __forceinline__ void bsplit2(float v0, float v1, uint32_t& hw, uint32_t& lw){
    uint16_t h0,l0,h1,l1;
    bsplit(v0,h0,l0); bsplit(v1,h1,l1);
    hw = (uint32_t)h0 | ((uint32_t)h1<<16);
    lw = (uint32_t)l0 | ((uint32_t)l1<<16);
}

// ===== 8-warp 64x64x64 bf16-split GEMM (warp tile m16 x n32), cb(m, n_even, v0, v1) =====
template<int AT, int BT, class CB>
__device__ __forceinline__ void tmm64(int wid, int l,
    const uint16_t* Ah_, const uint16_t* Al_,
    const uint16_t* Bh_, const uint16_t* Bl_, CB cb)
{
    int wm = wid & 3, wn = wid >> 2;
    float acc[4][4];
    #pragma unroll
    for (int i = 0; i < 4; i++)
        #pragma unroll
        for (int e = 0; e < 4; e++) acc[i][e] = 0.f;
    uint32_t aAh = smem_u32(Ah_), aAl = smem_u32(Al_);
    uint32_t aBh = smem_u32(Bh_), aBl = smem_u32(Bl_);
    #pragma unroll
    for (int ks = 0; ks < 4; ks++){
        int k0 = ks*16;
        uint32_t ah[4], al[4];
        if (!AT){
            uint32_t ad = (uint32_t)((wm*16 + (l&15))*PH + k0 + ((l>>4)<<3))*2u;
            ldm4(ah, aAh + ad); ldm4(al, aAl + ad);
        } else {
            uint32_t ad = (uint32_t)((k0 + (l&15))*PH + wm*16 + ((l>>4)<<3))*2u;
            uint32_t t[4];
            ldm4t(t, aAh + ad); ah[0]=t[0]; ah[1]=t[2]; ah[2]=t[1]; ah[3]=t[3];
            ldm4t(t, aAl + ad); al[0]=t[0]; al[1]=t[2]; al[2]=t[1]; al[3]=t[3];
        }
        uint32_t bh[2][4], bl[2][4];
        #pragma unroll
        for (int hh = 0; hh < 2; hh++){
            int n0 = wn*32 + hh*16;
            if (!BT){
                uint32_t bd = (uint32_t)((k0 + (l&15))*PH + n0 + ((l>>4)<<3))*2u;
                ldm4t(bh[hh], aBh + bd); ldm4t(bl[hh], aBl + bd);
            } else {
                uint32_t bd = (uint32_t)((n0 + (l&15))*PH + k0 + ((l>>4)<<3))*2u;
                uint32_t t[4];
                ldm4(t, aBh + bd); bh[hh][0]=t[0]; bh[hh][1]=t[2]; bh[hh][2]=t[1]; bh[hh][3]=t[3];
                ldm4(t, aBl + bd); bl[hh][0]=t[0]; bl[hh][1]=t[2]; bl[hh][2]=t[1]; bl[hh][3]=t[3];
            }
        }
        #pragma unroll
        for (int nt = 0; nt < 4; nt++){
            int hh = nt>>1, o = (nt&1)*2;
            mma16816(acc[nt], ah, bh[hh][o], bh[hh][o+1]);
            mma16816(acc[nt], al, bh[hh][o], bh[hh][o+1]);
            mma16816(acc[nt], ah, bl[hh][o], bl[hh][o+1]);
        }
    }
    int m0 = wm*16 + (l>>2);
    #pragma unroll
    for (int nt = 0; nt < 4; nt++){
        int n = wn*32 + nt*8 + ((l&3)<<1);
        cb(m0,   n, acc[nt][0], acc[nt][1]);
        cb(m0+8, n, acc[nt][2], acc[nt][3]);
    }
}

// ===== 16-warp variant (warp tile m16 x n16) =====
template<int AT, int BT, class CB>
__device__ __forceinline__ void tmm64w(int wid, int l,
    const uint16_t* Ah_, const uint16_t* Al_,
    const uint16_t* Bh_, const uint16_t* Bl_, CB cb)
{
    int wm = wid & 3, wn = wid >> 2;       // wn 0..3
    float acc[2][4];
    #pragma unroll
    for (int i = 0; i < 2; i++)
        #pragma unroll
        for (int e = 0; e < 4; e++) acc[i][e] = 0.f;
    uint32_t aAh = smem_u32(Ah_), aAl = smem_u32(Al_);
    uint32_t aBh = smem_u32(Bh_), aBl = smem_u32(Bl_);
    #pragma unroll
    for (int ks = 0; ks < 4; ks++){
        int k0 = ks*16;
        uint32_t ah[4], al[4];
        if (!AT){
            uint32_t ad = (uint32_t)((wm*16 + (l&15))*PH + k0 + ((l>>4)<<3))*2u;
            ldm4(ah, aAh + ad); ldm4(al, aAl + ad);
        } else {
            uint32_t ad = (uint32_t)((k0 + (l&15))*PH + wm*16 + ((l>>4)<<3))*2u;
            uint32_t t[4];
            ldm4t(t, aAh + ad); ah[0]=t[0]; ah[1]=t[2]; ah[2]=t[1]; ah[3]=t[3];
            ldm4t(t, aAl + ad); al[0]=t[0]; al[1]=t[2]; al[2]=t[1]; al[3]=t[3];
        }
        int n0 = wn*16;
        uint32_t bh[4], bl[4];
        if (!BT){
            uint32_t bd = (uint32_t)((k0 + (l&15))*PH + n0 + ((l>>4)<<3))*2u;
            ldm4t(bh, aBh + bd); ldm4t(bl, aBl + bd);
        } else {
            uint32_t bd = (uint32_t)((n0 + (l&15))*PH + k0 + ((l>>4)<<3))*2u;
            uint32_t t[4];
            ldm4(t, aBh + bd); bh[0]=t[0]; bh[1]=t[2]; bh[2]=t[1]; bh[3]=t[3];
            ldm4(t, aBl + bd); bl[0]=t[0]; bl[1]=t[2]; bl[2]=t[1]; bl[3]=t[3];
        }
        #pragma unroll
        for (int q = 0; q < 2; q++){
            int o = q*2;
            mma16816(acc[q], ah, bh[o], bh[o+1]);
            mma16816(acc[q], al, bh[o], bh[o+1]);
            mma16816(acc[q], ah, bl[o], bl[o+1]);
        }
    }
    int m0 = wm*16 + (l>>2);
    #pragma unroll
    for (int q = 0; q < 2; q++){
        int n = wn*16 + q*8 + ((l&3)<<1);
        cb(m0,   n, acc[q][0], acc[q][1]);
        cb(m0+8, n, acc[q][2], acc[q][3]);
    }
}

// ------------------- K1 -------------------
__global__ void k1_rmsnorm(const float* __restrict__ seq,
                           const float* __restrict__ Wstep,
                           const float* __restrict__ Wgate)
{
    int tok = blockIdx.x;
    int tid = threadIdx.x;
    __shared__ float s[DIM];
    __shared__ float red[256];
    float x0 = seq[(long)tok*DIM + tid*2];
    float x1 = seq[(long)tok*DIM + tid*2 + 1];
    red[tid] = x0*x0 + x1*x1;
    __syncthreads();
    for (int o = 128; o > 0; o >>= 1){
        if (tid < o) red[tid] += red[tid+o];
        __syncthreads();
    }
    float sc = rsqrtf(red[0]*(1.f/DIM) + EPSR);
    float s0 = x0*sc, s1 = x1*sc;
    s[tid*2] = s0; s[tid*2+1] = s1;
    g_s[(long)tok*DIM + tid*2]     = s0;
    g_s[(long)tok*DIM + tid*2 + 1] = s1;
    __syncthreads();
    int w = tid >> 5, lane = tid & 31;
    float ds = 0.f, dg = 0.f;
    for (int i = lane; i < DIM; i += 32){
        float sv = s[i];
        ds += sv * Wstep[i*H + w];
        dg += sv * Wgate[i*H + w];
    }
    for (int o = 16; o; o >>= 1){
        ds += __shfl_down_sync(0xffffffffu, ds, o);
        dg += __shfl_down_sync(0xffffffffu, dg, o);
    }
    if (lane == 0){
        int b = tok / T, t = tok % T;
        int bh = b*H + w;
        g_lr  [(long)bh*T + t] = sigm(ds) * MAXLR * (2.0f/D);
        g_gate[(long)bh*T + t] = sigm(dg);
    }
}

// ------------------- K2 -------------------
__global__ void k2_chunkgates(const float* __restrict__ Wmom,
                              const float* __restrict__ Wdecay)
{
    int nc = blockIdx.x, b = blockIdx.y;
    int tid = threadIdx.x;
    __shared__ float m[DIM];
    const float* base = g_s + ((long)b*T + nc*C)*DIM;
    float a0 = 0.f, a1 = 0.f;
    for (int r = 0; r < C; r++){
        a0 += base[(long)r*DIM + tid*2];
        a1 += base[(long)r*DIM + tid*2 + 1];
    }
    m[tid*2] = a0*(1.f/C); m[tid*2+1] = a1*(1.f/C);
    __syncthreads();
    int w = tid >> 5, lane = tid & 31;
    float dm = 0.f, dd = 0.f;
    for (int i = lane; i < DIM; i += 32){
        float v = m[i];
        dm += v * Wmom[i*H + w];
        dd += v * Wdecay[i*H + w];
    }
    for (int o = 16; o; o >>= 1){
        dm += __shfl_down_sync(0xffffffffu, dm, o);
        dd += __shfl_down_sync(0xffffffffu, dd, o);
    }
    if (lane == 0){
        int bh = b*H + w;
        g_mg [bh*NCH + nc] = sigm(dm);
        g_dec[bh*NCH + nc] = sigm(dd);
    }
}

// ===================== big GEMMs: bf16 2-split, 2-stage double buffer =====================
#define PA 40
#define PB 136
#define STGH (128*PA + 128*PA + 32*PB + 32*PB)   // 18944 halves per stage
__global__ void __launch_bounds__(256, 2)
kmma(const float* __restrict__ W0, const float* __restrict__ W1,
     float* __restrict__ outp, int mode)
{
    extern __shared__ __align__(16) uint16_t kms[];

    int tid = threadIdx.x, wid = tid >> 5, l = tid & 31;
    int wm = wid & 1, wn = wid >> 1;
    int row0 = blockIdx.y * 128;
    int col0 = blockIdx.x * 128;

    const float* A; const float* Bp; int ldb, bc0;
    if (mode == 0){
        A = g_s;
        if (col0 < 512){ Bp = W0; ldb = 512;  bc0 = col0; }
        else           { Bp = W1; ldb = 1024; bc0 = col0 - 512; }
    } else {
        A = g_vals; Bp = W0; ldb = 512; bc0 = col0;
    }

    float acc[4][4][4];
    #pragma unroll
    for (int i = 0; i < 4; i++)
        #pragma unroll
        for (int j = 0; j < 4; j++)
            #pragma unroll
            for (int e = 0; e < 4; e++) acc[i][j][e] = 0.f;

    int a_row = tid >> 1, a_cg = (tid & 1)*16;
    int b_row = tid >> 3, b_cg = (tid & 7)*16;

    uint32_t base0 = smem_u32(kms);

    // helpers to address stage s
    auto AhP = [&](int s){ return kms + s*STGH; };
    auto AlP = [&](int s){ return kms + s*STGH + 128*PA; };
    auto BhP = [&](int s){ return kms + s*STGH + 2*128*PA; };
    auto BlP = [&](int s){ return kms + s*STGH + 2*128*PA + 32*PB; };

    float aR[16];
    // load + store chunk 0 into stage 0
    {
        const float* ap = A + (long)(row0 + a_row)*512 + a_cg;
        #pragma unroll
        for (int j = 0; j < 4; j++)
            *(float4*)(aR + j*4) = *(const float4*)(ap + j*4);
        uint16_t* Ah = AhP(0); uint16_t* Al = AlP(0);
        #pragma unroll
        for (int j = 0; j < 4; j++){
            uint32_t hw0, lw0, hw1, lw1;
            bsplit2(aR[j*4+0], aR[j*4+1], hw0, lw0);
            bsplit2(aR[j*4+2], aR[j*4+3], hw1, lw1);
            int o = a_row*PA + a_cg + j*4;
            *(uint32_t*)&Ah[o]   = hw0; *(uint32_t*)&Ah[o+2] = hw1;
            *(uint32_t*)&Al[o]   = lw0; *(uint32_t*)&Al[o+2] = lw1;
        }
        const float* bp = Bp + (long)b_row*ldb + bc0 + b_cg;
        uint16_t* Bh = BhP(0); uint16_t* Bl = BlP(0);
        #pragma unroll
        for (int j = 0; j < 4; j++){
            float4 x = *(const float4*)(bp + j*4);
            uint32_t hw0, lw0, hw1, lw1;
            bsplit2(x.x, x.y, hw0, lw0);
            bsplit2(x.z, x.w, hw1, lw1);
            int o = b_row*PB + b_cg + j*4;
            *(uint32_t*)&Bh[o]   = hw0; *(uint32_t*)&Bh[o+2] = hw1;
            *(uint32_t*)&Bl[o]   = lw0; *(uint32_t*)&Bl[o+2] = lw1;
        }
    }
    __syncthreads();

    for (int i = 0; i < 16; i++){
        int cur = i & 1, nxt = cur ^ 1;
        // prefetch next A into regs
        if (i < 15){
            const float* ap = A + (long)(row0 + a_row)*512 + (i+1)*32 + a_cg;
            #pragma unroll
            for (int j = 0; j < 4; j++)
                *(float4*)(aR + j*4) = *(const float4*)(ap + j*4);
        }

        uint32_t aAh = base0 + (uint32_t)(cur*STGH)*2u;
        uint32_t aAl = aAh + 128*PA*2u;
        uint32_t aBh = aAh + 2u*128*PA*2u;
        uint32_t aBl = aBh + 32*PB*2u;

        #pragma unroll
        for (int ks = 0; ks < 2; ks++){
            int k0 = ks*16;
            int arow = wm*64 + (l & 15);
            int acol = k0 + (l >> 4)*8;
            int brow = k0 + (l & 15);
            int bcol = wn*32 + (l >> 4)*8;

            uint32_t ah[4][4], bh2[2][4];
            #pragma unroll
            for (int mt = 0; mt < 4; mt++)
                ldm4(ah[mt], aAh + ((arow + mt*16)*PA + acol)*2);
            #pragma unroll
            for (int bt = 0; bt < 2; bt++)
                ldm4t(bh2[bt], aBh + (brow*PB + bcol + bt*16)*2);
            #pragma unroll
            for (int mt = 0; mt < 4; mt++)
                #pragma unroll
                for (int nt = 0; nt < 4; nt++)
                    mma16816(acc[mt][nt], ah[mt], bh2[nt>>1][(nt&1)?2:0], bh2[nt>>1][(nt&1)?3:1]);
            {
                uint32_t al4[4][4];
                #pragma unroll
                for (int mt = 0; mt < 4; mt++)
                    ldm4(al4[mt], aAl + ((arow + mt*16)*PA + acol)*2);
                #pragma unroll
                for (int mt = 0; mt < 4; mt++)
                    #pragma unroll
                    for (int nt = 0; nt < 4; nt++)
                        mma16816(acc[mt][nt], al4[mt], bh2[nt>>1][(nt&1)?2:0], bh2[nt>>1][(nt&1)?3:1]);
            }
            {
                uint32_t bl2[2][4];
                #pragma unroll
                for (int bt = 0; bt < 2; bt++)
                    ldm4t(bl2[bt], aBl + (brow*PB + bcol + bt*16)*2);
                #pragma unroll
                for (int mt = 0; mt < 4; mt++)
                    #pragma unroll
                    for (int nt = 0; nt < 4; nt++)
                        mma16816(acc[mt][nt], ah[mt], bl2[nt>>1][(nt&1)?2:0], bl2[nt>>1][(nt&1)?3:1]);
            }
        }

        // store next chunk into stage nxt
        if (i < 15){
            uint16_t* Ah = AhP(nxt); uint16_t* Al = AlP(nxt);
            #pragma unroll
            for (int j = 0; j < 4; j++){
                uint32_t hw0, lw0, hw1, lw1;
                bsplit2(aR[j*4+0], aR[j*4+1], hw0, lw0);
                bsplit2(aR[j*4+2], aR[j*4+3], hw1, lw1);
                int o = a_row*PA + a_cg + j*4;
                *(uint32_t*)&Ah[o]   = hw0; *(uint32_t*)&Ah[o+2] = hw1;
                *(uint32_t*)&Al[o]   = lw0; *(uint32_t*)&Al[o+2] = lw1;
            }
            const float* bp = Bp + (long)((i+1)*32 + b_row)*ldb + bc0 + b_cg;
            uint16_t* Bh = BhP(nxt); uint16_t* Bl = BlP(nxt);
            #pragma unroll
            for (int j = 0; j < 4; j++){
                float4 x = *(const float4*)(bp + j*4);
                uint32_t hw0, lw0, hw1, lw1;
                bsplit2(x.x, x.y, hw0, lw0);
                bsplit2(x.z, x.w, hw1, lw1);
                int o = b_row*PB + b_cg + j*4;
                *(uint32_t*)&Bh[o]   = hw0; *(uint32_t*)&Bh[o+2] = hw1;
                *(uint32_t*)&Bl[o]   = lw0; *(uint32_t*)&Bl[o+2] = lw1;
            }
        }
        __syncthreads();
    }

    int g = l >> 2, tq = l & 3;
    #pragma unroll
    for (int mt = 0; mt < 4; mt++){
        #pragma unroll
        for (int nt = 0; nt < 4; nt++){
            int col = col0 + wn*32 + nt*8 + 2*tq;
            #pragma unroll
            for (int half = 0; half < 2; half++){
                int r = row0 + wm*64 + mt*16 + g + half*8;
                float2 v = make_float2(acc[mt][nt][half*2], acc[mt][nt][half*2+1]);
                if (mode == 0){
                    int mtx = col >> 9, cc = col & 511;
                    int hh = cc >> 6, j0 = cc & 63;
                    float* dst = (mtx == 0) ? g_q : (mtx == 1 ? g_k : g_v);
                    int b_ = r >> 13, tok = r & 8191;
                    *(float2*)(dst + ((long)(b_*H + hh)*T + tok)*D + j0) = v;
                } else {
                    int b_ = r >> 13, jr = r & 8191;
                    if (jr <= T - C)
                        *(float2*)(outp + ((long)b_*T + jr + (C-1))*DIM + col) = v;
                }
            }
        }
    }
}

// ------------------- K4: per-chunk MLP grads (512 threads) -------------------
__global__ void __launch_bounds__(512)
k4_grads(const float* __restrict__ w1, const float* __restrict__ w2)
{
    extern __shared__ __align__(16) char smraw[];
    uint16_t* Kh = (uint16_t*)smraw;
    uint16_t* Kl = Kh + 64*PH;
    uint16_t* Wh = Kl + 64*PH;
    uint16_t* Wl = Wh + 64*PH;
    uint16_t* Hh = Wl + 64*PH;
    uint16_t* Hl = Hh + 64*PH;
    uint16_t* Yh = Hl + 64*PH;   // dY
    uint16_t* Yl = Yh + 64*PH;
    uint16_t* Dh = Yl + 64*PH;   // X, then dX
    uint16_t* Dl = Dh + 64*PH;
    float* Vf  = (float*)(Dl + 64*PH);
    float* slr = Vf + 64*65;

    int nc = blockIdx.x, bh = blockIdx.y;
    int tid = threadIdx.x, wid = tid >> 5, l = tid & 31;
    long base = ((long)bh*T + nc*C)*D;
    for (int idx = tid; idx < 4096; idx += 512){
        int r = idx >> 6, c = idx & 63;
        uint16_t h_, l_;
        bsplit(g_k[base + idx], h_, l_); Kh[r*PH+c] = h_; Kl[r*PH+c] = l_;
        bsplit(w1[idx],        h_, l_); Wh[r*PH+c] = h_; Wl[r*PH+c] = l_;
        Vf[r*65+c] = g_v[base + idx];
    }
    if (tid < 64) slr[tid] = g_lr[(long)bh*T + nc*C + tid];
    __syncthreads();

    // X = K @ W1 ; H = silu(X). X saved split in D.
    tmm64w<0,0>(wid, l, Kh, Kl, Wh, Wl, [&](int m, int n, float v0, float v1){
        uint32_t hw, lw;
        bsplit2(v0, v1, hw, lw);
        *(uint32_t*)&Dh[m*PH+n] = hw; *(uint32_t*)&Dl[m*PH+n] = lw;
        bsplit2(v0*sigm(v0), v1*sigm(v1), hw, lw);
        *(uint32_t*)&Hh[m*PH+n] = hw; *(uint32_t*)&Hl[m*PH+n] = lw;
    });
    __syncthreads();
    for (int idx = tid; idx < 4096; idx += 512){
        int r = idx >> 6, c = idx & 63;
        uint16_t h_, l_; bsplit(w2[idx], h_, l_);
        Wh[r*PH+c] = h_; Wl[r*PH+c] = l_;
    }
    __syncthreads();
    // Y = H @ W2 ; dY = lr*(Y - V)
    tmm64w<0,0>(wid, l, Hh, Hl, Wh, Wl, [&](int m, int n, float y0, float y1){
        float lr = slr[m];
        uint32_t hw, lw;
        bsplit2(lr*(y0 - Vf[m*65+n]), lr*(y1 - Vf[m*65+n+1]), hw, lw);
        *(uint32_t*)&Yh[m*PH+n] = hw; *(uint32_t*)&Yl[m*PH+n] = lw;
    });
    __syncthreads();
    long gbase = ((long)bh*NCH + nc)*4096;
    // CONCURRENT: warps 0-7 G2 = H^T@dY ; warps 8-15 dH=dY@W2^T -> dX
    if (wid < 8){
        tmm64<1,0>(wid, l, Hh, Hl, Yh, Yl, [&](int m, int n, float v0, float v1){
            *(float2*)&g_u2[gbase + m*64 + n] = make_float2(-v0, -v1);
        });
    } else {
        tmm64<0,1>(wid-8, l, Yh, Yl, Wh, Wl, [&](int m, int n, float v0, float v1){
            float x0 = bjoin(Dh[m*PH+n],   Dl[m*PH+n]);
            float x1 = bjoin(Dh[m*PH+n+1], Dl[m*PH+n+1]);
            float sg0 = sigm(x0), sg1 = sigm(x1);
            float dx0 = v0 * sg0 * (1.f + x0*(1.f - sg0));
            float dx1 = v1 * sg1 * (1.f + x1*(1.f - sg1));
            uint32_t hw, lw;
            bsplit2(dx0, dx1, hw, lw);
            *(uint32_t*)&Dh[m*PH+n] = hw; *(uint32_t*)&Dl[m*PH+n] = lw;
        });
    }
    __syncthreads();
    // G1 = K^T @ dX
    tmm64w<1,0>(wid, l, Kh, Kl, Dh, Dl, [&](int m, int n, float v0, float v1){
        *(float2*)&g_u1[gbase + m*64 + n] = make_float2(-v0, -v1);
    });
}

// ------------------- K5: scans -------------------
__global__ void k5_scan()
{
    int e  = blockIdx.x*blockDim.x + threadIdx.x;
    int bh = blockIdx.y;
    float* g = blockIdx.z ? g_u2 : g_u1;
    const float* mg = g_mg  + bh*NCH;
    const float* dc = g_dec + bh*NCH;
    float m = 0.f, u = 0.f;
    long base = (long)bh*NCH*4096 + e;
    for (int t = 0; t < NCH; t++){
        float s = g[base + (long)t*4096];
        m = mg[t]*m + s;
        u = (1.f - dc[t])*u + m;
        g[base + (long)t*4096] = u;
    }
}

// ------------------- K6: retrieve (512 threads) -------------------
__global__ void __launch_bounds__(512)
k6_retrieve(const float* __restrict__ w1, const float* __restrict__ w2,
            const float* __restrict__ gamma)
{
    extern __shared__ __align__(16) char smraw[];
    uint16_t* Qh = (uint16_t*)smraw;     // Q, then O
    uint16_t* Ql = Qh + 64*PH;
    uint16_t* Wh = Ql + 64*PH;
    uint16_t* Wl = Wh + 64*PH;
    uint16_t* Xh = Wl + 64*PH;
    uint16_t* Xl = Xh + 64*PH;

    int nc = blockIdx.x, bh = blockIdx.y;
    int tid = threadIdx.x, wid = tid >> 5, l = tid & 31;
    int h = bh % H, b = bh / H;
    long ubase = ((long)bh*NCH + nc)*4096;
    for (int idx = tid; idx < 4096; idx += 512){
        int r = idx >> 6, c = idx & 63;
        int tok = nc*C + r + (C-1);
        float qv = (tok < T) ? g_q[((long)bh*T + tok)*D + c] : 0.f;
        uint16_t h_, l_;
        bsplit(qv, h_, l_); Qh[r*PH+c] = h_; Ql[r*PH+c] = l_;
        bsplit(w1[idx] + g_u1[ubase + idx], h_, l_); Wh[r*PH+c] = h_; Wl[r*PH+c] = l_;
    }
    __syncthreads();
    tmm64w<0,0>(wid, l, Qh, Ql, Wh, Wl, [&](int m, int n, float v0, float v1){
        uint32_t hw, lw;
        bsplit2(v0*sigm(v0), v1*sigm(v1), hw, lw);
        *(uint32_t*)&Xh[m*PH+n] = hw; *(uint32_t*)&Xl[m*PH+n] = lw;
    });
    __syncthreads();
    for (int idx = tid; idx < 4096; idx += 512){
        int r = idx >> 6, c = idx & 63;
        uint16_t h_, l_; bsplit(w2[idx] + g_u2[ubase + idx], h_, l_);
        Wh[r*PH+c] = h_; Wl[r*PH+c] = l_;
    }
    __syncthreads();
    tmm64w<0,0>(wid, l, Xh, Xl, Wh, Wl, [&](int m, int n, float v0, float v1){
        uint32_t hw, lw;
        bsplit2(v0, v1, hw, lw);
        *(uint32_t*)&Qh[m*PH+n] = hw; *(uint32_t*)&Ql[m*PH+n] = lw;
    });
    __syncthreads();
    // per-row RMSNorm: 8 lanes per row
    int row = tid >> 3, sub = tid & 7;
    float ss = 0.f;
    float ov[8];
    #pragma unroll
    for (int jj = 0; jj < 8; jj++){
        int j = sub + jj*8;
        float v = bjoin(Qh[row*PH+j], Ql[row*PH+j]);
        ov[jj] = v;
        ss += v*v;
    }
    ss += __shfl_xor_sync(0xffffffffu, ss, 1);
    ss += __shfl_xor_sync(0xffffffffu, ss, 2);
    ss += __shfl_xor_sync(0xffffffffu, ss, 4);
    float sc = rsqrtf(ss*(1.f/64) + EPSR);
    int tokq = nc*C + row + (C-1);
    float gate = (tokq < T) ? g_gate[(long)bh*T + tokq] : 0.f;
    float* dst = g_vals + ((long)b*T + nc*C + row)*DIM + h*D;
    #pragma unroll
    for (int jj = 0; jj < 8; jj++){
        int j = sub + jj*8;
        dst[j] = ov[jj]*sc*(gamma[h*D + j] + 1.f)*gate;
    }
}

// ------------------- K0 -------------------
__global__ void k0_zero(float* __restrict__ out)
{
    int i = blockIdx.x*blockDim.x + threadIdx.x;
    const int per = (C-1)*DIM;
    if (i < BB*per){
        int b = i / per, rem = i % per;
        out[(long)b*T*DIM + rem] = 0.f;
    }
}

// ------------------- launch -------------------
extern "C" void kernel_launch(void* const* d_in, const int* in_sizes, int n_in,
                              void* d_out, int out_size)
{
    const float* seq   = (const float*)d_in[0];
    const float* w1    = (const float*)d_in[1];
    const float* w2    = (const float*)d_in[2];
    const float* Wq    = (const float*)d_in[3];
    const float* Wkv   = (const float*)d_in[4];
    const float* Wstep = (const float*)d_in[5];
    const float* Wmom  = (const float*)d_in[6];
    const float* Wdecay= (const float*)d_in[7];
    const float* Wgate = (const float*)d_in[8];
    const float* Wcomb = (const float*)d_in[9];
    const float* gamma = (const float*)d_in[10];
    float* out = (float*)d_out;

    const int SM4 = 10*64*PH*2 + 64*65*4 + 256;   // 109,056 -> 2 CTAs/SM, 32 warps
    const int SM6 = 6*64*PH*2;                    //  55,296 -> 4 CTAs/SM, 64 warps
    const int SMG = 2*STGH*2;                     //  75,776 -> 2 CTAs/SM

    cudaFuncSetAttribute(k4_grads,    cudaFuncAttributeMaxDynamicSharedMemorySize, SM4);
    cudaFuncSetAttribute(k6_retrieve, cudaFuncAttributeMaxDynamicSharedMemorySize, SM6);
    cudaFuncSetAttribute(kmma,        cudaFuncAttributeMaxDynamicSharedMemorySize, SMG);

    k1_rmsnorm<<<BB*T, 256>>>(seq, Wstep, Wgate);
    k2_chunkgates<<<dim3(NCH, BB), 256>>>(Wmom, Wdecay);
    kmma<<<dim3(12, 256), 256, SMG>>>(Wq, Wkv, nullptr, 0);
    k4_grads<<<dim3(NCH, BH), 512, SM4>>>(w1, w2);
    k5_scan<<<dim3(16, BH, 2), 256>>>();
    k6_retrieve<<<dim3(NCH, BH), 512, SM6>>>(w1, w2, gamma);
    kmma<<<dim3(4, 256), 256, SMG>>>(Wcomb, nullptr, out, 1);
    k0_zero<<<504, 256>>>(out);
}

// round 9
// speedup vs baseline: 2.1376x; 1.0500x over previous
#include <cuda_runtime.h>
#include <cuda_bf16.h>
#include <stdint.h>
#include <math.h>

#define BB   4
#define T    8192
#define DIM  512
#define H    8
#define D    64
#define C    64
#define NCH  128
#define BH   32
#define EPSR 1.1920929e-07f
#define MAXLR 0.01f
#define PH   72

// ------------------- scratch -------------------
__device__ float g_s   [BB*T*DIM];
__device__ float g_q   [BH*T*D];
__device__ float g_k   [BH*T*D];
__device__ float g_v   [BH*T*D];
__device__ float g_lr  [BH*T];
__device__ float g_gate[BH*T];
__device__ float g_mg  [BH*NCH];
__device__ float g_dec [BH*NCH];
__device__ float g_u1  [(long)BH*NCH*D*D];
__device__ float g_u2  [(long)BH*NCH*D*D];
__device__ float g_vals[BB*T*DIM];

__device__ __forceinline__ float sigm(float x){ return 1.f/(1.f+__expf(-x)); }

__device__ __forceinline__ uint32_t smem_u32(const void* p){
    uint32_t a;
    asm("{ .reg .u64 t; cvta.to.shared.u64 t, %1; cvt.u32.u64 %0, t; }" : "=r"(a) : "l"(p));
    return a;
}
__device__ __forceinline__ void ldm4(uint32_t* r, uint32_t addr){
    asm volatile("ldmatrix.sync.aligned.m8n8.x4.shared.b16 {%0,%1,%2,%3}, [%4];"
                 : "=r"(r[0]),"=r"(r[1]),"=r"(r[2]),"=r"(r[3]) : "r"(addr));
}
__device__ __forceinline__ void ldm4t(uint32_t* r, uint32_t addr){
    asm volatile("ldmatrix.sync.aligned.m8n8.x4.trans.shared.b16 {%0,%1,%2,%3}, [%4];"
                 : "=r"(r[0]),"=r"(r[1]),"=r"(r[2]),"=r"(r[3]) : "r"(addr));
}
__device__ __forceinline__ void mma16816(float* c, const uint32_t* a, uint32_t b0, uint32_t b1){
    asm volatile("mma.sync.aligned.m16n8k16.row.col.f32.bf16.bf16.f32 "
                 "{%0,%1,%2,%3}, {%4,%5,%6,%7}, {%8,%9}, {%0,%1,%2,%3};"
                 : "+f"(c[0]),"+f"(c[1]),"+f"(c[2]),"+f"(c[3])
                 : "r"(a[0]),"r"(a[1]),"r"(a[2]),"r"(a[3]), "r"(b0),"r"(b1));
}
__device__ __forceinline__ void bsplit(float v, uint16_t& hi, uint16_t& lo){
    __nv_bfloat16 h = __float2bfloat16(v);
    __nv_bfloat16 l = __float2bfloat16(v - __bfloat162float(h));
    hi = __bfloat16_as_ushort(h);
    lo = __bfloat16_as_ushort(l);
}
__device__ __forceinline__ float bjoin(uint16_t hi, uint16_t lo){
    return __bfloat162float(__ushort_as_bfloat16(hi)) +
           __bfloat162float(__ushort_as_bfloat16(lo));
}
__device__ __forceinline__ void bsplit2(float v0, float v1, uint32_t& hw, uint32_t& lw){
    uint16_t h0,l0,h1,l1;
    bsplit(v0,h0,l0); bsplit(v1,h1,l1);
    hw = (uint32_t)h0 | ((uint32_t)h1<<16);
    lw = (uint32_t)l0 | ((uint32_t)l1<<16);
}
__device__ __forceinline__ uint32_t bpack2(float v0, float v1){
    return (uint32_t)__bfloat16_as_ushort(__float2bfloat16(v0))
         | ((uint32_t)__bfloat16_as_ushort(__float2bfloat16(v1))<<16);
}

// ===== 8-warp 64x64x64 split GEMM (m16 x n32), 3-term, cb(m, n_even, v0, v1) =====
template<int AT, int BT, class CB>
__device__ __forceinline__ void tmm64(int wid, int l,
    const uint16_t* Ah_, const uint16_t* Al_,
    const uint16_t* Bh_, const uint16_t* Bl_, CB cb)
{
    int wm = wid & 3, wn = wid >> 2;
    float acc[4][4];
    #pragma unroll
    for (int i = 0; i < 4; i++)
        #pragma unroll
        for (int e = 0; e < 4; e++) acc[i][e] = 0.f;
    uint32_t aAh = smem_u32(Ah_), aAl = smem_u32(Al_);
    uint32_t aBh = smem_u32(Bh_), aBl = smem_u32(Bl_);
    #pragma unroll
    for (int ks = 0; ks < 4; ks++){
        int k0 = ks*16;
        uint32_t ah[4], al[4];
        if (!AT){
            uint32_t ad = (uint32_t)((wm*16 + (l&15))*PH + k0 + ((l>>4)<<3))*2u;
            ldm4(ah, aAh + ad); ldm4(al, aAl + ad);
        } else {
            uint32_t ad = (uint32_t)((k0 + (l&15))*PH + wm*16 + ((l>>4)<<3))*2u;
            uint32_t t[4];
            ldm4t(t, aAh + ad); ah[0]=t[0]; ah[1]=t[2]; ah[2]=t[1]; ah[3]=t[3];
            ldm4t(t, aAl + ad); al[0]=t[0]; al[1]=t[2]; al[2]=t[1]; al[3]=t[3];
        }
        uint32_t bh[2][4], bl[2][4];
        #pragma unroll
        for (int hh = 0; hh < 2; hh++){
            int n0 = wn*32 + hh*16;
            if (!BT){
                uint32_t bd = (uint32_t)((k0 + (l&15))*PH + n0 + ((l>>4)<<3))*2u;
                ldm4t(bh[hh], aBh + bd); ldm4t(bl[hh], aBl + bd);
            } else {
                uint32_t bd = (uint32_t)((n0 + (l&15))*PH + k0 + ((l>>4)<<3))*2u;
                uint32_t t[4];
                ldm4(t, aBh + bd); bh[hh][0]=t[0]; bh[hh][1]=t[2]; bh[hh][2]=t[1]; bh[hh][3]=t[3];
                ldm4(t, aBl + bd); bl[hh][0]=t[0]; bl[hh][1]=t[2]; bl[hh][2]=t[1]; bl[hh][3]=t[3];
            }
        }
        #pragma unroll
        for (int nt = 0; nt < 4; nt++){
            int hh = nt>>1, o = (nt&1)*2;
            mma16816(acc[nt], ah, bh[hh][o], bh[hh][o+1]);
            mma16816(acc[nt], al, bh[hh][o], bh[hh][o+1]);
            mma16816(acc[nt], ah, bl[hh][o], bl[hh][o+1]);
        }
    }
    int m0 = wm*16 + (l>>2);
    #pragma unroll
    for (int nt = 0; nt < 4; nt++){
        int n = wn*32 + nt*8 + ((l&3)<<1);
        cb(m0,   n, acc[nt][0], acc[nt][1]);
        cb(m0+8, n, acc[nt][2], acc[nt][3]);
    }
}

// ===== 16-warp variant (m16 x n16), 3-term =====
template<int AT, int BT, class CB>
__device__ __forceinline__ void tmm64w(int wid, int l,
    const uint16_t* Ah_, const uint16_t* Al_,
    const uint16_t* Bh_, const uint16_t* Bl_, CB cb)
{
    int wm = wid & 3, wn = wid >> 2;
    float acc[2][4];
    #pragma unroll
    for (int i = 0; i < 2; i++)
        #pragma unroll
        for (int e = 0; e < 4; e++) acc[i][e] = 0.f;
    uint32_t aAh = smem_u32(Ah_), aAl = smem_u32(Al_);
    uint32_t aBh = smem_u32(Bh_), aBl = smem_u32(Bl_);
    #pragma unroll
    for (int ks = 0; ks < 4; ks++){
        int k0 = ks*16;
        uint32_t ah[4], al[4];
        if (!AT){
            uint32_t ad = (uint32_t)((wm*16 + (l&15))*PH + k0 + ((l>>4)<<3))*2u;
            ldm4(ah, aAh + ad); ldm4(al, aAl + ad);
        } else {
            uint32_t ad = (uint32_t)((k0 + (l&15))*PH + wm*16 + ((l>>4)<<3))*2u;
            uint32_t t[4];
            ldm4t(t, aAh + ad); ah[0]=t[0]; ah[1]=t[2]; ah[2]=t[1]; ah[3]=t[3];
            ldm4t(t, aAl + ad); al[0]=t[0]; al[1]=t[2]; al[2]=t[1]; al[3]=t[3];
        }
        int n0 = wn*16;
        uint32_t bh[4], bl[4];
        if (!BT){
            uint32_t bd = (uint32_t)((k0 + (l&15))*PH + n0 + ((l>>4)<<3))*2u;
            ldm4t(bh, aBh + bd); ldm4t(bl, aBl + bd);
        } else {
            uint32_t bd = (uint32_t)((n0 + (l&15))*PH + k0 + ((l>>4)<<3))*2u;
            uint32_t t[4];
            ldm4(t, aBh + bd); bh[0]=t[0]; bh[1]=t[2]; bh[2]=t[1]; bh[3]=t[3];
            ldm4(t, aBl + bd); bl[0]=t[0]; bl[1]=t[2]; bl[2]=t[1]; bl[3]=t[3];
        }
        #pragma unroll
        for (int q = 0; q < 2; q++){
            int o = q*2;
            mma16816(acc[q], ah, bh[o], bh[o+1]);
            mma16816(acc[q], al, bh[o], bh[o+1]);
            mma16816(acc[q], ah, bl[o], bl[o+1]);
        }
    }
    int m0 = wm*16 + (l>>2);
    #pragma unroll
    for (int q = 0; q < 2; q++){
        int n = wn*16 + q*8 + ((l&3)<<1);
        cb(m0,   n, acc[q][0], acc[q][1]);
        cb(m0+8, n, acc[q][2], acc[q][3]);
    }
}

// ===== single-term variants (gradient path) =====
template<int AT, int BT, class CB>
__device__ __forceinline__ void tmm64_1(int wid, int l,
    const uint16_t* Ah_, const uint16_t* Bh_, CB cb)
{
    int wm = wid & 3, wn = wid >> 2;
    float acc[4][4];
    #pragma unroll
    for (int i = 0; i < 4; i++)
        #pragma unroll
        for (int e = 0; e < 4; e++) acc[i][e] = 0.f;
    uint32_t aAh = smem_u32(Ah_), aBh = smem_u32(Bh_);
    #pragma unroll
    for (int ks = 0; ks < 4; ks++){
        int k0 = ks*16;
        uint32_t ah[4];
        if (!AT){
            uint32_t ad = (uint32_t)((wm*16 + (l&15))*PH + k0 + ((l>>4)<<3))*2u;
            ldm4(ah, aAh + ad);
        } else {
            uint32_t ad = (uint32_t)((k0 + (l&15))*PH + wm*16 + ((l>>4)<<3))*2u;
            uint32_t t[4];
            ldm4t(t, aAh + ad); ah[0]=t[0]; ah[1]=t[2]; ah[2]=t[1]; ah[3]=t[3];
        }
        #pragma unroll
        for (int hh = 0; hh < 2; hh++){
            int n0 = wn*32 + hh*16;
            uint32_t bh[4];
            if (!BT){
                uint32_t bd = (uint32_t)((k0 + (l&15))*PH + n0 + ((l>>4)<<3))*2u;
                ldm4t(bh, aBh + bd);
            } else {
                uint32_t bd = (uint32_t)((n0 + (l&15))*PH + k0 + ((l>>4)<<3))*2u;
                uint32_t t[4];
                ldm4(t, aBh + bd); bh[0]=t[0]; bh[1]=t[2]; bh[2]=t[1]; bh[3]=t[3];
            }
            mma16816(acc[hh*2],   ah, bh[0], bh[1]);
            mma16816(acc[hh*2+1], ah, bh[2], bh[3]);
        }
    }
    int m0 = wm*16 + (l>>2);
    #pragma unroll
    for (int nt = 0; nt < 4; nt++){
        int n = wn*32 + nt*8 + ((l&3)<<1);
        cb(m0,   n, acc[nt][0], acc[nt][1]);
        cb(m0+8, n, acc[nt][2], acc[nt][3]);
    }
}
template<int AT, int BT, class CB>
__device__ __forceinline__ void tmm64w1(int wid, int l,
    const uint16_t* Ah_, const uint16_t* Bh_, CB cb)
{
    int wm = wid & 3, wn = wid >> 2;
    float acc[2][4];
    #pragma unroll
    for (int i = 0; i < 2; i++)
        #pragma unroll
        for (int e = 0; e < 4; e++) acc[i][e] = 0.f;
    uint32_t aAh = smem_u32(Ah_), aBh = smem_u32(Bh_);
    #pragma unroll
    for (int ks = 0; ks < 4; ks++){
        int k0 = ks*16;
        uint32_t ah[4];
        if (!AT){
            uint32_t ad = (uint32_t)((wm*16 + (l&15))*PH + k0 + ((l>>4)<<3))*2u;
            ldm4(ah, aAh + ad);
        } else {
            uint32_t ad = (uint32_t)((k0 + (l&15))*PH + wm*16 + ((l>>4)<<3))*2u;
            uint32_t t[4];
            ldm4t(t, aAh + ad); ah[0]=t[0]; ah[1]=t[2]; ah[2]=t[1]; ah[3]=t[3];
        }
        int n0 = wn*16;
        uint32_t bh[4];
        if (!BT){
            uint32_t bd = (uint32_t)((k0 + (l&15))*PH + n0 + ((l>>4)<<3))*2u;
            ldm4t(bh, aBh + bd);
        } else {
            uint32_t bd = (uint32_t)((n0 + (l&15))*PH + k0 + ((l>>4)<<3))*2u;
            uint32_t t[4];
            ldm4(t, aBh + bd); bh[0]=t[0]; bh[1]=t[2]; bh[2]=t[1]; bh[3]=t[3];
        }
        mma16816(acc[0], ah, bh[0], bh[1]);
        mma16816(acc[1], ah, bh[2], bh[3]);
    }
    int m0 = wm*16 + (l>>2);
    #pragma unroll
    for (int q = 0; q < 2; q++){
        int n = wn*16 + q*8 + ((l&3)<<1);
        cb(m0,   n, acc[q][0], acc[q][1]);
        cb(m0+8, n, acc[q][2], acc[q][3]);
    }
}

// ------------------- K1 -------------------
__global__ void k1_rmsnorm(const float* __restrict__ seq,
                           const float* __restrict__ Wstep,
                           const float* __restrict__ Wgate)
{
    int tok = blockIdx.x;
    int tid = threadIdx.x;
    __shared__ float s[DIM];
    __shared__ float red[256];
    float x0 = seq[(long)tok*DIM + tid*2];
    float x1 = seq[(long)tok*DIM + tid*2 + 1];
    red[tid] = x0*x0 + x1*x1;
    __syncthreads();
    for (int o = 128; o > 0; o >>= 1){
        if (tid < o) red[tid] += red[tid+o];
        __syncthreads();
    }
    float sc = rsqrtf(red[0]*(1.f/DIM) + EPSR);
    float s0 = x0*sc, s1 = x1*sc;
    s[tid*2] = s0; s[tid*2+1] = s1;
    g_s[(long)tok*DIM + tid*2]     = s0;
    g_s[(long)tok*DIM + tid*2 + 1] = s1;
    __syncthreads();
    int w = tid >> 5, lane = tid & 31;
    float ds = 0.f, dg = 0.f;
    for (int i = lane; i < DIM; i += 32){
        float sv = s[i];
        ds += sv * Wstep[i*H + w];
        dg += sv * Wgate[i*H + w];
    }
    for (int o = 16; o; o >>= 1){
        ds += __shfl_down_sync(0xffffffffu, ds, o);
        dg += __shfl_down_sync(0xffffffffu, dg, o);
    }
    if (lane == 0){
        int b = tok / T, t = tok % T;
        int bh = b*H + w;
        g_lr  [(long)bh*T + t] = sigm(ds) * MAXLR * (2.0f/D);
        g_gate[(long)bh*T + t] = sigm(dg);
    }
}

// ------------------- K2 -------------------
__global__ void k2_chunkgates(const float* __restrict__ Wmom,
                              const float* __restrict__ Wdecay)
{
    int nc = blockIdx.x, b = blockIdx.y;
    int tid = threadIdx.x;
    __shared__ float m[DIM];
    const float* base = g_s + ((long)b*T + nc*C)*DIM;
    float a0 = 0.f, a1 = 0.f;
    for (int r = 0; r < C; r++){
        a0 += base[(long)r*DIM + tid*2];
        a1 += base[(long)r*DIM + tid*2 + 1];
    }
    m[tid*2] = a0*(1.f/C); m[tid*2+1] = a1*(1.f/C);
    __syncthreads();
    int w = tid >> 5, lane = tid & 31;
    float dm = 0.f, dd = 0.f;
    for (int i = lane; i < DIM; i += 32){
        float v = m[i];
        dm += v * Wmom[i*H + w];
        dd += v * Wdecay[i*H + w];
    }
    for (int o = 16; o; o >>= 1){
        dm += __shfl_down_sync(0xffffffffu, dm, o);
        dd += __shfl_down_sync(0xffffffffu, dd, o);
    }
    if (lane == 0){
        int bh = b*H + w;
        g_mg [bh*NCH + nc] = sigm(dm);
        g_dec[bh*NCH + nc] = sigm(dd);
    }
}

// ===================== big GEMMs: bf16 2-split, 2-stage double buffer =====================
#define PA 40
#define PB 136
#define STGH (128*PA + 128*PA + 32*PB + 32*PB)
__global__ void __launch_bounds__(256, 2)
kmma(const float* __restrict__ W0, const float* __restrict__ W1,
     float* __restrict__ outp, int mode)
{
    extern __shared__ __align__(16) uint16_t kms[];

    int tid = threadIdx.x, wid = tid >> 5, l = tid & 31;
    int wm = wid & 1, wn = wid >> 1;
    int row0 = blockIdx.y * 128;
    int col0 = blockIdx.x * 128;

    const float* A; const float* Bp; int ldb, bc0;
    if (mode == 0){
        A = g_s;
        if (col0 < 512){ Bp = W0; ldb = 512;  bc0 = col0; }
        else           { Bp = W1; ldb = 1024; bc0 = col0 - 512; }
    } else {
        A = g_vals; Bp = W0; ldb = 512; bc0 = col0;
    }

    float acc[4][4][4];
    #pragma unroll
    for (int i = 0; i < 4; i++)
        #pragma unroll
        for (int j = 0; j < 4; j++)
            #pragma unroll
            for (int e = 0; e < 4; e++) acc[i][j][e] = 0.f;

    int a_row = tid >> 1, a_cg = (tid & 1)*16;
    int b_row = tid >> 3, b_cg = (tid & 7)*16;

    uint32_t base0 = smem_u32(kms);
    auto AhP = [&](int s){ return kms + s*STGH; };
    auto AlP = [&](int s){ return kms + s*STGH + 128*PA; };
    auto BhP = [&](int s){ return kms + s*STGH + 2*128*PA; };
    auto BlP = [&](int s){ return kms + s*STGH + 2*128*PA + 32*PB; };

    float aR[16];
    {
        const float* ap = A + (long)(row0 + a_row)*512 + a_cg;
        #pragma unroll
        for (int j = 0; j < 4; j++)
            *(float4*)(aR + j*4) = *(const float4*)(ap + j*4);
        uint16_t* Ah = AhP(0); uint16_t* Al = AlP(0);
        #pragma unroll
        for (int j = 0; j < 4; j++){
            uint32_t hw0, lw0, hw1, lw1;
            bsplit2(aR[j*4+0], aR[j*4+1], hw0, lw0);
            bsplit2(aR[j*4+2], aR[j*4+3], hw1, lw1);
            int o = a_row*PA + a_cg + j*4;
            *(uint32_t*)&Ah[o]   = hw0; *(uint32_t*)&Ah[o+2] = hw1;
            *(uint32_t*)&Al[o]   = lw0; *(uint32_t*)&Al[o+2] = lw1;
        }
        const float* bp = Bp + (long)b_row*ldb + bc0 + b_cg;
        uint16_t* Bh = BhP(0); uint16_t* Bl = BlP(0);
        #pragma unroll
        for (int j = 0; j < 4; j++){
            float4 x = *(const float4*)(bp + j*4);
            uint32_t hw0, lw0, hw1, lw1;
            bsplit2(x.x, x.y, hw0, lw0);
            bsplit2(x.z, x.w, hw1, lw1);
            int o = b_row*PB + b_cg + j*4;
            *(uint32_t*)&Bh[o]   = hw0; *(uint32_t*)&Bh[o+2] = hw1;
            *(uint32_t*)&Bl[o]   = lw0; *(uint32_t*)&Bl[o+2] = lw1;
        }
    }
    __syncthreads();

    for (int i = 0; i < 16; i++){
        int cur = i & 1, nxt = cur ^ 1;
        if (i < 15){
            const float* ap = A + (long)(row0 + a_row)*512 + (i+1)*32 + a_cg;
            #pragma unroll
            for (int j = 0; j < 4; j++)
                *(float4*)(aR + j*4) = *(const float4*)(ap + j*4);
        }

        uint32_t aAh = base0 + (uint32_t)(cur*STGH)*2u;
        uint32_t aAl = aAh + 128*PA*2u;
        uint32_t aBh = aAh + 2u*128*PA*2u;
        uint32_t aBl = aBh + 32*PB*2u;

        #pragma unroll
        for (int ks = 0; ks < 2; ks++){
            int k0 = ks*16;
            int arow = wm*64 + (l & 15);
            int acol = k0 + (l >> 4)*8;
            int brow = k0 + (l & 15);
            int bcol = wn*32 + (l >> 4)*8;

            uint32_t ah[4][4], bh2[2][4];
            #pragma unroll
            for (int mt = 0; mt < 4; mt++)
                ldm4(ah[mt], aAh + ((arow + mt*16)*PA + acol)*2);
            #pragma unroll
            for (int bt = 0; bt < 2; bt++)
                ldm4t(bh2[bt], aBh + (brow*PB + bcol + bt*16)*2);
            #pragma unroll
            for (int mt = 0; mt < 4; mt++)
                #pragma unroll
                for (int nt = 0; nt < 4; nt++)
                    mma16816(acc[mt][nt], ah[mt], bh2[nt>>1][(nt&1)?2:0], bh2[nt>>1][(nt&1)?3:1]);
            {
                uint32_t al4[4][4];
                #pragma unroll
                for (int mt = 0; mt < 4; mt++)
                    ldm4(al4[mt], aAl + ((arow + mt*16)*PA + acol)*2);
                #pragma unroll
                for (int mt = 0; mt < 4; mt++)
                    #pragma unroll
                    for (int nt = 0; nt < 4; nt++)
                        mma16816(acc[mt][nt], al4[mt], bh2[nt>>1][(nt&1)?2:0], bh2[nt>>1][(nt&1)?3:1]);
            }
            {
                uint32_t bl2[2][4];
                #pragma unroll
                for (int bt = 0; bt < 2; bt++)
                    ldm4t(bl2[bt], aBl + (brow*PB + bcol + bt*16)*2);
                #pragma unroll
                for (int mt = 0; mt < 4; mt++)
                    #pragma unroll
                    for (int nt = 0; nt < 4; nt++)
                        mma16816(acc[mt][nt], ah[mt], bl2[nt>>1][(nt&1)?2:0], bl2[nt>>1][(nt&1)?3:1]);
            }
        }

        if (i < 15){
            uint16_t* Ah = AhP(nxt); uint16_t* Al = AlP(nxt);
            #pragma unroll
            for (int j = 0; j < 4; j++){
                uint32_t hw0, lw0, hw1, lw1;
                bsplit2(aR[j*4+0], aR[j*4+1], hw0, lw0);
                bsplit2(aR[j*4+2], aR[j*4+3], hw1, lw1);
                int o = a_row*PA + a_cg + j*4;
                *(uint32_t*)&Ah[o]   = hw0; *(uint32_t*)&Ah[o+2] = hw1;
                *(uint32_t*)&Al[o]   = lw0; *(uint32_t*)&Al[o+2] = lw1;
            }
            const float* bp = Bp + (long)((i+1)*32 + b_row)*ldb + bc0 + b_cg;
            uint16_t* Bh = BhP(nxt); uint16_t* Bl = BlP(nxt);
            #pragma unroll
            for (int j = 0; j < 4; j++){
                float4 x = *(const float4*)(bp + j*4);
                uint32_t hw0, lw0, hw1, lw1;
                bsplit2(x.x, x.y, hw0, lw0);
                bsplit2(x.z, x.w, hw1, lw1);
                int o = b_row*PB + b_cg + j*4;
                *(uint32_t*)&Bh[o]   = hw0; *(uint32_t*)&Bh[o+2] = hw1;
                *(uint32_t*)&Bl[o]   = lw0; *(uint32_t*)&Bl[o+2] = lw1;
            }
        }
        __syncthreads();
    }

    int g = l >> 2, tq = l & 3;
    #pragma unroll
    for (int mt = 0; mt < 4; mt++){
        #pragma unroll
        for (int nt = 0; nt < 4; nt++){
            int col = col0 + wn*32 + nt*8 + 2*tq;
            #pragma unroll
            for (int half = 0; half < 2; half++){
                int r = row0 + wm*64 + mt*16 + g + half*8;
                float2 v = make_float2(acc[mt][nt][half*2], acc[mt][nt][half*2+1]);
                if (mode == 0){
                    int mtx = col >> 9, cc = col & 511;
                    int hh = cc >> 6, j0 = cc & 63;
                    float* dst = (mtx == 0) ? g_q : (mtx == 1 ? g_k : g_v);
                    int b_ = r >> 13, tok = r & 8191;
                    *(float2*)(dst + ((long)(b_*H + hh)*T + tok)*D + j0) = v;
                } else {
                    int b_ = r >> 13, jr = r & 8191;
                    if (jr <= T - C)
                        *(float2*)(outp + ((long)b_*T + jr + (C-1))*DIM + col) = v;
                }
            }
        }
    }
}

// ------------------- K4: per-chunk MLP grads (512 thr, 8 smem buffers, 3 CTAs/SM) -------------------
__global__ void __launch_bounds__(512, 3)
k4_grads(const float* __restrict__ w1, const float* __restrict__ w2)
{
    extern __shared__ __align__(16) char smraw[];
    uint16_t* Kh = (uint16_t*)smraw;
    uint16_t* Kl = Kh + 64*PH;
    uint16_t* Wh = Kl + 64*PH;
    uint16_t* Wl = Wh + 64*PH;
    uint16_t* Hh = Wl + 64*PH;
    uint16_t* Hl = Hh + 64*PH;
    uint16_t* Yh = Hl + 64*PH;   // dY (single bf16)
    uint16_t* Dh = Yh + 64*PH;   // X, then dX (single bf16)
    float* slr = (float*)(Dh + 64*PH);   // 64

    int nc = blockIdx.x, bh = blockIdx.y;
    int tid = threadIdx.x, wid = tid >> 5, l = tid & 31;
    long base = ((long)bh*T + nc*C)*D;
    for (int idx = tid; idx < 4096; idx += 512){
        int r = idx >> 6, c = idx & 63;
        uint16_t h_, l_;
        bsplit(g_k[base + idx], h_, l_); Kh[r*PH+c] = h_; Kl[r*PH+c] = l_;
        bsplit(w1[idx],        h_, l_); Wh[r*PH+c] = h_; Wl[r*PH+c] = l_;
    }
    if (tid < 64) slr[tid] = g_lr[(long)bh*T + nc*C + tid];
    __syncthreads();

    // X = K @ W1 (3-term); X -> Dh (bf16), H = silu(X) split
    tmm64w<0,0>(wid, l, Kh, Kl, Wh, Wl, [&](int m, int n, float v0, float v1){
        *(uint32_t*)&Dh[m*PH+n] = bpack2(v0, v1);
        uint32_t hw, lw;
        bsplit2(v0*sigm(v0), v1*sigm(v1), hw, lw);
        *(uint32_t*)&Hh[m*PH+n] = hw; *(uint32_t*)&Hl[m*PH+n] = lw;
    });
    __syncthreads();
    for (int idx = tid; idx < 4096; idx += 512){
        int r = idx >> 6, c = idx & 63;
        uint16_t h_, l_; bsplit(w2[idx], h_, l_);
        Wh[r*PH+c] = h_; Wl[r*PH+c] = l_;
    }
    __syncthreads();
    // Y = H @ W2 (3-term); dY = lr*(Y - V) with V direct from gmem -> Yh (bf16)
    tmm64w<0,0>(wid, l, Hh, Hl, Wh, Wl, [&](int m, int n, float y0, float y1){
        float2 vv = *(const float2*)&g_v[base + m*64 + n];
        float lr = slr[m];
        *(uint32_t*)&Yh[m*PH+n] = bpack2(lr*(y0 - vv.x), lr*(y1 - vv.y));
    });
    __syncthreads();
    long gbase = ((long)bh*NCH + nc)*4096;
    // CONCURRENT single-term grads: warps 0-7 G2 = H^T@dY ; warps 8-15 dH = dY@W2^T -> dX
    if (wid < 8){
        tmm64_1<1,0>(wid, l, Hh, Yh, [&](int m, int n, float v0, float v1){
            *(float2*)&g_u2[gbase + m*64 + n] = make_float2(-v0, -v1);
        });
    } else {
        tmm64_1<0,1>(wid-8, l, Yh, Wh, [&](int m, int n, float v0, float v1){
            float x0 = __bfloat162float(__ushort_as_bfloat16(Dh[m*PH+n]));
            float x1 = __bfloat162float(__ushort_as_bfloat16(Dh[m*PH+n+1]));
            float sg0 = sigm(x0), sg1 = sigm(x1);
            float dx0 = v0 * sg0 * (1.f + x0*(1.f - sg0));
            float dx1 = v1 * sg1 * (1.f + x1*(1.f - sg1));
            *(uint32_t*)&Dh[m*PH+n] = bpack2(dx0, dx1);
        });
    }
    __syncthreads();
    // G1 = K^T @ dX (single-term)
    tmm64w1<1,0>(wid, l, Kh, Dh, [&](int m, int n, float v0, float v1){
        *(float2*)&g_u1[gbase + m*64 + n] = make_float2(-v0, -v1);
    });
}

// ------------------- K5: scans -------------------
__global__ void k5_scan()
{
    int e  = blockIdx.x*blockDim.x + threadIdx.x;
    int bh = blockIdx.y;
    float* g = blockIdx.z ? g_u2 : g_u1;
    const float* mg = g_mg  + bh*NCH;
    const float* dc = g_dec + bh*NCH;
    float m = 0.f, u = 0.f;
    long base = (long)bh*NCH*4096 + e;
    for (int t = 0; t < NCH; t++){
        float s = g[base + (long)t*4096];
        m = mg[t]*m + s;
        u = (1.f - dc[t])*u + m;
        g[base + (long)t*4096] = u;
    }
}

// ------------------- K6: retrieve (512 threads) -------------------
__global__ void __launch_bounds__(512)
k6_retrieve(const float* __restrict__ w1, const float* __restrict__ w2,
            const float* __restrict__ gamma)
{
    extern __shared__ __align__(16) char smraw[];
    uint16_t* Qh = (uint16_t*)smraw;     // Q, then O
    uint16_t* Ql = Qh + 64*PH;
    uint16_t* Wh = Ql + 64*PH;
    uint16_t* Wl = Wh + 64*PH;
    uint16_t* Xh = Wl + 64*PH;
    uint16_t* Xl = Xh + 64*PH;

    int nc = blockIdx.x, bh = blockIdx.y;
    int tid = threadIdx.x, wid = tid >> 5, l = tid & 31;
    int h = bh % H, b = bh / H;
    long ubase = ((long)bh*NCH + nc)*4096;
    for (int idx = tid; idx < 4096; idx += 512){
        int r = idx >> 6, c = idx & 63;
        int tok = nc*C + r + (C-1);
        float qv = (tok < T) ? g_q[((long)bh*T + tok)*D + c] : 0.f;
        uint16_t h_, l_;
        bsplit(qv, h_, l_); Qh[r*PH+c] = h_; Ql[r*PH+c] = l_;
        bsplit(w1[idx] + g_u1[ubase + idx], h_, l_); Wh[r*PH+c] = h_; Wl[r*PH+c] = l_;
    }
    __syncthreads();
    tmm64w<0,0>(wid, l, Qh, Ql, Wh, Wl, [&](int m, int n, float v0, float v1){
        uint32_t hw, lw;
        bsplit2(v0*sigm(v0), v1*sigm(v1), hw, lw);
        *(uint32_t*)&Xh[m*PH+n] = hw; *(uint32_t*)&Xl[m*PH+n] = lw;
    });
    __syncthreads();
    for (int idx = tid; idx < 4096; idx += 512){
        int r = idx >> 6, c = idx & 63;
        uint16_t h_, l_; bsplit(w2[idx] + g_u2[ubase + idx], h_, l_);
        Wh[r*PH+c] = h_; Wl[r*PH+c] = l_;
    }
    __syncthreads();
    tmm64w<0,0>(wid, l, Xh, Xl, Wh, Wl, [&](int m, int n, float v0, float v1){
        uint32_t hw, lw;
        bsplit2(v0, v1, hw, lw);
        *(uint32_t*)&Qh[m*PH+n] = hw; *(uint32_t*)&Ql[m*PH+n] = lw;
    });
    __syncthreads();
    int row = tid >> 3, sub = tid & 7;
    float ss = 0.f;
    float ov[8];
    #pragma unroll
    for (int jj = 0; jj < 8; jj++){
        int j = sub + jj*8;
        float v = bjoin(Qh[row*PH+j], Ql[row*PH+j]);
        ov[jj] = v;
        ss += v*v;
    }
    ss += __shfl_xor_sync(0xffffffffu, ss, 1);
    ss += __shfl_xor_sync(0xffffffffu, ss, 2);
    ss += __shfl_xor_sync(0xffffffffu, ss, 4);
    float sc = rsqrtf(ss*(1.f/64) + EPSR);
    int tokq = nc*C + row + (C-1);
    float gate = (tokq < T) ? g_gate[(long)bh*T + tokq] : 0.f;
    float* dst = g_vals + ((long)b*T + nc*C + row)*DIM + h*D;
    #pragma unroll
    for (int jj = 0; jj < 8; jj++){
        int j = sub + jj*8;
        dst[j] = ov[jj]*sc*(gamma[h*D + j] + 1.f)*gate;
    }
}

// ------------------- K0 -------------------
__global__ void k0_zero(float* __restrict__ out)
{
    int i = blockIdx.x*blockDim.x + threadIdx.x;
    const int per = (C-1)*DIM;
    if (i < BB*per){
        int b = i / per, rem = i % per;
        out[(long)b*T*DIM + rem] = 0.f;
    }
}

// ------------------- launch -------------------
extern "C" void kernel_launch(void* const* d_in, const int* in_sizes, int n_in,
                              void* d_out, int out_size)
{
    const float* seq   = (const float*)d_in[0];
    const float* w1    = (const float*)d_in[1];
    const float* w2    = (const float*)d_in[2];
    const float* Wq    = (const float*)d_in[3];
    const float* Wkv   = (const float*)d_in[4];
    const float* Wstep = (const float*)d_in[5];
    const float* Wmom  = (const float*)d_in[6];
    const float* Wdecay= (const float*)d_in[7];
    const float* Wgate = (const float*)d_in[8];
    const float* Wcomb = (const float*)d_in[9];
    const float* gamma = (const float*)d_in[10];
    float* out = (float*)d_out;

    const int SM4 = 8*64*PH*2 + 256;   // 73,984 -> 3 CTAs/SM
    const int SM6 = 6*64*PH*2;         // 55,296 -> 4 CTAs/SM
    const int SMG = 2*STGH*2;          // 75,776 -> 2 CTAs/SM

    cudaFuncSetAttribute(k4_grads,    cudaFuncAttributeMaxDynamicSharedMemorySize, SM4);
    cudaFuncSetAttribute(k6_retrieve, cudaFuncAttributeMaxDynamicSharedMemorySize, SM6);
    cudaFuncSetAttribute(kmma,        cudaFuncAttributeMaxDynamicSharedMemorySize, SMG);

    k1_rmsnorm<<<BB*T, 256>>>(seq, Wstep, Wgate);
    k2_chunkgates<<<dim3(NCH, BB), 256>>>(Wmom, Wdecay);
    kmma<<<dim3(12, 256), 256, SMG>>>(Wq, Wkv, nullptr, 0);
    k4_grads<<<dim3(NCH, BH), 512, SM4>>>(w1, w2);
    k5_scan<<<dim3(16, BH, 2), 256>>>();
    k6_retrieve<<<dim3(NCH, BH), 512, SM6>>>(w1, w2, gamma);
    kmma<<<dim3(4, 256), 256, SMG>>>(Wcomb, nullptr, out, 1);
    k0_zero<<<504, 256>>>(out);
}